// round 1
// baseline (speedup 1.0000x reference)
#include <cuda_runtime.h>
#include <math.h>
#include <stdint.h>

#define NNODES 100000
#define NEDGES 320000
#define NGRAPH 2048
#define HID    256
#define EDIM   128
#define NODE_F 48
#define EDGE_F 6
#define NLAYER 8

// ---------------- scratch (device globals; no allocation allowed) ----------
__device__ float g_h0[(size_t)NNODES * HID];
__device__ float g_h1[(size_t)NNODES * HID];
__device__ float g_agg[(size_t)NNODES * HID];
__device__ float g_tmp[(size_t)NNODES * HID];
__device__ float g_z  [(size_t)NNODES * HID];
__device__ float g_e  [(size_t)NEDGES * EDIM];
__device__ float g_ee [(size_t)NEDGES * HID];
__device__ float g_stats[2 * HID];
__device__ float g_gmean[(size_t)NGRAPH * HID];
__device__ float g_msq [NGRAPH];
__device__ float g_cnt [NGRAPH];
__device__ float g_wexp[NNODES];
__device__ float g_wsum[NGRAPH];

// ---------------- SGEMM: C = act( A_eff @ B + bias ) -----------------------
// A_eff = (1+*eps_ptr)*A1 + A2   if HAS_A2 else A1
// A1,A2: [M,K] row-major. B: [K,N] row-major. bias: [N].
// Requires K % 8 == 0, N % 128 == 0.
#define BM 128
#define BN 128
#define BK 8
#define TM 8
#define TN 8

template <int ACT, bool HAS_A2>
__global__ __launch_bounds__(256) void sgemm_kernel(
    int M, int N, int K,
    const float* __restrict__ A1, const float* __restrict__ A2,
    const float* __restrict__ eps_ptr,
    const float* __restrict__ B, const float* __restrict__ bias,
    float* __restrict__ C)
{
    __shared__ float As[BK][BM];
    __shared__ float Bs[BK][BN];

    const int tid = threadIdx.x;
    const int m0 = blockIdx.y * BM;
    const int n0 = blockIdx.x * BN;

    float alpha = 1.0f;
    if (HAS_A2) alpha = 1.0f + __ldg(eps_ptr);

    const int aRow = tid >> 1;          // 0..127
    const int aCol = (tid & 1) * 4;     // 0 or 4
    const int bRow = tid >> 5;          // 0..7
    const int bCol = (tid & 31) * 4;    // 0..124

    const int tx = tid & 15;
    const int ty = tid >> 4;

    float acc[TM][TN];
#pragma unroll
    for (int i = 0; i < TM; i++)
#pragma unroll
        for (int j = 0; j < TN; j++) acc[i][j] = 0.0f;

    for (int k0 = 0; k0 < K; k0 += BK) {
        // load A tile (with optional A2 combine)
        const int gm = m0 + aRow;
        float4 av = make_float4(0.f, 0.f, 0.f, 0.f);
        if (gm < M) {
            av = *(const float4*)(A1 + (size_t)gm * K + k0 + aCol);
            if (HAS_A2) {
                float4 a2 = *(const float4*)(A2 + (size_t)gm * K + k0 + aCol);
                av.x = alpha * av.x + a2.x;
                av.y = alpha * av.y + a2.y;
                av.z = alpha * av.z + a2.z;
                av.w = alpha * av.w + a2.w;
            }
        }
        As[aCol + 0][aRow] = av.x;
        As[aCol + 1][aRow] = av.y;
        As[aCol + 2][aRow] = av.z;
        As[aCol + 3][aRow] = av.w;

        // load B tile
        float4 bv = *(const float4*)(B + (size_t)(k0 + bRow) * N + n0 + bCol);
        *(float4*)&Bs[bRow][bCol] = bv;

        __syncthreads();

#pragma unroll
        for (int kk = 0; kk < BK; kk++) {
            float ra[TM], rb[TN];
#pragma unroll
            for (int i = 0; i < TM; i++) ra[i] = As[kk][ty * TM + i];
#pragma unroll
            for (int j = 0; j < TN; j++) rb[j] = Bs[kk][tx * TN + j];
#pragma unroll
            for (int i = 0; i < TM; i++)
#pragma unroll
                for (int j = 0; j < TN; j++) acc[i][j] = fmaf(ra[i], rb[j], acc[i][j]);
        }
        __syncthreads();
    }

    // epilogue
#pragma unroll
    for (int i = 0; i < TM; i++) {
        const int m = m0 + ty * TM + i;
        if (m >= M) continue;
#pragma unroll
        for (int j = 0; j < TN; j += 4) {
            const int n = n0 + tx * TN + j;
            float4 r;
            r.x = acc[i][j + 0] + __ldg(bias + n + 0);
            r.y = acc[i][j + 1] + __ldg(bias + n + 1);
            r.z = acc[i][j + 2] + __ldg(bias + n + 2);
            r.w = acc[i][j + 3] + __ldg(bias + n + 3);
            if (ACT == 1) {
                r.x = fmaxf(r.x, 0.f); r.y = fmaxf(r.y, 0.f);
                r.z = fmaxf(r.z, 0.f); r.w = fmaxf(r.w, 0.f);
            } else if (ACT == 2) {
                r.x = tanhf(r.x); r.y = tanhf(r.y);
                r.z = tanhf(r.z); r.w = tanhf(r.w);
            }
            *(float4*)(C + (size_t)m * N + n) = r;
        }
    }
}

// ---------------- edge embedding: e = edge_attr @ edge_w + edge_b ----------
__global__ void edge_embed_kernel(const float* __restrict__ ea,
                                  const float* __restrict__ W,
                                  const float* __restrict__ b,
                                  float* __restrict__ e)
{
    __shared__ float sW[EDGE_F * EDIM];
    __shared__ float sb[EDIM];
    for (int i = threadIdx.x; i < EDGE_F * EDIM; i += blockDim.x) sW[i] = W[i];
    for (int i = threadIdx.x; i < EDIM; i += blockDim.x) sb[i] = b[i];
    __syncthreads();

    size_t idx = (size_t)blockIdx.x * blockDim.x + threadIdx.x;
    if (idx >= (size_t)NEDGES * EDIM) return;
    int ed = (int)(idx >> 7);
    int c = (int)(idx & 127);
    float acc = sb[c];
#pragma unroll
    for (int k = 0; k < EDGE_F; k++)
        acc = fmaf(__ldg(ea + (size_t)ed * EDGE_F + k), sW[k * EDIM + c], acc);
    e[idx] = acc;
}

// ---------------- message + scatter: agg[dst] += relu(h[src] + ee) ---------
__global__ void scatter_kernel(const float* __restrict__ h,
                               const float* __restrict__ ee,
                               const int* __restrict__ src,
                               const int* __restrict__ dst,
                               float* __restrict__ agg)
{
    int warp = (blockIdx.x * blockDim.x + threadIdx.x) >> 5;
    int lane = threadIdx.x & 31;
    if (warp >= NEDGES) return;
    int s = __ldg(src + warp);
    int d = __ldg(dst + warp);
    const float4* hp = (const float4*)(h + (size_t)s * HID);
    const float4* ep = (const float4*)(ee + (size_t)warp * HID);
    float* ap = agg + (size_t)d * HID;
#pragma unroll
    for (int i = lane; i < HID / 4; i += 32) {
        float4 a = __ldg(hp + i);
        float4 b = __ldg(ep + i);
        float m0 = fmaxf(a.x + b.x, 0.f);
        float m1 = fmaxf(a.y + b.y, 0.f);
        float m2 = fmaxf(a.z + b.z, 0.f);
        float m3 = fmaxf(a.w + b.w, 0.f);
        atomicAdd(ap + i * 4 + 0, m0);
        atomicAdd(ap + i * 4 + 1, m1);
        atomicAdd(ap + i * 4 + 2, m2);
        atomicAdd(ap + i * 4 + 3, m3);
    }
}

// ---------------- BN statistics (sum, sumsq per channel) -------------------
__global__ void bn_stats_kernel(const float* __restrict__ z, float* __restrict__ stats)
{
    int c = threadIdx.x;  // 256 threads, thread owns channel c
    float s = 0.f, q = 0.f;
    for (int r = blockIdx.x; r < NNODES; r += gridDim.x) {
        float v = z[(size_t)r * HID + c];
        s += v;
        q = fmaf(v, v, q);
    }
    atomicAdd(&stats[c], s);
    atomicAdd(&stats[HID + c], q);
}

// ---------------- BN normalize + accumulate per-graph mean sums ------------
__global__ void bn_norm_kernel(float* __restrict__ z,
                               const float* __restrict__ stats,
                               const float* __restrict__ gamma,
                               const float* __restrict__ beta,
                               const int* __restrict__ batch,
                               float* __restrict__ gmean)
{
    size_t idx = (size_t)blockIdx.x * blockDim.x + threadIdx.x;
    if (idx >= (size_t)NNODES * HID) return;
    int c = (int)(idx & (HID - 1));
    int r = (int)(idx >> 8);
    const float invN = 1.0f / (float)NNODES;
    float mu = __ldg(stats + c) * invN;
    float var = __ldg(stats + HID + c) * invN - mu * mu;
    float v = __ldg(gamma + c) * (z[idx] - mu) * rsqrtf(var + 1e-5f) + __ldg(beta + c);
    z[idx] = v;
    int g = __ldg(batch + r);
    atomicAdd(&gmean[(size_t)g * HID + c], v);
}

// ---------------- PairNorm: center + per-graph mean-square-norm ------------
__global__ void center_msq_kernel(float* __restrict__ z,
                                  const float* __restrict__ gmean,
                                  const float* __restrict__ cnt,
                                  const int* __restrict__ batch,
                                  float* __restrict__ msq)
{
    int row = (blockIdx.x * blockDim.x + threadIdx.x) >> 5;
    int lane = threadIdx.x & 31;
    if (row >= NNODES) return;
    int g = __ldg(batch + row);
    float inv = 1.0f / __ldg(cnt + g);
    float4* zp = (float4*)(z + (size_t)row * HID);
    const float4* mp = (const float4*)(gmean + (size_t)g * HID);
    float acc = 0.f;
#pragma unroll
    for (int i = lane; i < HID / 4; i += 32) {
        float4 v = zp[i];
        float4 m = __ldg(mp + i);
        v.x -= m.x * inv; v.y -= m.y * inv; v.z -= m.z * inv; v.w -= m.w * inv;
        zp[i] = v;
        acc += v.x * v.x + v.y * v.y + v.z * v.z + v.w * v.w;
    }
#pragma unroll
    for (int o = 16; o > 0; o >>= 1) acc += __shfl_down_sync(0xffffffffu, acc, o);
    if (lane == 0) atomicAdd(&msq[g], acc);
}

// ---------------- PairNorm scale + ReLU -> h_next ---------------------------
__global__ void scale_relu_kernel(const float* __restrict__ z,
                                  const float* __restrict__ msq,
                                  const float* __restrict__ cnt,
                                  const int* __restrict__ batch,
                                  float* __restrict__ hout)
{
    size_t idx = (size_t)blockIdx.x * blockDim.x + threadIdx.x;
    if (idx >= (size_t)NNODES * HID) return;
    int r = (int)(idx >> 8);
    int g = __ldg(batch + r);
    float sc = rsqrtf(1e-5f + __ldg(msq + g) / __ldg(cnt + g));
    hout[idx] = fmaxf(z[idx] * sc, 0.f);
}

// ---------------- graph node counts -----------------------------------------
__global__ void count_kernel(const int* __restrict__ batch, float* __restrict__ cnt)
{
    int n = blockIdx.x * blockDim.x + threadIdx.x;
    if (n >= NNODES) return;
    atomicAdd(&cnt[__ldg(batch + n)], 1.0f);
}
__global__ void clamp_cnt_kernel(float* __restrict__ cnt)
{
    int g = blockIdx.x * blockDim.x + threadIdx.x;
    if (g < NGRAPH) cnt[g] = fmaxf(cnt[g], 1.0f);
}

// ---------------- attention score: s = s1 @ w2 + b2; w = exp(s) ------------
__global__ void attn_score_kernel(const float* __restrict__ s1,
                                  const float* __restrict__ w2,
                                  const float* __restrict__ b2,
                                  const int* __restrict__ batch,
                                  float* __restrict__ wexp,
                                  float* __restrict__ wsum)
{
    int row = (blockIdx.x * blockDim.x + threadIdx.x) >> 5;
    int lane = threadIdx.x & 31;
    if (row >= NNODES) return;
    float acc = 0.f;
#pragma unroll
    for (int k = lane; k < EDIM; k += 32)
        acc = fmaf(__ldg(s1 + (size_t)row * EDIM + k), __ldg(w2 + k), acc);
#pragma unroll
    for (int o = 16; o > 0; o >>= 1) acc += __shfl_down_sync(0xffffffffu, acc, o);
    if (lane == 0) {
        float w = expf(acc + __ldg(b2));
        wexp[row] = w;
        atomicAdd(&wsum[__ldg(batch + row)], w);
    }
}

// ---------------- pooling: mean-sum / max / attention-sum ------------------
__global__ void pool_kernel(const float* __restrict__ h,
                            const float* __restrict__ wexp,
                            const float* __restrict__ wsum,
                            const int* __restrict__ batch,
                            float* __restrict__ out)
{
    int row = (blockIdx.x * blockDim.x + threadIdx.x) >> 5;
    int lane = threadIdx.x & 31;
    if (row >= NNODES) return;
    int g = __ldg(batch + row);
    float coeff = __ldg(wexp + row) / (__ldg(wsum + g) + 1e-8f);
    float* og = out + (size_t)g * (3 * HID);
    const float* hr = h + (size_t)row * HID;
#pragma unroll
    for (int i = lane; i < HID; i += 32) {
        float v = __ldg(hr + i);
        atomicAdd(og + i, v);                                    // mean sum
        atomicMax((int*)(og + HID + i), __float_as_int(v));      // max (v >= 0)
        atomicAdd(og + 2 * HID + i, v * coeff);                  // attention
    }
}

__global__ void finalize_kernel(float* __restrict__ out, const float* __restrict__ cnt)
{
    int idx = blockIdx.x * blockDim.x + threadIdx.x;
    if (idx >= NGRAPH * HID) return;
    int g = idx >> 8;
    int c = idx & (HID - 1);
    out[(size_t)g * (3 * HID) + c] *= (1.0f / cnt[g]);
}

// ---------------- launch -----------------------------------------------------
static inline void launch_gemm(int act, bool has_a2, int M, int N, int K,
                               const float* A1, const float* A2, const float* eps_ptr,
                               const float* B, const float* bias, float* C)
{
    dim3 grid((N + BN - 1) / BN, (M + BM - 1) / BM);
    if (has_a2) {
        if (act == 1) sgemm_kernel<1, true><<<grid, 256>>>(M, N, K, A1, A2, eps_ptr, B, bias, C);
        else          sgemm_kernel<0, true><<<grid, 256>>>(M, N, K, A1, A2, eps_ptr, B, bias, C);
    } else {
        if (act == 0)      sgemm_kernel<0, false><<<grid, 256>>>(M, N, K, A1, A2, eps_ptr, B, bias, C);
        else if (act == 1) sgemm_kernel<1, false><<<grid, 256>>>(M, N, K, A1, A2, eps_ptr, B, bias, C);
        else               sgemm_kernel<2, false><<<grid, 256>>>(M, N, K, A1, A2, eps_ptr, B, bias, C);
    }
}

extern "C" void kernel_launch(void* const* d_in, const int* in_sizes, int n_in,
                              void* d_out, int out_size)
{
    const float* x         = (const float*)d_in[0];
    const float* edge_attr = (const float*)d_in[1];
    const float* node_w    = (const float*)d_in[2];
    const float* node_b    = (const float*)d_in[3];
    const float* edge_w    = (const float*)d_in[4];
    const float* edge_b    = (const float*)d_in[5];
    const float* conv_w    = (const float*)d_in[6];
    const float* conv_b    = (const float*)d_in[7];
    const float* mlp_w1    = (const float*)d_in[8];
    const float* mlp_b1    = (const float*)d_in[9];
    const float* mlp_w2    = (const float*)d_in[10];
    const float* mlp_b2    = (const float*)d_in[11];
    const float* eps       = (const float*)d_in[12];
    const float* bn_gamma  = (const float*)d_in[13];
    const float* bn_beta   = (const float*)d_in[14];
    const float* att_w1    = (const float*)d_in[15];
    const float* att_b1    = (const float*)d_in[16];
    const float* att_w2    = (const float*)d_in[17];
    const float* att_b2    = (const float*)d_in[18];
    const int*   edge_index= (const int*)d_in[19];
    const int*   batch     = (const int*)d_in[20];
    float* out = (float*)d_out;

    const int* src = edge_index;
    const int* dst = edge_index + NEDGES;

    float *p_h0, *p_h1, *p_agg, *p_tmp, *p_z, *p_e, *p_ee, *p_stats, *p_gmean,
          *p_msq, *p_cnt, *p_wexp, *p_wsum;
    cudaGetSymbolAddress((void**)&p_h0, g_h0);
    cudaGetSymbolAddress((void**)&p_h1, g_h1);
    cudaGetSymbolAddress((void**)&p_agg, g_agg);
    cudaGetSymbolAddress((void**)&p_tmp, g_tmp);
    cudaGetSymbolAddress((void**)&p_z, g_z);
    cudaGetSymbolAddress((void**)&p_e, g_e);
    cudaGetSymbolAddress((void**)&p_ee, g_ee);
    cudaGetSymbolAddress((void**)&p_stats, g_stats);
    cudaGetSymbolAddress((void**)&p_gmean, g_gmean);
    cudaGetSymbolAddress((void**)&p_msq, g_msq);
    cudaGetSymbolAddress((void**)&p_cnt, g_cnt);
    cudaGetSymbolAddress((void**)&p_wexp, g_wexp);
    cudaGetSymbolAddress((void**)&p_wsum, g_wsum);

    // zero output + graph counts
    cudaMemsetAsync(out, 0, (size_t)out_size * sizeof(float));
    cudaMemsetAsync(p_cnt, 0, NGRAPH * sizeof(float));
    count_kernel<<<(NNODES + 255) / 256, 256>>>(batch, p_cnt);
    clamp_cnt_kernel<<<(NGRAPH + 255) / 256, 256>>>(p_cnt);

    // node embedding: h0 = x @ node_w + node_b   [N, 256], K=48
    launch_gemm(0, false, NNODES, HID, NODE_F, x, nullptr, nullptr, node_w, node_b, p_h0);

    // edge embedding: e = edge_attr @ edge_w + edge_b  [E, 128], K=6
    {
        size_t total = (size_t)NEDGES * EDIM;
        edge_embed_kernel<<<(unsigned)((total + 255) / 256), 256>>>(edge_attr, edge_w, edge_b, p_e);
    }

    float* h_cur = p_h0;
    float* h_nxt = p_h1;

    for (int i = 0; i < NLAYER; i++) {
        // ee = e @ conv_w[i] + conv_b[i]   [E, 256], K=128
        launch_gemm(0, false, NEDGES, HID, EDIM, p_e, nullptr, nullptr,
                    conv_w + (size_t)i * EDIM * HID, conv_b + (size_t)i * HID, p_ee);

        // agg = scatter_add(relu(h[src] + ee), dst)
        cudaMemsetAsync(p_agg, 0, (size_t)NNODES * HID * sizeof(float));
        scatter_kernel<<<(NEDGES * 32 + 255) / 256, 256>>>(h_cur, p_ee, src, dst, p_agg);

        // tmp = relu( ((1+eps)h + agg) @ w1 + b1 )
        launch_gemm(1, true, NNODES, HID, HID, h_cur, p_agg, eps + i,
                    mlp_w1 + (size_t)i * HID * HID, mlp_b1 + (size_t)i * HID, p_tmp);

        // z = tmp @ w2 + b2
        launch_gemm(0, false, NNODES, HID, HID, p_tmp, nullptr, nullptr,
                    mlp_w2 + (size_t)i * HID * HID, mlp_b2 + (size_t)i * HID, p_z);

        // BatchNorm
        cudaMemsetAsync(p_stats, 0, 2 * HID * sizeof(float));
        bn_stats_kernel<<<1024, HID>>>(p_z, p_stats);
        cudaMemsetAsync(p_gmean, 0, (size_t)NGRAPH * HID * sizeof(float));
        bn_norm_kernel<<<(unsigned)(((size_t)NNODES * HID + 255) / 256), 256>>>(
            p_z, p_stats, bn_gamma + (size_t)i * HID, bn_beta + (size_t)i * HID, batch, p_gmean);

        // PairNorm
        cudaMemsetAsync(p_msq, 0, NGRAPH * sizeof(float));
        center_msq_kernel<<<(NNODES * 32 + 255) / 256, 256>>>(p_z, p_gmean, p_cnt, batch, p_msq);
        scale_relu_kernel<<<(unsigned)(((size_t)NNODES * HID + 255) / 256), 256>>>(
            p_z, p_msq, p_cnt, batch, h_nxt);

        float* t = h_cur; h_cur = h_nxt; h_nxt = t;
    }

    // attention hidden: s1 = tanh(h @ att_w1 + att_b1)   [N, 128], K=256
    launch_gemm(2, false, NNODES, EDIM, HID, h_cur, nullptr, nullptr, att_w1, att_b1, p_tmp);

    // scores -> exp weights -> per-graph sums
    cudaMemsetAsync(p_wsum, 0, NGRAPH * sizeof(float));
    attn_score_kernel<<<(NNODES * 32 + 255) / 256, 256>>>(p_tmp, att_w2, att_b2, batch, p_wexp, p_wsum);

    // pooling into d_out (mean-sum | max | att-sum), then mean divide
    pool_kernel<<<(NNODES * 32 + 255) / 256, 256>>>(h_cur, p_wexp, p_wsum, batch, out);
    finalize_kernel<<<(NGRAPH * HID + 255) / 256, 256>>>(out, p_cnt);

    (void)in_sizes; (void)n_in;
}

// round 2
// speedup vs baseline: 2.1923x; 2.1923x over previous
#include <cuda_runtime.h>
#include <math.h>
#include <stdint.h>

#define NNODES 100000
#define NEDGES 320000
#define NGRAPH 2048
#define HID    256
#define EDIM   128
#define NODE_F 48
#define EDGE_F 6
#define NLAYER 8

// ---------------- scratch (device globals) ----------------------------------
__device__ float g_h0 [(size_t)NNODES * HID];
__device__ float g_h1 [(size_t)NNODES * HID];
__device__ float g_aeff[(size_t)NNODES * HID];
__device__ float g_tmp[(size_t)NNODES * HID];
__device__ float g_z  [(size_t)NNODES * HID];
__device__ float g_e  [(size_t)NEDGES * EDIM];
__device__ float g_ee [(size_t)NEDGES * HID];
__device__ float g_stats[2 * HID];
__device__ float g_gmean[(size_t)NGRAPH * HID];
__device__ float g_msq [NGRAPH];
__device__ float g_cnt [NGRAPH];
__device__ float g_wexp[NNODES];
__device__ float g_wsum[NGRAPH];
__device__ int   g_deg [NNODES];
__device__ int   g_rowstart[NNODES + 1];
__device__ int   g_cursor[NNODES];
__device__ int   g_csr_eid[NEDGES];
__device__ int   g_csr_src[NEDGES];
__device__ int   g_gstart[NGRAPH + 1];

// ---------------- TF32 tensor-core GEMM ------------------------------------
// C = act( A @ B + bias ),  A [M,K] row-major, B [K,N] row-major, bias [N].
// Requires N % 128 == 0, K % 16 == 0.
// CTA tile 128x128, BK=32, 128 threads (4 warps, 2x2, warp tile 64x64),
// double-buffered cp.async, mma.sync.m16n8k8.tf32 with rna rounding.
#define GA_STRIDE 36              // 32 + 4 pad (words)
#define GB_STRIDE 132             // 128 + 4 pad (words)
#define A_TILE_W (128 * GA_STRIDE)
#define B_TILE_W (32 * GB_STRIDE)
#define GEMM_SMEM_BYTES ((2 * A_TILE_W + 2 * B_TILE_W) * 4)

__device__ __forceinline__ uint32_t f2tf32(float x) {
    uint32_t r;
    asm volatile("cvt.rna.tf32.f32 %0, %1;" : "=r"(r) : "f"(x));
    return r;
}
__device__ __forceinline__ void cp16(float* dst, const float* src, bool pred) {
    unsigned d = (unsigned)__cvta_generic_to_shared(dst);
    int sz = pred ? 16 : 0;
    asm volatile("cp.async.cg.shared.global [%0], [%1], 16, %2;" :: "r"(d), "l"(src), "r"(sz));
}
__device__ __forceinline__ void cp_commit() { asm volatile("cp.async.commit_group;"); }
template <int Np>
__device__ __forceinline__ void cp_wait() { asm volatile("cp.async.wait_group %0;" :: "n"(Np)); }

__device__ __forceinline__ void mma_tf32(float* c, const uint32_t* a, const uint32_t* b) {
    asm volatile(
        "mma.sync.aligned.m16n8k8.row.col.f32.tf32.tf32.f32 "
        "{%0,%1,%2,%3}, {%4,%5,%6,%7}, {%8,%9}, {%0,%1,%2,%3};"
        : "+f"(c[0]), "+f"(c[1]), "+f"(c[2]), "+f"(c[3])
        : "r"(a[0]), "r"(a[1]), "r"(a[2]), "r"(a[3]), "r"(b[0]), "r"(b[1]));
}

template <int ACT>
__global__ __launch_bounds__(128, 2) void tf32_gemm(
    int M, int N, int K,
    const float* __restrict__ A, const float* __restrict__ B,
    const float* __restrict__ bias, float* __restrict__ C)
{
    extern __shared__ float sm[];
    float* As = sm;                      // [2][128][GA_STRIDE]
    float* Bs = sm + 2 * A_TILE_W;       // [2][32][GB_STRIDE]

    const int tid = threadIdx.x;
    const int warp = tid >> 5;
    const int lane = tid & 31;
    const int g = lane >> 2;
    const int tq = lane & 3;
    const int m0 = blockIdx.y * 128;
    const int n0 = blockIdx.x * 128;
    const int wm = (warp >> 1) * 64;
    const int wn = (warp & 1) * 64;

    float acc[4][8][4];
#pragma unroll
    for (int i = 0; i < 4; i++)
#pragma unroll
        for (int j = 0; j < 8; j++)
#pragma unroll
            for (int r = 0; r < 4; r++) acc[i][j][r] = 0.0f;

    const int arow = tid >> 3;          // 0..15
    const int ac4 = tid & 7;            // 0..7 (float4 index)
    const int brow = tid >> 5;          // 0..3
    const int bc4 = tid & 31;           // 0..31

    const int nk = (K + 31) / 32;

    // -------- prologue: load chunk 0 into buffer 0
    {
        const int kc = 0;
#pragma unroll
        for (int it = 0; it < 8; it++) {
            int row = arow + it * 16;
            int gm = m0 + row;
            int gk = kc * 32 + ac4 * 4;
            bool p = (gm < M) && (gk < K);
            const float* src = A + (size_t)(p ? gm : 0) * K + (p ? gk : 0);
            cp16(As + row * GA_STRIDE + ac4 * 4, src, p);
        }
#pragma unroll
        for (int it = 0; it < 8; it++) {
            int row = brow + it * 4;
            int gk = kc * 32 + row;
            bool p = (gk < K);
            const float* src = B + (size_t)(p ? gk : 0) * N + n0 + bc4 * 4;
            cp16(Bs + row * GB_STRIDE + bc4 * 4, src, p);
        }
        cp_commit();
    }

    int buf = 0;
    for (int i = 0; i < nk; i++) {
        if (i + 1 < nk) {
            const int kc = i + 1;
            float* Ad = As + (buf ^ 1) * A_TILE_W;
            float* Bd = Bs + (buf ^ 1) * B_TILE_W;
#pragma unroll
            for (int it = 0; it < 8; it++) {
                int row = arow + it * 16;
                int gm = m0 + row;
                int gk = kc * 32 + ac4 * 4;
                bool p = (gm < M) && (gk < K);
                const float* src = A + (size_t)(p ? gm : 0) * K + (p ? gk : 0);
                cp16(Ad + row * GA_STRIDE + ac4 * 4, src, p);
            }
#pragma unroll
            for (int it = 0; it < 8; it++) {
                int row = brow + it * 4;
                int gk = kc * 32 + row;
                bool p = (gk < K);
                const float* src = B + (size_t)(p ? gk : 0) * N + n0 + bc4 * 4;
                cp16(Bd + row * GB_STRIDE + bc4 * 4, src, p);
            }
            cp_commit();
            cp_wait<1>();
        } else {
            cp_wait<0>();
        }
        __syncthreads();

        const float* Ab = As + buf * A_TILE_W;
        const float* Bb = Bs + buf * B_TILE_W;
#pragma unroll
        for (int kk = 0; kk < 4; kk++) {
            const int k = kk * 8;
            uint32_t af[4][4];
#pragma unroll
            for (int mi = 0; mi < 4; mi++) {
                const float* p = Ab + (wm + mi * 16 + g) * GA_STRIDE + k + tq;
                af[mi][0] = f2tf32(p[0]);
                af[mi][1] = f2tf32(p[8 * GA_STRIDE]);
                af[mi][2] = f2tf32(p[4]);
                af[mi][3] = f2tf32(p[8 * GA_STRIDE + 4]);
            }
            uint32_t bf[8][2];
#pragma unroll
            for (int ni = 0; ni < 8; ni++) {
                const float* p = Bb + (k + tq) * GB_STRIDE + wn + ni * 8 + g;
                bf[ni][0] = f2tf32(p[0]);
                bf[ni][1] = f2tf32(p[4 * GB_STRIDE]);
            }
#pragma unroll
            for (int mi = 0; mi < 4; mi++)
#pragma unroll
                for (int ni = 0; ni < 8; ni++)
                    mma_tf32(acc[mi][ni], af[mi], bf[ni]);
        }
        __syncthreads();
        buf ^= 1;
    }

    // -------- epilogue
#pragma unroll
    for (int mi = 0; mi < 4; mi++) {
        int r0 = m0 + wm + mi * 16 + g;
        int r1 = r0 + 8;
#pragma unroll
        for (int ni = 0; ni < 8; ni++) {
            int col = n0 + wn + ni * 8 + tq * 2;
            float b0 = __ldg(bias + col);
            float b1 = __ldg(bias + col + 1);
            float v0 = acc[mi][ni][0] + b0;
            float v1 = acc[mi][ni][1] + b1;
            float v2 = acc[mi][ni][2] + b0;
            float v3 = acc[mi][ni][3] + b1;
            if (ACT == 1) {
                v0 = fmaxf(v0, 0.f); v1 = fmaxf(v1, 0.f);
                v2 = fmaxf(v2, 0.f); v3 = fmaxf(v3, 0.f);
            } else if (ACT == 2) {
                v0 = tanhf(v0); v1 = tanhf(v1);
                v2 = tanhf(v2); v3 = tanhf(v3);
            }
            if (r0 < M) *(float2*)(C + (size_t)r0 * N + col) = make_float2(v0, v1);
            if (r1 < M) *(float2*)(C + (size_t)r1 * N + col) = make_float2(v2, v3);
        }
    }
}

// ---------------- edge embedding: e = edge_attr @ edge_w + edge_b ----------
__global__ void edge_embed_kernel(const float* __restrict__ ea,
                                  const float* __restrict__ W,
                                  const float* __restrict__ b,
                                  float* __restrict__ e)
{
    __shared__ float sW[EDGE_F * EDIM];
    __shared__ float sb[EDIM];
    for (int i = threadIdx.x; i < EDGE_F * EDIM; i += blockDim.x) sW[i] = W[i];
    for (int i = threadIdx.x; i < EDIM; i += blockDim.x) sb[i] = b[i];
    __syncthreads();

    size_t idx = (size_t)blockIdx.x * blockDim.x + threadIdx.x;
    if (idx >= (size_t)NEDGES * EDIM) return;
    int ed = (int)(idx >> 7);
    int c = (int)(idx & 127);
    float acc = sb[c];
#pragma unroll
    for (int k = 0; k < EDGE_F; k++)
        acc = fmaf(__ldg(ea + (size_t)ed * EDGE_F + k), sW[k * EDIM + c], acc);
    e[idx] = acc;
}

// ---------------- CSR build --------------------------------------------------
__global__ void deg_kernel(const int* __restrict__ dst, int* __restrict__ deg)
{
    int e = blockIdx.x * blockDim.x + threadIdx.x;
    if (e < NEDGES) atomicAdd(&deg[__ldg(dst + e)], 1);
}

__global__ void csr_scan_kernel(const int* __restrict__ deg,
                                int* __restrict__ rowstart,
                                int* __restrict__ cursor)
{
    const int CH = (NNODES + 1023) / 1024;
    __shared__ int ssum[1024];
    int t = threadIdx.x;
    int lo = t * CH;
    int hi = min(lo + CH, NNODES);
    int s = 0;
    for (int i = lo; i < hi; i++) s += deg[i];
    ssum[t] = s;
    __syncthreads();
    for (int off = 1; off < 1024; off <<= 1) {
        int v = (t >= off) ? ssum[t - off] : 0;
        __syncthreads();
        ssum[t] += v;
        __syncthreads();
    }
    int run = ssum[t] - s;   // exclusive prefix
    for (int i = lo; i < hi; i++) {
        rowstart[i] = run;
        cursor[i] = run;
        run += deg[i];
    }
    if (hi == NNODES) rowstart[NNODES] = run;
}

__global__ void csr_fill_kernel(const int* __restrict__ src,
                                const int* __restrict__ dst,
                                int* __restrict__ cursor,
                                int* __restrict__ csr_eid,
                                int* __restrict__ csr_src)
{
    int e = blockIdx.x * blockDim.x + threadIdx.x;
    if (e >= NEDGES) return;
    int d = __ldg(dst + e);
    int p = atomicAdd(&cursor[d], 1);
    csr_eid[p] = e;
    csr_src[p] = __ldg(src + e);
}

// ---------------- graph ranges (batch is sorted) ----------------------------
__global__ void gstart_min_kernel(const int* __restrict__ batch, int* __restrict__ gstart)
{
    int n = blockIdx.x * blockDim.x + threadIdx.x;
    if (n < NNODES) atomicMin(&gstart[__ldg(batch + n)], n);
}

__global__ void gstart_fix_kernel(int* __restrict__ gstart, float* __restrict__ cnt)
{
    __shared__ int sg[NGRAPH + 1];
    int t = threadIdx.x;
    for (int i = t; i <= NGRAPH; i += 1024) sg[i] = gstart[i];
    __syncthreads();
    if (t == 0) {
        sg[NGRAPH] = NNODES;
        for (int g2 = NGRAPH - 1; g2 >= 0; g2--)
            if (sg[g2] > sg[g2 + 1]) sg[g2] = sg[g2 + 1];
    }
    __syncthreads();
    for (int i = t; i <= NGRAPH; i += 1024) gstart[i] = sg[i];
    for (int i = t; i < NGRAPH; i += 1024)
        cnt[i] = fmaxf((float)(sg[i + 1] - sg[i]), 1.0f);
}

// ---------------- GINE aggregate + (1+eps)h fusion --------------------------
// aeff[n] = (1+eps)*h[n] + sum_{e: dst=n} relu(h[src_e] + ee[e])
__global__ void gine_gather_kernel(const float* __restrict__ h,
                                   const float* __restrict__ ee,
                                   const int* __restrict__ rowstart,
                                   const int* __restrict__ csr_eid,
                                   const int* __restrict__ csr_src,
                                   const float* __restrict__ eps_ptr,
                                   float* __restrict__ aeff)
{
    int n = (blockIdx.x * blockDim.x + threadIdx.x) >> 5;
    int lane = threadIdx.x & 31;
    if (n >= NNODES) return;
    float alpha = 1.0f + __ldg(eps_ptr);
    const float4* hn = (const float4*)(h + (size_t)n * HID);
    float4 a0 = __ldg(hn + lane);
    float4 a1 = __ldg(hn + 32 + lane);
    a0.x *= alpha; a0.y *= alpha; a0.z *= alpha; a0.w *= alpha;
    a1.x *= alpha; a1.y *= alpha; a1.z *= alpha; a1.w *= alpha;
    int lo = __ldg(rowstart + n), hi = __ldg(rowstart + n + 1);
    for (int j = lo; j < hi; j++) {
        int eid = __ldg(csr_eid + j);
        int s = __ldg(csr_src + j);
        const float4* ep = (const float4*)(ee + (size_t)eid * HID);
        const float4* hp = (const float4*)(h + (size_t)s * HID);
        float4 e0 = __ldg(ep + lane), h0 = __ldg(hp + lane);
        float4 e1 = __ldg(ep + 32 + lane), h1 = __ldg(hp + 32 + lane);
        a0.x += fmaxf(h0.x + e0.x, 0.f); a0.y += fmaxf(h0.y + e0.y, 0.f);
        a0.z += fmaxf(h0.z + e0.z, 0.f); a0.w += fmaxf(h0.w + e0.w, 0.f);
        a1.x += fmaxf(h1.x + e1.x, 0.f); a1.y += fmaxf(h1.y + e1.y, 0.f);
        a1.z += fmaxf(h1.z + e1.z, 0.f); a1.w += fmaxf(h1.w + e1.w, 0.f);
    }
    float4* ap = (float4*)(aeff + (size_t)n * HID);
    ap[lane] = a0;
    ap[32 + lane] = a1;
}

// ---------------- BN statistics ----------------------------------------------
__global__ void bn_stats_kernel(const float* __restrict__ z, float* __restrict__ stats)
{
    int c = threadIdx.x;
    float s = 0.f, q = 0.f;
    for (int r = blockIdx.x; r < NNODES; r += gridDim.x) {
        float v = z[(size_t)r * HID + c];
        s += v;
        q = fmaf(v, v, q);
    }
    atomicAdd(&stats[c], s);
    atomicAdd(&stats[HID + c], q);
}

// ---------------- BN normalize (in place) ------------------------------------
__global__ void bn_norm_kernel(float* __restrict__ z,
                               const float* __restrict__ stats,
                               const float* __restrict__ gamma,
                               const float* __restrict__ beta)
{
    size_t idx = (size_t)blockIdx.x * blockDim.x + threadIdx.x;
    if (idx >= (size_t)NNODES * HID) return;
    int c = (int)(idx & (HID - 1));
    const float invN = 1.0f / (float)NNODES;
    float mu = __ldg(stats + c) * invN;
    float var = __ldg(stats + HID + c) * invN - mu * mu;
    z[idx] = __ldg(gamma + c) * (z[idx] - mu) * rsqrtf(var + 1e-5f) + __ldg(beta + c);
}

// ---------------- per-graph mean (block per graph; sorted batch) -------------
__global__ void gmean_kernel(const float* __restrict__ z,
                             const int* __restrict__ gstart,
                             const float* __restrict__ cnt,
                             float* __restrict__ gmean)
{
    int g = blockIdx.x;
    int c = threadIdx.x;
    int lo = gstart[g], hi = gstart[g + 1];
    float s = 0.f;
    for (int n = lo; n < hi; n++) s += __ldg(z + (size_t)n * HID + c);
    gmean[(size_t)g * HID + c] = s / cnt[g];
}

// ---------------- PairNorm: center + mean-square-norm ------------------------
__global__ void center_msq_kernel(float* __restrict__ z,
                                  const float* __restrict__ gmean,
                                  const int* __restrict__ batch,
                                  float* __restrict__ msq)
{
    int row = (blockIdx.x * blockDim.x + threadIdx.x) >> 5;
    int lane = threadIdx.x & 31;
    if (row >= NNODES) return;
    int g = __ldg(batch + row);
    float4* zp = (float4*)(z + (size_t)row * HID);
    const float4* mp = (const float4*)(gmean + (size_t)g * HID);
    float acc = 0.f;
#pragma unroll
    for (int i = lane; i < HID / 4; i += 32) {
        float4 v = zp[i];
        float4 m = __ldg(mp + i);
        v.x -= m.x; v.y -= m.y; v.z -= m.z; v.w -= m.w;
        zp[i] = v;
        acc += v.x * v.x + v.y * v.y + v.z * v.z + v.w * v.w;
    }
#pragma unroll
    for (int o = 16; o > 0; o >>= 1) acc += __shfl_down_sync(0xffffffffu, acc, o);
    if (lane == 0) atomicAdd(&msq[g], acc);
}

// ---------------- PairNorm scale + ReLU -> h_next -----------------------------
__global__ void scale_relu_kernel(const float* __restrict__ z,
                                  const float* __restrict__ msq,
                                  const float* __restrict__ cnt,
                                  const int* __restrict__ batch,
                                  float* __restrict__ hout)
{
    size_t idx = (size_t)blockIdx.x * blockDim.x + threadIdx.x;
    if (idx >= (size_t)NNODES * HID) return;
    int r = (int)(idx >> 8);
    int g = __ldg(batch + r);
    float sc = rsqrtf(1e-5f + __ldg(msq + g) / __ldg(cnt + g));
    hout[idx] = fmaxf(z[idx] * sc, 0.f);
}

// ---------------- attention score --------------------------------------------
__global__ void attn_score_kernel(const float* __restrict__ s1,
                                  const float* __restrict__ w2,
                                  const float* __restrict__ b2,
                                  const int* __restrict__ batch,
                                  float* __restrict__ wexp,
                                  float* __restrict__ wsum)
{
    int row = (blockIdx.x * blockDim.x + threadIdx.x) >> 5;
    int lane = threadIdx.x & 31;
    if (row >= NNODES) return;
    float acc = 0.f;
#pragma unroll
    for (int k = lane; k < EDIM; k += 32)
        acc = fmaf(__ldg(s1 + (size_t)row * EDIM + k), __ldg(w2 + k), acc);
#pragma unroll
    for (int o = 16; o > 0; o >>= 1) acc += __shfl_down_sync(0xffffffffu, acc, o);
    if (lane == 0) {
        float w = expf(acc + __ldg(b2));
        wexp[row] = w;
        atomicAdd(&wsum[__ldg(batch + row)], w);
    }
}

// ---------------- pooling: block per graph ------------------------------------
__global__ void pool_graph_kernel(const float* __restrict__ h,
                                  const float* __restrict__ wexp,
                                  const float* __restrict__ wsum,
                                  const int* __restrict__ gstart,
                                  const float* __restrict__ cnt,
                                  float* __restrict__ out)
{
    int g = blockIdx.x;
    int c = threadIdx.x;
    int lo = gstart[g], hi = gstart[g + 1];
    float inv_ws = 1.0f / (wsum[g] + 1e-8f);
    float s = 0.f, mx = 0.f, att = 0.f;
    for (int n = lo; n < hi; n++) {
        float v = __ldg(h + (size_t)n * HID + c);
        float coeff = __ldg(wexp + n) * inv_ws;
        s += v;
        mx = fmaxf(mx, v);
        att = fmaf(v, coeff, att);
    }
    float* og = out + (size_t)g * (3 * HID);
    og[c] = s / cnt[g];
    og[HID + c] = mx;
    og[2 * HID + c] = att;
}

// ---------------- host launch --------------------------------------------------
static inline void launch_tf32(int act, int M, int N, int K,
                               const float* A, const float* B,
                               const float* bias, float* C)
{
    dim3 grid(N / 128, (M + 127) / 128);
    if (act == 0)      tf32_gemm<0><<<grid, 128, GEMM_SMEM_BYTES>>>(M, N, K, A, B, bias, C);
    else if (act == 1) tf32_gemm<1><<<grid, 128, GEMM_SMEM_BYTES>>>(M, N, K, A, B, bias, C);
    else               tf32_gemm<2><<<grid, 128, GEMM_SMEM_BYTES>>>(M, N, K, A, B, bias, C);
}

extern "C" void kernel_launch(void* const* d_in, const int* in_sizes, int n_in,
                              void* d_out, int out_size)
{
    const float* x         = (const float*)d_in[0];
    const float* edge_attr = (const float*)d_in[1];
    const float* node_w    = (const float*)d_in[2];
    const float* node_b    = (const float*)d_in[3];
    const float* edge_w    = (const float*)d_in[4];
    const float* edge_b    = (const float*)d_in[5];
    const float* conv_w    = (const float*)d_in[6];
    const float* conv_b    = (const float*)d_in[7];
    const float* mlp_w1    = (const float*)d_in[8];
    const float* mlp_b1    = (const float*)d_in[9];
    const float* mlp_w2    = (const float*)d_in[10];
    const float* mlp_b2    = (const float*)d_in[11];
    const float* eps       = (const float*)d_in[12];
    const float* bn_gamma  = (const float*)d_in[13];
    const float* bn_beta   = (const float*)d_in[14];
    const float* att_w1    = (const float*)d_in[15];
    const float* att_b1    = (const float*)d_in[16];
    const float* att_w2    = (const float*)d_in[17];
    const float* att_b2    = (const float*)d_in[18];
    const int*   edge_index= (const int*)d_in[19];
    const int*   batch     = (const int*)d_in[20];
    float* out = (float*)d_out;

    const int* src = edge_index;
    const int* dst = edge_index + NEDGES;

    cudaFuncSetAttribute(tf32_gemm<0>, cudaFuncAttributeMaxDynamicSharedMemorySize, GEMM_SMEM_BYTES);
    cudaFuncSetAttribute(tf32_gemm<1>, cudaFuncAttributeMaxDynamicSharedMemorySize, GEMM_SMEM_BYTES);
    cudaFuncSetAttribute(tf32_gemm<2>, cudaFuncAttributeMaxDynamicSharedMemorySize, GEMM_SMEM_BYTES);

    float *p_h0, *p_h1, *p_aeff, *p_tmp, *p_z, *p_e, *p_ee, *p_stats, *p_gmean,
          *p_msq, *p_cnt, *p_wexp, *p_wsum;
    int *p_deg, *p_rowstart, *p_cursor, *p_eid, *p_csrc, *p_gstart;
    cudaGetSymbolAddress((void**)&p_h0, g_h0);
    cudaGetSymbolAddress((void**)&p_h1, g_h1);
    cudaGetSymbolAddress((void**)&p_aeff, g_aeff);
    cudaGetSymbolAddress((void**)&p_tmp, g_tmp);
    cudaGetSymbolAddress((void**)&p_z, g_z);
    cudaGetSymbolAddress((void**)&p_e, g_e);
    cudaGetSymbolAddress((void**)&p_ee, g_ee);
    cudaGetSymbolAddress((void**)&p_stats, g_stats);
    cudaGetSymbolAddress((void**)&p_gmean, g_gmean);
    cudaGetSymbolAddress((void**)&p_msq, g_msq);
    cudaGetSymbolAddress((void**)&p_cnt, g_cnt);
    cudaGetSymbolAddress((void**)&p_wexp, g_wexp);
    cudaGetSymbolAddress((void**)&p_wsum, g_wsum);
    cudaGetSymbolAddress((void**)&p_deg, g_deg);
    cudaGetSymbolAddress((void**)&p_rowstart, g_rowstart);
    cudaGetSymbolAddress((void**)&p_cursor, g_cursor);
    cudaGetSymbolAddress((void**)&p_eid, g_csr_eid);
    cudaGetSymbolAddress((void**)&p_csrc, g_csr_src);
    cudaGetSymbolAddress((void**)&p_gstart, g_gstart);

    // ----- CSR build (edge_index fixed across layers)
    cudaMemsetAsync(p_deg, 0, NNODES * sizeof(int));
    deg_kernel<<<(NEDGES + 255) / 256, 256>>>(dst, p_deg);
    csr_scan_kernel<<<1, 1024>>>(p_deg, p_rowstart, p_cursor);
    csr_fill_kernel<<<(NEDGES + 255) / 256, 256>>>(src, dst, p_cursor, p_eid, p_csrc);

    // ----- graph ranges + counts (batch sorted)
    cudaMemsetAsync(p_gstart, 0x7F, (NGRAPH + 1) * sizeof(int));
    gstart_min_kernel<<<(NNODES + 255) / 256, 256>>>(batch, p_gstart);
    gstart_fix_kernel<<<1, 1024>>>(p_gstart, p_cnt);

    // ----- embeddings
    launch_tf32(0, NNODES, HID, NODE_F, x, node_w, node_b, p_h0);
    {
        size_t total = (size_t)NEDGES * EDIM;
        edge_embed_kernel<<<(unsigned)((total + 255) / 256), 256>>>(edge_attr, edge_w, edge_b, p_e);
    }

    float* h_cur = p_h0;
    float* h_nxt = p_h1;

    for (int i = 0; i < NLAYER; i++) {
        // ee = e @ conv_w[i] + conv_b[i]   [E, 256], K=128
        launch_tf32(0, NEDGES, HID, EDIM, p_e,
                    conv_w + (size_t)i * EDIM * HID, conv_b + (size_t)i * HID, p_ee);

        // aeff = (1+eps)h + gather-agg
        gine_gather_kernel<<<(NNODES * 32 + 255) / 256, 256>>>(
            h_cur, p_ee, p_rowstart, p_eid, p_csrc, eps + i, p_aeff);

        // tmp = relu(aeff @ w1 + b1)
        launch_tf32(1, NNODES, HID, HID, p_aeff,
                    mlp_w1 + (size_t)i * HID * HID, mlp_b1 + (size_t)i * HID, p_tmp);

        // z = tmp @ w2 + b2
        launch_tf32(0, NNODES, HID, HID, p_tmp,
                    mlp_w2 + (size_t)i * HID * HID, mlp_b2 + (size_t)i * HID, p_z);

        // BatchNorm
        cudaMemsetAsync(p_stats, 0, 2 * HID * sizeof(float));
        bn_stats_kernel<<<1024, HID>>>(p_z, p_stats);
        bn_norm_kernel<<<(unsigned)(((size_t)NNODES * HID + 255) / 256), 256>>>(
            p_z, p_stats, bn_gamma + (size_t)i * HID, bn_beta + (size_t)i * HID);

        // PairNorm
        gmean_kernel<<<NGRAPH, HID>>>(p_z, p_gstart, p_cnt, p_gmean);
        cudaMemsetAsync(p_msq, 0, NGRAPH * sizeof(float));
        center_msq_kernel<<<(NNODES * 32 + 255) / 256, 256>>>(p_z, p_gmean, batch, p_msq);
        scale_relu_kernel<<<(unsigned)(((size_t)NNODES * HID + 255) / 256), 256>>>(
            p_z, p_msq, p_cnt, batch, h_nxt);

        float* t = h_cur; h_cur = h_nxt; h_nxt = t;
    }

    // attention hidden: s1 = tanh(h @ att_w1 + att_b1)   [N, 128], K=256
    launch_tf32(2, NNODES, EDIM, HID, h_cur, att_w1, att_b1, p_tmp);

    cudaMemsetAsync(p_wsum, 0, NGRAPH * sizeof(float));
    attn_score_kernel<<<(NNODES * 32 + 255) / 256, 256>>>(p_tmp, att_w2, att_b2, batch, p_wexp, p_wsum);

    // pooling (block per graph; writes every output element)
    pool_graph_kernel<<<NGRAPH, HID>>>(h_cur, p_wexp, p_wsum, p_gstart, p_cnt, out);

    (void)in_sizes; (void)n_in; (void)out_size;
}

// round 3
// speedup vs baseline: 3.3373x; 1.5223x over previous
#include <cuda_runtime.h>
#include <math.h>
#include <stdint.h>

#define NNODES 100000
#define NEDGES 320000
#define NGRAPH 2048
#define HID    256
#define EDIM   128
#define NODE_F 48
#define EDGE_F 6
#define NLAYER 8

// ---------------- scratch (device globals) ----------------------------------
__device__ float g_h0 [(size_t)NNODES * HID];
__device__ float g_h1 [(size_t)NNODES * HID];
__device__ float g_aeff[(size_t)NNODES * HID];
__device__ float g_tmp[(size_t)NNODES * HID];
__device__ float g_z  [(size_t)NNODES * HID];
__device__ float g_stats[2 * HID];
__device__ float g_a   [HID];
__device__ float g_gsum[(size_t)NGRAPH * HID];   // per-graph sums -> means
__device__ float g_gsq [(size_t)NGRAPH * HID];   // per-graph sum of squares
__device__ float g_sc  [NGRAPH];                 // pairnorm scale per graph
__device__ float g_cnt [NGRAPH];
__device__ float g_wexp[NNODES];
__device__ float g_wsum[NGRAPH];
__device__ float g_wf  [(size_t)NLAYER * 7 * HID]; // fused edge weights [L][7][256]
__device__ int   g_deg [NNODES];
__device__ int   g_rowstart[NNODES + 1];
__device__ int   g_cursor[NNODES];
__device__ int   g_csr_eid[NEDGES];
__device__ int   g_csr_src[NEDGES];
__device__ int   g_gstart[NGRAPH + 1];

// ---------------- TF32 tensor-core GEMM ------------------------------------
// C = act( A @ B + bias ),  A [M,K] row-major, B [K,N] row-major, bias [N].
// Requires N % 128 == 0. 256 threads, 8 warps (4x2), warp tile 32x64,
// CTA tile 128x128, BK=32, double-buffered cp.async, mma m16n8k8 tf32 (rna).
#define GA_STRIDE 36
#define GB_STRIDE 132
#define A_TILE_W (128 * GA_STRIDE)
#define B_TILE_W (32 * GB_STRIDE)
#define GEMM_SMEM_BYTES ((2 * A_TILE_W + 2 * B_TILE_W) * 4)

__device__ __forceinline__ uint32_t f2tf32(float x) {
    uint32_t r;
    asm volatile("cvt.rna.tf32.f32 %0, %1;" : "=r"(r) : "f"(x));
    return r;
}
__device__ __forceinline__ void cp16(float* dst, const float* src, bool pred) {
    unsigned d = (unsigned)__cvta_generic_to_shared(dst);
    int sz = pred ? 16 : 0;
    asm volatile("cp.async.cg.shared.global [%0], [%1], 16, %2;" :: "r"(d), "l"(src), "r"(sz));
}
__device__ __forceinline__ void cp_commit() { asm volatile("cp.async.commit_group;"); }
template <int Np>
__device__ __forceinline__ void cp_wait() { asm volatile("cp.async.wait_group %0;" :: "n"(Np)); }

__device__ __forceinline__ void mma_tf32(float* c, const uint32_t* a, const uint32_t* b) {
    asm volatile(
        "mma.sync.aligned.m16n8k8.row.col.f32.tf32.tf32.f32 "
        "{%0,%1,%2,%3}, {%4,%5,%6,%7}, {%8,%9}, {%0,%1,%2,%3};"
        : "+f"(c[0]), "+f"(c[1]), "+f"(c[2]), "+f"(c[3])
        : "r"(a[0]), "r"(a[1]), "r"(a[2]), "r"(a[3]), "r"(b[0]), "r"(b[1]));
}

template <int ACT>
__global__ __launch_bounds__(256, 2) void tf32_gemm(
    int M, int N, int K,
    const float* __restrict__ A, const float* __restrict__ B,
    const float* __restrict__ bias, float* __restrict__ C)
{
    extern __shared__ float sm[];
    float* As = sm;
    float* Bs = sm + 2 * A_TILE_W;

    const int tid = threadIdx.x;
    const int warp = tid >> 5;
    const int lane = tid & 31;
    const int g = lane >> 2;
    const int tq = lane & 3;
    const int m0 = blockIdx.y * 128;
    const int n0 = blockIdx.x * 128;
    const int wm = (warp >> 1) * 32;
    const int wn = (warp & 1) * 64;

    float acc[2][8][4];
#pragma unroll
    for (int i = 0; i < 2; i++)
#pragma unroll
        for (int j = 0; j < 8; j++)
#pragma unroll
            for (int r = 0; r < 4; r++) acc[i][j][r] = 0.0f;

    const int arow = tid >> 3;   // 0..31 (+it*32)
    const int ac4 = tid & 7;
    const int brow = tid >> 5;   // 0..7 (+it*8)
    const int bc4 = tid & 31;

    const int nk = (K + 31) / 32;

    {
#pragma unroll
        for (int it = 0; it < 4; it++) {
            int row = arow + it * 32;
            int gm = m0 + row;
            int gk = ac4 * 4;
            bool p = (gm < M) && (gk < K);
            const float* src = A + (size_t)(p ? gm : 0) * K + (p ? gk : 0);
            cp16(As + row * GA_STRIDE + ac4 * 4, src, p);
        }
#pragma unroll
        for (int it = 0; it < 4; it++) {
            int row = brow + it * 8;
            bool p = (row < K);
            const float* src = B + (size_t)(p ? row : 0) * N + n0 + bc4 * 4;
            cp16(Bs + row * GB_STRIDE + bc4 * 4, src, p);
        }
        cp_commit();
    }

    int buf = 0;
    for (int i = 0; i < nk; i++) {
        if (i + 1 < nk) {
            const int kc = i + 1;
            float* Ad = As + (buf ^ 1) * A_TILE_W;
            float* Bd = Bs + (buf ^ 1) * B_TILE_W;
#pragma unroll
            for (int it = 0; it < 4; it++) {
                int row = arow + it * 32;
                int gm = m0 + row;
                int gk = kc * 32 + ac4 * 4;
                bool p = (gm < M) && (gk < K);
                const float* src = A + (size_t)(p ? gm : 0) * K + (p ? gk : 0);
                cp16(Ad + row * GA_STRIDE + ac4 * 4, src, p);
            }
#pragma unroll
            for (int it = 0; it < 4; it++) {
                int row = brow + it * 8;
                int gk = kc * 32 + row;
                bool p = (gk < K);
                const float* src = B + (size_t)(p ? gk : 0) * N + n0 + bc4 * 4;
                cp16(Bd + row * GB_STRIDE + bc4 * 4, src, p);
            }
            cp_commit();
            cp_wait<1>();
        } else {
            cp_wait<0>();
        }
        __syncthreads();

        const float* Ab = As + buf * A_TILE_W;
        const float* Bb = Bs + buf * B_TILE_W;
#pragma unroll
        for (int kk = 0; kk < 4; kk++) {
            const int k = kk * 8;
            uint32_t af[2][4];
#pragma unroll
            for (int mi = 0; mi < 2; mi++) {
                const float* p = Ab + (wm + mi * 16 + g) * GA_STRIDE + k + tq;
                af[mi][0] = f2tf32(p[0]);
                af[mi][1] = f2tf32(p[8 * GA_STRIDE]);
                af[mi][2] = f2tf32(p[4]);
                af[mi][3] = f2tf32(p[8 * GA_STRIDE + 4]);
            }
            uint32_t bf[8][2];
#pragma unroll
            for (int ni = 0; ni < 8; ni++) {
                const float* p = Bb + (k + tq) * GB_STRIDE + wn + ni * 8 + g;
                bf[ni][0] = f2tf32(p[0]);
                bf[ni][1] = f2tf32(p[4 * GB_STRIDE]);
            }
#pragma unroll
            for (int mi = 0; mi < 2; mi++)
#pragma unroll
                for (int ni = 0; ni < 8; ni++)
                    mma_tf32(acc[mi][ni], af[mi], bf[ni]);
        }
        __syncthreads();
        buf ^= 1;
    }

#pragma unroll
    for (int mi = 0; mi < 2; mi++) {
        int r0 = m0 + wm + mi * 16 + g;
        int r1 = r0 + 8;
#pragma unroll
        for (int ni = 0; ni < 8; ni++) {
            int col = n0 + wn + ni * 8 + tq * 2;
            float b0 = __ldg(bias + col);
            float b1 = __ldg(bias + col + 1);
            float v0 = acc[mi][ni][0] + b0;
            float v1 = acc[mi][ni][1] + b1;
            float v2 = acc[mi][ni][2] + b0;
            float v3 = acc[mi][ni][3] + b1;
            if (ACT == 1) {
                v0 = fmaxf(v0, 0.f); v1 = fmaxf(v1, 0.f);
                v2 = fmaxf(v2, 0.f); v3 = fmaxf(v3, 0.f);
            } else if (ACT == 2) {
                v0 = tanhf(v0); v1 = tanhf(v1);
                v2 = tanhf(v2); v3 = tanhf(v3);
            }
            if (r0 < M) *(float2*)(C + (size_t)r0 * N + col) = make_float2(v0, v1);
            if (r1 < M) *(float2*)(C + (size_t)r1 * N + col) = make_float2(v2, v3);
        }
    }
}

// ---------------- fused edge weights: W_f = edge_w @ conv_w, b_f = ... -------
__global__ void wfuse_kernel(const float* __restrict__ edge_w,
                             const float* __restrict__ edge_b,
                             const float* __restrict__ conv_w,
                             const float* __restrict__ conv_b,
                             float* __restrict__ wf)
{
    int layer = blockIdx.x;
    int k = blockIdx.y;      // 0..6 (6 = bias row)
    int c = threadIdx.x;
    const float* cw = conv_w + (size_t)layer * EDIM * HID;
    float s = 0.f;
    if (k < EDGE_F) {
        for (int j = 0; j < EDIM; j++)
            s = fmaf(__ldg(edge_w + k * EDIM + j), __ldg(cw + (size_t)j * HID + c), s);
    } else {
        for (int j = 0; j < EDIM; j++)
            s = fmaf(__ldg(edge_b + j), __ldg(cw + (size_t)j * HID + c), s);
        s += __ldg(conv_b + (size_t)layer * HID + c);
    }
    wf[((size_t)layer * 7 + k) * HID + c] = s;
}

// ---------------- CSR build --------------------------------------------------
__global__ void deg_kernel(const int* __restrict__ dst, int* __restrict__ deg)
{
    int e = blockIdx.x * blockDim.x + threadIdx.x;
    if (e < NEDGES) atomicAdd(&deg[__ldg(dst + e)], 1);
}

__global__ void csr_scan_kernel(const int* __restrict__ deg,
                                int* __restrict__ rowstart,
                                int* __restrict__ cursor)
{
    const int CH = (NNODES + 1023) / 1024;
    __shared__ int ssum[1024];
    int t = threadIdx.x;
    int lo = t * CH;
    int hi = min(lo + CH, NNODES);
    int s = 0;
    for (int i = lo; i < hi; i++) s += deg[i];
    ssum[t] = s;
    __syncthreads();
    for (int off = 1; off < 1024; off <<= 1) {
        int v = (t >= off) ? ssum[t - off] : 0;
        __syncthreads();
        ssum[t] += v;
        __syncthreads();
    }
    int run = ssum[t] - s;
    for (int i = lo; i < hi; i++) {
        rowstart[i] = run;
        cursor[i] = run;
        run += deg[i];
    }
    if (hi == NNODES) rowstart[NNODES] = run;
}

__global__ void csr_fill_kernel(const int* __restrict__ src,
                                const int* __restrict__ dst,
                                int* __restrict__ cursor,
                                int* __restrict__ csr_eid,
                                int* __restrict__ csr_src)
{
    int e = blockIdx.x * blockDim.x + threadIdx.x;
    if (e >= NEDGES) return;
    int d = __ldg(dst + e);
    int p = atomicAdd(&cursor[d], 1);
    csr_eid[p] = e;
    csr_src[p] = __ldg(src + e);
}

// ---------------- graph ranges (batch is sorted) ----------------------------
__global__ void gstart_min_kernel(const int* __restrict__ batch, int* __restrict__ gstart)
{
    int n = blockIdx.x * blockDim.x + threadIdx.x;
    if (n < NNODES) atomicMin(&gstart[__ldg(batch + n)], n);
}

__global__ void gstart_fix_kernel(int* __restrict__ gstart, float* __restrict__ cnt)
{
    __shared__ int sg[NGRAPH + 1];
    int t = threadIdx.x;
    for (int i = t; i <= NGRAPH; i += 1024) sg[i] = gstart[i];
    __syncthreads();
    if (t == 0) {
        sg[NGRAPH] = NNODES;
        for (int g2 = NGRAPH - 1; g2 >= 0; g2--)
            if (sg[g2] > sg[g2 + 1]) sg[g2] = sg[g2 + 1];
    }
    __syncthreads();
    for (int i = t; i <= NGRAPH; i += 1024) gstart[i] = sg[i];
    for (int i = t; i < NGRAPH; i += 1024)
        cnt[i] = fmaxf((float)(sg[i + 1] - sg[i]), 1.0f);
}

// ---------------- GINE gather with on-the-fly edge embedding ----------------
// aeff[n] = (1+eps)h[n] + sum_{e:dst=n} relu(h[src_e] + ea[e] @ W_f + b_f)
__global__ __launch_bounds__(256) void gine_gather_fused(
    const float* __restrict__ h,
    const float* __restrict__ ea,          // [E, 6]
    const int* __restrict__ rowstart,
    const int* __restrict__ csr_eid,
    const int* __restrict__ csr_src,
    const float* __restrict__ wf,          // layer slice [7][256]
    const float* __restrict__ eps_ptr,
    float* __restrict__ aeff)
{
    const int lane = threadIdx.x & 31;
    const int warp_g = (blockIdx.x * blockDim.x + threadIdx.x) >> 5;
    const int nwarps = (gridDim.x * blockDim.x) >> 5;
    const float alpha = 1.0f + __ldg(eps_ptr);

    // load fused weights for this lane's 8 channels into registers
    float4 w0[EDGE_F], w1[EDGE_F];
#pragma unroll
    for (int k = 0; k < EDGE_F; k++) {
        w0[k] = __ldg((const float4*)(wf + k * HID) + lane);
        w1[k] = __ldg((const float4*)(wf + k * HID) + 32 + lane);
    }
    float4 bf0 = __ldg((const float4*)(wf + EDGE_F * HID) + lane);
    float4 bf1 = __ldg((const float4*)(wf + EDGE_F * HID) + 32 + lane);

    for (int n = warp_g; n < NNODES; n += nwarps) {
        const float4* hn = (const float4*)(h + (size_t)n * HID);
        float4 a0 = __ldg(hn + lane);
        float4 a1 = __ldg(hn + 32 + lane);
        a0.x *= alpha; a0.y *= alpha; a0.z *= alpha; a0.w *= alpha;
        a1.x *= alpha; a1.y *= alpha; a1.z *= alpha; a1.w *= alpha;

        int lo = __ldg(rowstart + n), hi = __ldg(rowstart + n + 1);
        for (int j = lo; j < hi; j++) {
            int eid = __ldg(csr_eid + j);
            int s = __ldg(csr_src + j);
            const float* er = ea + (size_t)eid * EDGE_F;
            float e0 = __ldg(er + 0), e1 = __ldg(er + 1), e2 = __ldg(er + 2);
            float e3 = __ldg(er + 3), e4 = __ldg(er + 4), e5 = __ldg(er + 5);

            float4 ee0 = bf0, ee1 = bf1;
            ee0.x = fmaf(e0, w0[0].x, ee0.x); ee0.y = fmaf(e0, w0[0].y, ee0.y);
            ee0.z = fmaf(e0, w0[0].z, ee0.z); ee0.w = fmaf(e0, w0[0].w, ee0.w);
            ee1.x = fmaf(e0, w1[0].x, ee1.x); ee1.y = fmaf(e0, w1[0].y, ee1.y);
            ee1.z = fmaf(e0, w1[0].z, ee1.z); ee1.w = fmaf(e0, w1[0].w, ee1.w);
            ee0.x = fmaf(e1, w0[1].x, ee0.x); ee0.y = fmaf(e1, w0[1].y, ee0.y);
            ee0.z = fmaf(e1, w0[1].z, ee0.z); ee0.w = fmaf(e1, w0[1].w, ee0.w);
            ee1.x = fmaf(e1, w1[1].x, ee1.x); ee1.y = fmaf(e1, w1[1].y, ee1.y);
            ee1.z = fmaf(e1, w1[1].z, ee1.z); ee1.w = fmaf(e1, w1[1].w, ee1.w);
            ee0.x = fmaf(e2, w0[2].x, ee0.x); ee0.y = fmaf(e2, w0[2].y, ee0.y);
            ee0.z = fmaf(e2, w0[2].z, ee0.z); ee0.w = fmaf(e2, w0[2].w, ee0.w);
            ee1.x = fmaf(e2, w1[2].x, ee1.x); ee1.y = fmaf(e2, w1[2].y, ee1.y);
            ee1.z = fmaf(e2, w1[2].z, ee1.z); ee1.w = fmaf(e2, w1[2].w, ee1.w);
            ee0.x = fmaf(e3, w0[3].x, ee0.x); ee0.y = fmaf(e3, w0[3].y, ee0.y);
            ee0.z = fmaf(e3, w0[3].z, ee0.z); ee0.w = fmaf(e3, w0[3].w, ee0.w);
            ee1.x = fmaf(e3, w1[3].x, ee1.x); ee1.y = fmaf(e3, w1[3].y, ee1.y);
            ee1.z = fmaf(e3, w1[3].z, ee1.z); ee1.w = fmaf(e3, w1[3].w, ee1.w);
            ee0.x = fmaf(e4, w0[4].x, ee0.x); ee0.y = fmaf(e4, w0[4].y, ee0.y);
            ee0.z = fmaf(e4, w0[4].z, ee0.z); ee0.w = fmaf(e4, w0[4].w, ee0.w);
            ee1.x = fmaf(e4, w1[4].x, ee1.x); ee1.y = fmaf(e4, w1[4].y, ee1.y);
            ee1.z = fmaf(e4, w1[4].z, ee1.z); ee1.w = fmaf(e4, w1[4].w, ee1.w);
            ee0.x = fmaf(e5, w0[5].x, ee0.x); ee0.y = fmaf(e5, w0[5].y, ee0.y);
            ee0.z = fmaf(e5, w0[5].z, ee0.z); ee0.w = fmaf(e5, w0[5].w, ee0.w);
            ee1.x = fmaf(e5, w1[5].x, ee1.x); ee1.y = fmaf(e5, w1[5].y, ee1.y);
            ee1.z = fmaf(e5, w1[5].z, ee1.z); ee1.w = fmaf(e5, w1[5].w, ee1.w);

            const float4* hp = (const float4*)(h + (size_t)s * HID);
            float4 h0 = __ldg(hp + lane);
            float4 h1 = __ldg(hp + 32 + lane);
            a0.x += fmaxf(h0.x + ee0.x, 0.f); a0.y += fmaxf(h0.y + ee0.y, 0.f);
            a0.z += fmaxf(h0.z + ee0.z, 0.f); a0.w += fmaxf(h0.w + ee0.w, 0.f);
            a1.x += fmaxf(h1.x + ee1.x, 0.f); a1.y += fmaxf(h1.y + ee1.y, 0.f);
            a1.z += fmaxf(h1.z + ee1.z, 0.f); a1.w += fmaxf(h1.w + ee1.w, 0.f);
        }
        float4* ap = (float4*)(aeff + (size_t)n * HID);
        ap[lane] = a0;
        ap[32 + lane] = a1;
    }
}

// ---------------- per-graph (sum, sumsq) -------------------------------------
__global__ void graph_stats_kernel(const float* __restrict__ z,
                                   const int* __restrict__ gstart,
                                   float* __restrict__ gsum,
                                   float* __restrict__ gsq)
{
    int g = blockIdx.x;
    int c = threadIdx.x;
    int lo = gstart[g], hi = gstart[g + 1];
    float s = 0.f, q = 0.f;
    for (int n = lo; n < hi; n++) {
        float v = __ldg(z + (size_t)n * HID + c);
        s += v;
        q = fmaf(v, v, q);
    }
    gsum[(size_t)g * HID + c] = s;
    gsq[(size_t)g * HID + c] = q;
}

// ---------------- channel stats from graph partials --------------------------
__global__ void chan_stats_kernel(const float* __restrict__ gsum,
                                  const float* __restrict__ gsq,
                                  float* __restrict__ stats)
{
    int c = threadIdx.x;
    int b = blockIdx.x;          // 16 blocks x 128 graphs
    float s = 0.f, q = 0.f;
    for (int g = b * 128; g < (b + 1) * 128; g++) {
        s += __ldg(gsum + (size_t)g * HID + c);
        q += __ldg(gsq + (size_t)g * HID + c);
    }
    atomicAdd(&stats[c], s);
    atomicAdd(&stats[HID + c], q);
}

// ---------------- a_c = gamma * rsqrt(var + 1e-5) ---------------------------
__global__ void finalize_a_kernel(const float* __restrict__ stats,
                                  const float* __restrict__ gamma,
                                  float* __restrict__ a)
{
    int c = threadIdx.x;
    const float invN = 1.0f / (float)NNODES;
    float mu = stats[c] * invN;
    float var = stats[HID + c] * invN - mu * mu;
    a[c] = __ldg(gamma + c) * rsqrtf(var + 1e-5f);
}

// ---------------- per-graph msq -> scale; gsum -> mean -----------------------
__global__ void graph_msq_kernel(const float* __restrict__ a,
                                 const float* __restrict__ cnt,
                                 float* __restrict__ gsum,
                                 const float* __restrict__ gsq,
                                 float* __restrict__ sc)
{
    __shared__ float red[HID];
    int g = blockIdx.x;
    int c = threadIdx.x;
    float cg = cnt[g];
    size_t i = (size_t)g * HID + c;
    float S = gsum[i], Q = gsq[i];
    float m = S / cg;
    gsum[i] = m;
    float ac = a[c];
    red[c] = ac * ac * (Q - cg * m * m);
    __syncthreads();
    for (int o = HID / 2; o > 0; o >>= 1) {
        if (c < o) red[c] += red[c + o];
        __syncthreads();
    }
    if (c == 0) sc[g] = rsqrtf(1e-5f + red[0] / cg);
}

// ---------------- fused BN+PairNorm normalize + ReLU ------------------------
__global__ void final_norm_kernel(const float* __restrict__ z,
                                  const float* __restrict__ a,
                                  const float* __restrict__ gmean,
                                  const float* __restrict__ sc,
                                  const int* __restrict__ batch,
                                  float* __restrict__ hout)
{
    int r = blockIdx.x;          // one block per node (block = 256 = HID)
    int c = threadIdx.x;
    int g = __ldg(batch + r);
    size_t i = (size_t)r * HID + c;
    float v = __ldg(a + c) * (z[i] - __ldg(gmean + (size_t)g * HID + c)) * __ldg(sc + g);
    hout[i] = fmaxf(v, 0.f);
}

// ---------------- attention score --------------------------------------------
__global__ void attn_score_kernel(const float* __restrict__ s1,
                                  const float* __restrict__ w2,
                                  const float* __restrict__ b2,
                                  const int* __restrict__ batch,
                                  float* __restrict__ wexp,
                                  float* __restrict__ wsum)
{
    int row = (blockIdx.x * blockDim.x + threadIdx.x) >> 5;
    int lane = threadIdx.x & 31;
    if (row >= NNODES) return;
    float acc = 0.f;
#pragma unroll
    for (int k = lane; k < EDIM; k += 32)
        acc = fmaf(__ldg(s1 + (size_t)row * EDIM + k), __ldg(w2 + k), acc);
#pragma unroll
    for (int o = 16; o > 0; o >>= 1) acc += __shfl_down_sync(0xffffffffu, acc, o);
    if (lane == 0) {
        float w = expf(acc + __ldg(b2));
        wexp[row] = w;
        atomicAdd(&wsum[__ldg(batch + row)], w);
    }
}

// ---------------- pooling: block per graph ------------------------------------
__global__ void pool_graph_kernel(const float* __restrict__ h,
                                  const float* __restrict__ wexp,
                                  const float* __restrict__ wsum,
                                  const int* __restrict__ gstart,
                                  const float* __restrict__ cnt,
                                  float* __restrict__ out)
{
    int g = blockIdx.x;
    int c = threadIdx.x;
    int lo = gstart[g], hi = gstart[g + 1];
    float inv_ws = 1.0f / (wsum[g] + 1e-8f);
    float s = 0.f, mx = 0.f, att = 0.f;
    for (int n = lo; n < hi; n++) {
        float v = __ldg(h + (size_t)n * HID + c);
        float coeff = __ldg(wexp + n) * inv_ws;
        s += v;
        mx = fmaxf(mx, v);
        att = fmaf(v, coeff, att);
    }
    float* og = out + (size_t)g * (3 * HID);
    og[c] = s / cnt[g];
    og[HID + c] = mx;
    og[2 * HID + c] = att;
}

// ---------------- host launch --------------------------------------------------
static inline void launch_tf32(int act, int M, int N, int K,
                               const float* A, const float* B,
                               const float* bias, float* C)
{
    dim3 grid(N / 128, (M + 127) / 128);
    if (act == 0)      tf32_gemm<0><<<grid, 256, GEMM_SMEM_BYTES>>>(M, N, K, A, B, bias, C);
    else if (act == 1) tf32_gemm<1><<<grid, 256, GEMM_SMEM_BYTES>>>(M, N, K, A, B, bias, C);
    else               tf32_gemm<2><<<grid, 256, GEMM_SMEM_BYTES>>>(M, N, K, A, B, bias, C);
}

extern "C" void kernel_launch(void* const* d_in, const int* in_sizes, int n_in,
                              void* d_out, int out_size)
{
    const float* x         = (const float*)d_in[0];
    const float* edge_attr = (const float*)d_in[1];
    const float* node_w    = (const float*)d_in[2];
    const float* node_b    = (const float*)d_in[3];
    const float* edge_w    = (const float*)d_in[4];
    const float* edge_b    = (const float*)d_in[5];
    const float* conv_w    = (const float*)d_in[6];
    const float* conv_b    = (const float*)d_in[7];
    const float* mlp_w1    = (const float*)d_in[8];
    const float* mlp_b1    = (const float*)d_in[9];
    const float* mlp_w2    = (const float*)d_in[10];
    const float* mlp_b2    = (const float*)d_in[11];
    const float* eps       = (const float*)d_in[12];
    const float* bn_gamma  = (const float*)d_in[13];
    const float* bn_beta   = (const float*)d_in[14];
    const float* att_w1    = (const float*)d_in[15];
    const float* att_b1    = (const float*)d_in[16];
    const float* att_w2    = (const float*)d_in[17];
    const float* att_b2    = (const float*)d_in[18];
    const int*   edge_index= (const int*)d_in[19];
    const int*   batch     = (const int*)d_in[20];
    float* out = (float*)d_out;
    (void)bn_beta;   // cancels exactly under PairNorm centering

    const int* src = edge_index;
    const int* dst = edge_index + NEDGES;

    cudaFuncSetAttribute(tf32_gemm<0>, cudaFuncAttributeMaxDynamicSharedMemorySize, GEMM_SMEM_BYTES);
    cudaFuncSetAttribute(tf32_gemm<1>, cudaFuncAttributeMaxDynamicSharedMemorySize, GEMM_SMEM_BYTES);
    cudaFuncSetAttribute(tf32_gemm<2>, cudaFuncAttributeMaxDynamicSharedMemorySize, GEMM_SMEM_BYTES);

    float *p_h0, *p_h1, *p_aeff, *p_tmp, *p_z, *p_stats, *p_a, *p_gsum, *p_gsq,
          *p_sc, *p_cnt, *p_wexp, *p_wsum, *p_wf;
    int *p_deg, *p_rowstart, *p_cursor, *p_eid, *p_csrc, *p_gstart;
    cudaGetSymbolAddress((void**)&p_h0, g_h0);
    cudaGetSymbolAddress((void**)&p_h1, g_h1);
    cudaGetSymbolAddress((void**)&p_aeff, g_aeff);
    cudaGetSymbolAddress((void**)&p_tmp, g_tmp);
    cudaGetSymbolAddress((void**)&p_z, g_z);
    cudaGetSymbolAddress((void**)&p_stats, g_stats);
    cudaGetSymbolAddress((void**)&p_a, g_a);
    cudaGetSymbolAddress((void**)&p_gsum, g_gsum);
    cudaGetSymbolAddress((void**)&p_gsq, g_gsq);
    cudaGetSymbolAddress((void**)&p_sc, g_sc);
    cudaGetSymbolAddress((void**)&p_cnt, g_cnt);
    cudaGetSymbolAddress((void**)&p_wexp, g_wexp);
    cudaGetSymbolAddress((void**)&p_wsum, g_wsum);
    cudaGetSymbolAddress((void**)&p_wf, g_wf);
    cudaGetSymbolAddress((void**)&p_deg, g_deg);
    cudaGetSymbolAddress((void**)&p_rowstart, g_rowstart);
    cudaGetSymbolAddress((void**)&p_cursor, g_cursor);
    cudaGetSymbolAddress((void**)&p_eid, g_csr_eid);
    cudaGetSymbolAddress((void**)&p_csrc, g_csr_src);
    cudaGetSymbolAddress((void**)&p_gstart, g_gstart);

    // ----- CSR build
    cudaMemsetAsync(p_deg, 0, NNODES * sizeof(int));
    deg_kernel<<<(NEDGES + 255) / 256, 256>>>(dst, p_deg);
    csr_scan_kernel<<<1, 1024>>>(p_deg, p_rowstart, p_cursor);
    csr_fill_kernel<<<(NEDGES + 255) / 256, 256>>>(src, dst, p_cursor, p_eid, p_csrc);

    // ----- graph ranges + counts
    cudaMemsetAsync(p_gstart, 0x7F, (NGRAPH + 1) * sizeof(int));
    gstart_min_kernel<<<(NNODES + 255) / 256, 256>>>(batch, p_gstart);
    gstart_fix_kernel<<<1, 1024>>>(p_gstart, p_cnt);

    // ----- fused edge weights for all layers
    wfuse_kernel<<<dim3(NLAYER, 7), HID>>>(edge_w, edge_b, conv_w, conv_b, p_wf);

    // ----- node embedding
    launch_tf32(0, NNODES, HID, NODE_F, x, node_w, node_b, p_h0);

    float* h_cur = p_h0;
    float* h_nxt = p_h1;

    for (int i = 0; i < NLAYER; i++) {
        gine_gather_fused<<<1024, 256>>>(
            h_cur, edge_attr, p_rowstart, p_eid, p_csrc,
            p_wf + (size_t)i * 7 * HID, eps + i, p_aeff);

        launch_tf32(1, NNODES, HID, HID, p_aeff,
                    mlp_w1 + (size_t)i * HID * HID, mlp_b1 + (size_t)i * HID, p_tmp);
        launch_tf32(0, NNODES, HID, HID, p_tmp,
                    mlp_w2 + (size_t)i * HID * HID, mlp_b2 + (size_t)i * HID, p_z);

        // fused BN + PairNorm (affine-collapsed)
        graph_stats_kernel<<<NGRAPH, HID>>>(p_z, p_gstart, p_gsum, p_gsq);
        cudaMemsetAsync(p_stats, 0, 2 * HID * sizeof(float));
        chan_stats_kernel<<<16, HID>>>(p_gsum, p_gsq, p_stats);
        finalize_a_kernel<<<1, HID>>>(p_stats, bn_gamma + (size_t)i * HID, p_a);
        graph_msq_kernel<<<NGRAPH, HID>>>(p_a, p_cnt, p_gsum, p_gsq, p_sc);
        final_norm_kernel<<<NNODES, HID>>>(p_z, p_a, p_gsum, p_sc, batch, h_nxt);

        float* t = h_cur; h_cur = h_nxt; h_nxt = t;
    }

    // attention hidden: s1 = tanh(h @ att_w1 + att_b1)
    launch_tf32(2, NNODES, EDIM, HID, h_cur, att_w1, att_b1, p_tmp);

    cudaMemsetAsync(p_wsum, 0, NGRAPH * sizeof(float));
    attn_score_kernel<<<(NNODES * 32 + 255) / 256, 256>>>(p_tmp, att_w2, att_b2, batch, p_wexp, p_wsum);

    pool_graph_kernel<<<NGRAPH, HID>>>(h_cur, p_wexp, p_wsum, p_gstart, p_cnt, out);

    (void)in_sizes; (void)n_in; (void)out_size;
}

// round 5
// speedup vs baseline: 4.0513x; 1.2140x over previous
#include <cuda_runtime.h>
#include <cuda_fp16.h>
#include <math.h>
#include <stdint.h>

#define NNODES 100000
#define NEDGES 320000
#define NGRAPH 2048
#define HID    256
#define EDIM   128
#define NODE_F 48
#define EDGE_F 6
#define NLAYER 8

// ---------------- scratch (device globals) ----------------------------------
__device__ float   g_h0 [(size_t)NNODES * HID];
__device__ float   g_h1 [(size_t)NNODES * HID];
__device__ float   g_tmp[(size_t)NNODES * HID];       // fp32 (attention s1)
__device__ float   g_z  [(size_t)NNODES * HID];
__device__ __half  g_aeffh[(size_t)NNODES * HID];
__device__ __half  g_tmph [(size_t)NNODES * HID];
__device__ __half2 g_w1p[(size_t)NLAYER * (HID / 2) * HID];
__device__ __half2 g_w2p[(size_t)NLAYER * (HID / 2) * HID];
__device__ float   g_stats[2 * HID];
__device__ float   g_gsum[(size_t)NGRAPH * HID];
__device__ float   g_gsq [(size_t)NGRAPH * HID];
__device__ float   g_sc  [NGRAPH];
__device__ float   g_cnt [NGRAPH];
__device__ float   g_wexp[NNODES];
__device__ float   g_wsum[NGRAPH];
__device__ float   g_wf  [(size_t)NLAYER * 7 * HID];
__device__ int     g_deg [NNODES];
__device__ int     g_rowstart[NNODES + 1];
__device__ int     g_cursor[NNODES];
__device__ int     g_csr_eid[NEDGES];
__device__ int     g_csr_src[NEDGES];
__device__ int     g_gstart[NGRAPH + 1];

// ---------------- common helpers ---------------------------------------------
__device__ __forceinline__ uint32_t f2tf32(float x) {
    uint32_t r;
    asm volatile("cvt.rna.tf32.f32 %0, %1;" : "=r"(r) : "f"(x));
    return r;
}
__device__ __forceinline__ void cp16s(uint32_t d, const void* src, bool pred) {
    int sz = pred ? 16 : 0;
    asm volatile("cp.async.cg.shared.global [%0], [%1], 16, %2;" :: "r"(d), "l"(src), "r"(sz));
}
__device__ __forceinline__ void cp_commit() { asm volatile("cp.async.commit_group;"); }
template <int Np>
__device__ __forceinline__ void cp_wait() { asm volatile("cp.async.wait_group %0;" :: "n"(Np)); }

extern __shared__ char smemc[];

// ===================== fp16 tensor-core GEMM (K=256, N=256) ===================
// C = act(A @ B + bias).  A [M,256] half row-major.
// Bp [128][256] half2 (k-pair packed: Bp[p][n] = {B[2p][n], B[2p+1][n]}).
// MODE 0: float C, no act.  MODE 1: half C, relu.
#define HA_STRIDE 40              // halves per A smem row (32 + 8 pad)
#define HA_TILE   (128 * HA_STRIDE)
#define HB_STRIDE 132             // half2 per B smem row (128 + 4 pad)
#define HB_TILE   (16 * HB_STRIDE)
#define HG_SMEM_BYTES (2 * HA_TILE * 2 + 2 * HB_TILE * 4)   // 37376

__device__ __forceinline__ void mma_f16(float* c, const uint32_t* a, const uint32_t* b) {
    asm volatile(
        "mma.sync.aligned.m16n8k16.row.col.f32.f16.f16.f32 "
        "{%0,%1,%2,%3}, {%4,%5,%6,%7}, {%8,%9}, {%0,%1,%2,%3};"
        : "+f"(c[0]), "+f"(c[1]), "+f"(c[2]), "+f"(c[3])
        : "r"(a[0]), "r"(a[1]), "r"(a[2]), "r"(a[3]), "r"(b[0]), "r"(b[1]));
}

__device__ __forceinline__ void hg_fillA(uint32_t sb, int buf, const __half* A,
                                         int m0, int k0, int M, int tid)
{
#pragma unroll
    for (int it = 0; it < 2; it++) {
        int f4 = tid + it * 256;
        int r = f4 >> 2;
        int c = (f4 & 3) * 8;       // half index within 32
        int gm = m0 + r;
        bool p = gm < M;
        cp16s(sb + (buf * HA_TILE + r * HA_STRIDE + c) * 2,
              A + (size_t)(p ? gm : 0) * 256 + k0 + c, p);
    }
}
__device__ __forceinline__ void hg_fillB(uint32_t sb, int buf, const __half2* Bp,
                                         int n0, int k0, int tid)
{
    uint32_t bbase = sb + 2 * HA_TILE * 2;
#pragma unroll
    for (int it = 0; it < 2; it++) {
        int f4 = tid + it * 256;
        int pr = f4 >> 5;           // pair row 0..15
        int c2 = (f4 & 31) * 4;     // half2 index within 128
        cp16s(bbase + (buf * HB_TILE + pr * HB_STRIDE + c2) * 4,
              Bp + (size_t)((k0 >> 1) + pr) * 256 + n0 + c2, true);
    }
}

template <int MODE>
__global__ __launch_bounds__(256, 2) void hgemm(
    int M, const __half* __restrict__ A, const __half2* __restrict__ Bp,
    const float* __restrict__ bias, float* __restrict__ Cf, __half* __restrict__ Ch)
{
    const __half* hA = (const __half*)smemc;
    const __half2* hB = (const __half2*)(smemc + 2 * HA_TILE * 2);
    uint32_t sb = (uint32_t)__cvta_generic_to_shared(smemc);

    const int tid = threadIdx.x;
    const int warp = tid >> 5;
    const int lane = tid & 31;
    const int g = lane >> 2;
    const int tq = lane & 3;
    const int m0 = blockIdx.y * 128;
    const int n0 = blockIdx.x * 128;
    const int wm = (warp >> 1) * 32;
    const int wn = (warp & 1) * 64;

    float acc[2][8][4];
#pragma unroll
    for (int i = 0; i < 2; i++)
#pragma unroll
        for (int j = 0; j < 8; j++)
#pragma unroll
            for (int r = 0; r < 4; r++) acc[i][j][r] = 0.0f;

    hg_fillA(sb, 0, A, m0, 0, M, tid);
    hg_fillB(sb, 0, Bp, n0, 0, tid);
    cp_commit();

    int buf = 0;
#pragma unroll 1
    for (int i = 0; i < 8; i++) {
        if (i + 1 < 8) {
            hg_fillA(sb, buf ^ 1, A, m0, (i + 1) * 32, M, tid);
            hg_fillB(sb, buf ^ 1, Bp, n0, (i + 1) * 32, tid);
            cp_commit();
            cp_wait<1>();
        } else {
            cp_wait<0>();
        }
        __syncthreads();

        const __half* Ab = hA + buf * HA_TILE;
        const __half2* Bb = hB + buf * HB_TILE;
#pragma unroll
        for (int kk = 0; kk < 2; kk++) {
            uint32_t af[2][4];
#pragma unroll
            for (int mi = 0; mi < 2; mi++) {
                const __half* p = Ab + (wm + mi * 16 + g) * HA_STRIDE + kk * 16 + 2 * tq;
                af[mi][0] = *(const uint32_t*)(p);
                af[mi][1] = *(const uint32_t*)(p + 8 * HA_STRIDE);
                af[mi][2] = *(const uint32_t*)(p + 8);
                af[mi][3] = *(const uint32_t*)(p + 8 * HA_STRIDE + 8);
            }
            uint32_t bf[8][2];
#pragma unroll
            for (int ni = 0; ni < 8; ni++) {
                const __half2* p = Bb + (kk * 8 + tq) * HB_STRIDE + wn + ni * 8 + g;
                bf[ni][0] = *(const uint32_t*)(p);
                bf[ni][1] = *(const uint32_t*)(p + 4 * HB_STRIDE);
            }
#pragma unroll
            for (int mi = 0; mi < 2; mi++)
#pragma unroll
                for (int ni = 0; ni < 8; ni++)
                    mma_f16(acc[mi][ni], af[mi], bf[ni]);
        }
        __syncthreads();
        buf ^= 1;
    }

#pragma unroll
    for (int mi = 0; mi < 2; mi++) {
        int r0 = m0 + wm + mi * 16 + g;
        int r1 = r0 + 8;
#pragma unroll
        for (int ni = 0; ni < 8; ni++) {
            int col = n0 + wn + ni * 8 + tq * 2;
            float b0 = __ldg(bias + col);
            float b1 = __ldg(bias + col + 1);
            float v0 = acc[mi][ni][0] + b0;
            float v1 = acc[mi][ni][1] + b1;
            float v2 = acc[mi][ni][2] + b0;
            float v3 = acc[mi][ni][3] + b1;
            if (MODE == 1) {
                v0 = fmaxf(v0, 0.f); v1 = fmaxf(v1, 0.f);
                v2 = fmaxf(v2, 0.f); v3 = fmaxf(v3, 0.f);
                if (r0 < M) *(__half2*)(Ch + (size_t)r0 * 256 + col) = __floats2half2_rn(v0, v1);
                if (r1 < M) *(__half2*)(Ch + (size_t)r1 * 256 + col) = __floats2half2_rn(v2, v3);
            } else {
                if (r0 < M) *(float2*)(Cf + (size_t)r0 * 256 + col) = make_float2(v0, v1);
                if (r1 < M) *(float2*)(Cf + (size_t)r1 * 256 + col) = make_float2(v2, v3);
            }
        }
    }
}

// ---------------- weight pack: [L][K][N] fp32 -> [L][K/2][N] half2 ------------
__global__ void wpack_kernel(const float* __restrict__ w1, const float* __restrict__ w2,
                             __half2* __restrict__ w1p, __half2* __restrict__ w2p)
{
    int idx = blockIdx.x * 256 + threadIdx.x;   // [0, L*128*256)
    int l = idx >> 15;
    int rem = idx & 32767;
    int p = rem >> 8;
    int n = rem & 255;
    size_t base = (size_t)l * 65536 + (size_t)(2 * p) * 256 + n;
    w1p[idx] = __floats2half2_rn(__ldg(w1 + base), __ldg(w1 + base + 256));
    w2p[idx] = __floats2half2_rn(__ldg(w2 + base), __ldg(w2 + base + 256));
}

// ===================== mma.sync TF32 GEMM (node embed + attention) ============
#define GA_STRIDE 36
#define GB_STRIDE 132
#define A_TILE_W (128 * GA_STRIDE)
#define B_TILE_W (32 * GB_STRIDE)
#define GEMM_SMEM_BYTES ((2 * A_TILE_W + 2 * B_TILE_W) * 4)

__device__ __forceinline__ void cp16(float* dst, const float* src, bool pred) {
    cp16s((uint32_t)__cvta_generic_to_shared(dst), src, pred);
}
__device__ __forceinline__ void mma_tf32(float* c, const uint32_t* a, const uint32_t* b) {
    asm volatile(
        "mma.sync.aligned.m16n8k8.row.col.f32.tf32.tf32.f32 "
        "{%0,%1,%2,%3}, {%4,%5,%6,%7}, {%8,%9}, {%0,%1,%2,%3};"
        : "+f"(c[0]), "+f"(c[1]), "+f"(c[2]), "+f"(c[3])
        : "r"(a[0]), "r"(a[1]), "r"(a[2]), "r"(a[3]), "r"(b[0]), "r"(b[1]));
}

template <int ACT>
__global__ __launch_bounds__(256, 2) void tf32_gemm(
    int M, int N, int K,
    const float* __restrict__ A, const float* __restrict__ B,
    const float* __restrict__ bias, float* __restrict__ C)
{
    float* sm = (float*)smemc;
    float* As = sm;
    float* Bs = sm + 2 * A_TILE_W;

    const int tid = threadIdx.x;
    const int warp = tid >> 5;
    const int lane = tid & 31;
    const int g = lane >> 2;
    const int tq = lane & 3;
    const int m0 = blockIdx.y * 128;
    const int n0 = blockIdx.x * 128;
    const int wm = (warp >> 1) * 32;
    const int wn = (warp & 1) * 64;

    float acc[2][8][4];
#pragma unroll
    for (int i = 0; i < 2; i++)
#pragma unroll
        for (int j = 0; j < 8; j++)
#pragma unroll
            for (int r = 0; r < 4; r++) acc[i][j][r] = 0.0f;

    const int arow = tid >> 3;
    const int ac4 = tid & 7;
    const int brow = tid >> 5;
    const int bc4 = tid & 31;
    const int nk = (K + 31) / 32;

    {
#pragma unroll
        for (int it = 0; it < 4; it++) {
            int row = arow + it * 32;
            int gm = m0 + row;
            int gk = ac4 * 4;
            bool p = (gm < M) && (gk < K);
            const float* src = A + (size_t)(p ? gm : 0) * K + (p ? gk : 0);
            cp16(As + row * GA_STRIDE + ac4 * 4, src, p);
        }
#pragma unroll
        for (int it = 0; it < 4; it++) {
            int row = brow + it * 8;
            bool p = (row < K);
            const float* src = B + (size_t)(p ? row : 0) * N + n0 + bc4 * 4;
            cp16(Bs + row * GB_STRIDE + bc4 * 4, src, p);
        }
        cp_commit();
    }

    int buf = 0;
    for (int i = 0; i < nk; i++) {
        if (i + 1 < nk) {
            const int kc = i + 1;
            float* Ad = As + (buf ^ 1) * A_TILE_W;
            float* Bd = Bs + (buf ^ 1) * B_TILE_W;
#pragma unroll
            for (int it = 0; it < 4; it++) {
                int row = arow + it * 32;
                int gm = m0 + row;
                int gk = kc * 32 + ac4 * 4;
                bool p = (gm < M) && (gk < K);
                const float* src = A + (size_t)(p ? gm : 0) * K + (p ? gk : 0);
                cp16(Ad + row * GA_STRIDE + ac4 * 4, src, p);
            }
#pragma unroll
            for (int it = 0; it < 4; it++) {
                int row = brow + it * 8;
                int gk = kc * 32 + row;
                bool p = (gk < K);
                const float* src = B + (size_t)(p ? gk : 0) * N + n0 + bc4 * 4;
                cp16(Bd + row * GB_STRIDE + bc4 * 4, src, p);
            }
            cp_commit();
            cp_wait<1>();
        } else {
            cp_wait<0>();
        }
        __syncthreads();

        const float* Ab = As + buf * A_TILE_W;
        const float* Bb = Bs + buf * B_TILE_W;
#pragma unroll
        for (int kk = 0; kk < 4; kk++) {
            const int k = kk * 8;
            uint32_t af[2][4];
#pragma unroll
            for (int mi = 0; mi < 2; mi++) {
                const float* p = Ab + (wm + mi * 16 + g) * GA_STRIDE + k + tq;
                af[mi][0] = f2tf32(p[0]);
                af[mi][1] = f2tf32(p[8 * GA_STRIDE]);
                af[mi][2] = f2tf32(p[4]);
                af[mi][3] = f2tf32(p[8 * GA_STRIDE + 4]);
            }
            uint32_t bf[8][2];
#pragma unroll
            for (int ni = 0; ni < 8; ni++) {
                const float* p = Bb + (k + tq) * GB_STRIDE + wn + ni * 8 + g;
                bf[ni][0] = f2tf32(p[0]);
                bf[ni][1] = f2tf32(p[4 * GB_STRIDE]);
            }
#pragma unroll
            for (int mi = 0; mi < 2; mi++)
#pragma unroll
                for (int ni = 0; ni < 8; ni++)
                    mma_tf32(acc[mi][ni], af[mi], bf[ni]);
        }
        __syncthreads();
        buf ^= 1;
    }

#pragma unroll
    for (int mi = 0; mi < 2; mi++) {
        int r0 = m0 + wm + mi * 16 + g;
        int r1 = r0 + 8;
#pragma unroll
        for (int ni = 0; ni < 8; ni++) {
            int col = n0 + wn + ni * 8 + tq * 2;
            float b0 = __ldg(bias + col);
            float b1 = __ldg(bias + col + 1);
            float v0 = acc[mi][ni][0] + b0;
            float v1 = acc[mi][ni][1] + b1;
            float v2 = acc[mi][ni][2] + b0;
            float v3 = acc[mi][ni][3] + b1;
            if (ACT == 2) {
                v0 = tanhf(v0); v1 = tanhf(v1);
                v2 = tanhf(v2); v3 = tanhf(v3);
            }
            if (r0 < M) *(float2*)(C + (size_t)r0 * N + col) = make_float2(v0, v1);
            if (r1 < M) *(float2*)(C + (size_t)r1 * N + col) = make_float2(v2, v3);
        }
    }
}

// ---------------- fused edge weights ------------------------------------------
__global__ void wfuse_kernel(const float* __restrict__ edge_w,
                             const float* __restrict__ edge_b,
                             const float* __restrict__ conv_w,
                             const float* __restrict__ conv_b,
                             float* __restrict__ wf)
{
    int layer = blockIdx.x;
    int k = blockIdx.y;
    int c = threadIdx.x;
    const float* cw = conv_w + (size_t)layer * EDIM * HID;
    float s = 0.f;
    if (k < EDGE_F) {
        for (int j = 0; j < EDIM; j++)
            s = fmaf(__ldg(edge_w + k * EDIM + j), __ldg(cw + (size_t)j * HID + c), s);
    } else {
        for (int j = 0; j < EDIM; j++)
            s = fmaf(__ldg(edge_b + j), __ldg(cw + (size_t)j * HID + c), s);
        s += __ldg(conv_b + (size_t)layer * HID + c);
    }
    wf[((size_t)layer * 7 + k) * HID + c] = s;
}

// ---------------- CSR build ----------------------------------------------------
__global__ void deg_kernel(const int* __restrict__ dst, int* __restrict__ deg)
{
    int e = blockIdx.x * blockDim.x + threadIdx.x;
    if (e < NEDGES) atomicAdd(&deg[__ldg(dst + e)], 1);
}

__global__ void csr_scan_kernel(const int* __restrict__ deg,
                                int* __restrict__ rowstart,
                                int* __restrict__ cursor)
{
    const int CH = (NNODES + 1023) / 1024;
    __shared__ int ssum[1024];
    int t = threadIdx.x;
    int lo = t * CH;
    int hi = min(lo + CH, NNODES);
    int s = 0;
    for (int i = lo; i < hi; i++) s += deg[i];
    ssum[t] = s;
    __syncthreads();
    for (int off = 1; off < 1024; off <<= 1) {
        int v = (t >= off) ? ssum[t - off] : 0;
        __syncthreads();
        ssum[t] += v;
        __syncthreads();
    }
    int run = ssum[t] - s;
    for (int i = lo; i < hi; i++) {
        rowstart[i] = run;
        cursor[i] = run;
        run += deg[i];
    }
    if (hi == NNODES) rowstart[NNODES] = run;
}

__global__ void csr_fill_kernel(const int* __restrict__ src,
                                const int* __restrict__ dst,
                                int* __restrict__ cursor,
                                int* __restrict__ csr_eid,
                                int* __restrict__ csr_src)
{
    int e = blockIdx.x * blockDim.x + threadIdx.x;
    if (e >= NEDGES) return;
    int d = __ldg(dst + e);
    int p = atomicAdd(&cursor[d], 1);
    csr_eid[p] = e;
    csr_src[p] = __ldg(src + e);
}

// ---------------- graph ranges --------------------------------------------------
__global__ void gstart_min_kernel(const int* __restrict__ batch, int* __restrict__ gstart)
{
    int n = blockIdx.x * blockDim.x + threadIdx.x;
    if (n < NNODES) atomicMin(&gstart[__ldg(batch + n)], n);
}

__global__ void gstart_fix_kernel(int* __restrict__ gstart, float* __restrict__ cnt)
{
    __shared__ int sg[NGRAPH + 1];
    int t = threadIdx.x;
    for (int i = t; i <= NGRAPH; i += 1024) sg[i] = gstart[i];
    __syncthreads();
    if (t == 0) {
        sg[NGRAPH] = NNODES;
        for (int g2 = NGRAPH - 1; g2 >= 0; g2--)
            if (sg[g2] > sg[g2 + 1]) sg[g2] = sg[g2 + 1];
    }
    __syncthreads();
    for (int i = t; i <= NGRAPH; i += 1024) gstart[i] = sg[i];
    for (int i = t; i < NGRAPH; i += 1024)
        cnt[i] = fmaxf((float)(sg[i + 1] - sg[i]), 1.0f);
}

// ---------------- GINE gather (on-the-fly edge emb; half output) --------------
__global__ __launch_bounds__(256) void gine_gather_fused(
    const float* __restrict__ h,
    const float* __restrict__ ea,
    const int* __restrict__ rowstart,
    const int* __restrict__ csr_eid,
    const int* __restrict__ csr_src,
    const float* __restrict__ wf,
    const float* __restrict__ eps_ptr,
    __half* __restrict__ aeffh)
{
    const int lane = threadIdx.x & 31;
    const int warp_g = (blockIdx.x * blockDim.x + threadIdx.x) >> 5;
    const int nwarps = (gridDim.x * blockDim.x) >> 5;
    const float alpha = 1.0f + __ldg(eps_ptr);

    float4 w0[EDGE_F], w1[EDGE_F];
#pragma unroll
    for (int k = 0; k < EDGE_F; k++) {
        w0[k] = __ldg((const float4*)(wf + k * HID) + lane);
        w1[k] = __ldg((const float4*)(wf + k * HID) + 32 + lane);
    }
    float4 bf0 = __ldg((const float4*)(wf + EDGE_F * HID) + lane);
    float4 bf1 = __ldg((const float4*)(wf + EDGE_F * HID) + 32 + lane);

    for (int n = warp_g; n < NNODES; n += nwarps) {
        const float4* hn = (const float4*)(h + (size_t)n * HID);
        float4 a0 = __ldg(hn + lane);
        float4 a1 = __ldg(hn + 32 + lane);
        a0.x *= alpha; a0.y *= alpha; a0.z *= alpha; a0.w *= alpha;
        a1.x *= alpha; a1.y *= alpha; a1.z *= alpha; a1.w *= alpha;

        int lo = __ldg(rowstart + n), hi = __ldg(rowstart + n + 1);
        for (int j = lo; j < hi; j++) {
            int eid = __ldg(csr_eid + j);
            int s = __ldg(csr_src + j);
            const float* er = ea + (size_t)eid * EDGE_F;
            float e0 = __ldg(er + 0), e1 = __ldg(er + 1), e2 = __ldg(er + 2);
            float e3 = __ldg(er + 3), e4 = __ldg(er + 4), e5 = __ldg(er + 5);

            float4 ee0 = bf0, ee1 = bf1;
            ee0.x = fmaf(e0, w0[0].x, ee0.x); ee0.y = fmaf(e0, w0[0].y, ee0.y);
            ee0.z = fmaf(e0, w0[0].z, ee0.z); ee0.w = fmaf(e0, w0[0].w, ee0.w);
            ee1.x = fmaf(e0, w1[0].x, ee1.x); ee1.y = fmaf(e0, w1[0].y, ee1.y);
            ee1.z = fmaf(e0, w1[0].z, ee1.z); ee1.w = fmaf(e0, w1[0].w, ee1.w);
            ee0.x = fmaf(e1, w0[1].x, ee0.x); ee0.y = fmaf(e1, w0[1].y, ee0.y);
            ee0.z = fmaf(e1, w0[1].z, ee0.z); ee0.w = fmaf(e1, w0[1].w, ee0.w);
            ee1.x = fmaf(e1, w1[1].x, ee1.x); ee1.y = fmaf(e1, w1[1].y, ee1.y);
            ee1.z = fmaf(e1, w1[1].z, ee1.z); ee1.w = fmaf(e1, w1[1].w, ee1.w);
            ee0.x = fmaf(e2, w0[2].x, ee0.x); ee0.y = fmaf(e2, w0[2].y, ee0.y);
            ee0.z = fmaf(e2, w0[2].z, ee0.z); ee0.w = fmaf(e2, w0[2].w, ee0.w);
            ee1.x = fmaf(e2, w1[2].x, ee1.x); ee1.y = fmaf(e2, w1[2].y, ee1.y);
            ee1.z = fmaf(e2, w1[2].z, ee1.z); ee1.w = fmaf(e2, w1[2].w, ee1.w);
            ee0.x = fmaf(e3, w0[3].x, ee0.x); ee0.y = fmaf(e3, w0[3].y, ee0.y);
            ee0.z = fmaf(e3, w0[3].z, ee0.z); ee0.w = fmaf(e3, w0[3].w, ee0.w);
            ee1.x = fmaf(e3, w1[3].x, ee1.x); ee1.y = fmaf(e3, w1[3].y, ee1.y);
            ee1.z = fmaf(e3, w1[3].z, ee1.z); ee1.w = fmaf(e3, w1[3].w, ee1.w);
            ee0.x = fmaf(e4, w0[4].x, ee0.x); ee0.y = fmaf(e4, w0[4].y, ee0.y);
            ee0.z = fmaf(e4, w0[4].z, ee0.z); ee0.w = fmaf(e4, w0[4].w, ee0.w);
            ee1.x = fmaf(e4, w1[4].x, ee1.x); ee1.y = fmaf(e4, w1[4].y, ee1.y);
            ee1.z = fmaf(e4, w1[4].z, ee1.z); ee1.w = fmaf(e4, w1[4].w, ee1.w);
            ee0.x = fmaf(e5, w0[5].x, ee0.x); ee0.y = fmaf(e5, w0[5].y, ee0.y);
            ee0.z = fmaf(e5, w0[5].z, ee0.z); ee0.w = fmaf(e5, w0[5].w, ee0.w);
            ee1.x = fmaf(e5, w1[5].x, ee1.x); ee1.y = fmaf(e5, w1[5].y, ee1.y);
            ee1.z = fmaf(e5, w1[5].z, ee1.z); ee1.w = fmaf(e5, w1[5].w, ee1.w);

            const float4* hp = (const float4*)(h + (size_t)s * HID);
            float4 h0 = __ldg(hp + lane);
            float4 h1 = __ldg(hp + 32 + lane);
            a0.x += fmaxf(h0.x + ee0.x, 0.f); a0.y += fmaxf(h0.y + ee0.y, 0.f);
            a0.z += fmaxf(h0.z + ee0.z, 0.f); a0.w += fmaxf(h0.w + ee0.w, 0.f);
            a1.x += fmaxf(h1.x + ee1.x, 0.f); a1.y += fmaxf(h1.y + ee1.y, 0.f);
            a1.z += fmaxf(h1.z + ee1.z, 0.f); a1.w += fmaxf(h1.w + ee1.w, 0.f);
        }
        __half2* ap = (__half2*)(aeffh + (size_t)n * HID);
        ap[lane * 2]          = __floats2half2_rn(a0.x, a0.y);
        ap[lane * 2 + 1]      = __floats2half2_rn(a0.z, a0.w);
        ap[64 + lane * 2]     = __floats2half2_rn(a1.x, a1.y);
        ap[64 + lane * 2 + 1] = __floats2half2_rn(a1.z, a1.w);
    }
}

// ---------------- per-graph stats + global BN stats (atomic) -------------------
__global__ void graph_stats_kernel(const float* __restrict__ z,
                                   const int* __restrict__ gstart,
                                   float* __restrict__ gsum,
                                   float* __restrict__ gsq,
                                   float* __restrict__ stats)
{
    int g = blockIdx.x;
    int c = threadIdx.x;
    int lo = gstart[g], hi = gstart[g + 1];
    float s = 0.f, q = 0.f;
    for (int n = lo; n < hi; n++) {
        float v = __ldg(z + (size_t)n * HID + c);
        s += v;
        q = fmaf(v, v, q);
    }
    gsum[(size_t)g * HID + c] = s;
    gsq[(size_t)g * HID + c] = q;
    atomicAdd(&stats[c], s);
    atomicAdd(&stats[HID + c], q);
}

// ---------------- per-graph msq -> scale; gsum -> mean (a inline) --------------
__global__ void graph_msq_kernel(const float* __restrict__ stats,
                                 const float* __restrict__ gamma,
                                 const float* __restrict__ cnt,
                                 float* __restrict__ gsum,
                                 const float* __restrict__ gsq,
                                 float* __restrict__ sc)
{
    __shared__ float red[HID];
    int g = blockIdx.x;
    int c = threadIdx.x;
    const float invN = 1.0f / (float)NNODES;
    float mu = __ldg(stats + c) * invN;
    float var = __ldg(stats + HID + c) * invN - mu * mu;
    float ac = __ldg(gamma + c) * rsqrtf(var + 1e-5f);
    float cg = cnt[g];
    size_t i = (size_t)g * HID + c;
    float S = gsum[i], Q = gsq[i];
    float m = S / cg;
    gsum[i] = m;
    red[c] = ac * ac * (Q - cg * m * m);
    __syncthreads();
    for (int o = HID / 2; o > 0; o >>= 1) {
        if (c < o) red[c] += red[c + o];
        __syncthreads();
    }
    if (c == 0) sc[g] = rsqrtf(1e-5f + red[0] / cg);
}

// ---------------- fused BN+PairNorm normalize + ReLU (a inline) ----------------
__global__ void final_norm_kernel(const float* __restrict__ z,
                                  const float* __restrict__ stats,
                                  const float* __restrict__ gamma,
                                  const float* __restrict__ gmean,
                                  const float* __restrict__ sc,
                                  const int* __restrict__ batch,
                                  float* __restrict__ hout)
{
    int r = blockIdx.x;
    int c = threadIdx.x;
    int g = __ldg(batch + r);
    const float invN = 1.0f / (float)NNODES;
    float mu = __ldg(stats + c) * invN;
    float var = __ldg(stats + HID + c) * invN - mu * mu;
    float ac = __ldg(gamma + c) * rsqrtf(var + 1e-5f);
    size_t i = (size_t)r * HID + c;
    float v = ac * (z[i] - __ldg(gmean + (size_t)g * HID + c)) * __ldg(sc + g);
    hout[i] = fmaxf(v, 0.f);
}

// ---------------- attention score ----------------------------------------------
__global__ void attn_score_kernel(const float* __restrict__ s1,
                                  const float* __restrict__ w2,
                                  const float* __restrict__ b2,
                                  const int* __restrict__ batch,
                                  float* __restrict__ wexp,
                                  float* __restrict__ wsum)
{
    int row = (blockIdx.x * blockDim.x + threadIdx.x) >> 5;
    int lane = threadIdx.x & 31;
    if (row >= NNODES) return;
    float acc = 0.f;
#pragma unroll
    for (int k = lane; k < EDIM; k += 32)
        acc = fmaf(__ldg(s1 + (size_t)row * EDIM + k), __ldg(w2 + k), acc);
#pragma unroll
    for (int o = 16; o > 0; o >>= 1) acc += __shfl_down_sync(0xffffffffu, acc, o);
    if (lane == 0) {
        float w = expf(acc + __ldg(b2));
        wexp[row] = w;
        atomicAdd(&wsum[__ldg(batch + row)], w);
    }
}

// ---------------- pooling --------------------------------------------------------
__global__ void pool_graph_kernel(const float* __restrict__ h,
                                  const float* __restrict__ wexp,
                                  const float* __restrict__ wsum,
                                  const int* __restrict__ gstart,
                                  const float* __restrict__ cnt,
                                  float* __restrict__ out)
{
    int g = blockIdx.x;
    int c = threadIdx.x;
    int lo = gstart[g], hi = gstart[g + 1];
    float inv_ws = 1.0f / (wsum[g] + 1e-8f);
    float s = 0.f, mx = 0.f, att = 0.f;
    for (int n = lo; n < hi; n++) {
        float v = __ldg(h + (size_t)n * HID + c);
        float coeff = __ldg(wexp + n) * inv_ws;
        s += v;
        mx = fmaxf(mx, v);
        att = fmaf(v, coeff, att);
    }
    float* og = out + (size_t)g * (3 * HID);
    og[c] = s / cnt[g];
    og[HID + c] = mx;
    og[2 * HID + c] = att;
}

// ---------------- host launch ------------------------------------------------------
static inline void launch_tf32(int act, int M, int N, int K,
                               const float* A, const float* B,
                               const float* bias, float* C)
{
    dim3 grid(N / 128, (M + 127) / 128);
    if (act == 0) tf32_gemm<0><<<grid, 256, GEMM_SMEM_BYTES>>>(M, N, K, A, B, bias, C);
    else          tf32_gemm<2><<<grid, 256, GEMM_SMEM_BYTES>>>(M, N, K, A, B, bias, C);
}

extern "C" void kernel_launch(void* const* d_in, const int* in_sizes, int n_in,
                              void* d_out, int out_size)
{
    const float* x         = (const float*)d_in[0];
    const float* edge_attr = (const float*)d_in[1];
    const float* node_w    = (const float*)d_in[2];
    const float* node_b    = (const float*)d_in[3];
    const float* edge_w    = (const float*)d_in[4];
    const float* edge_b    = (const float*)d_in[5];
    const float* conv_w    = (const float*)d_in[6];
    const float* conv_b    = (const float*)d_in[7];
    const float* mlp_w1    = (const float*)d_in[8];
    const float* mlp_b1    = (const float*)d_in[9];
    const float* mlp_w2    = (const float*)d_in[10];
    const float* mlp_b2    = (const float*)d_in[11];
    const float* eps       = (const float*)d_in[12];
    const float* bn_gamma  = (const float*)d_in[13];
    const float* bn_beta   = (const float*)d_in[14];
    const float* att_w1    = (const float*)d_in[15];
    const float* att_b1    = (const float*)d_in[16];
    const float* att_w2    = (const float*)d_in[17];
    const float* att_b2    = (const float*)d_in[18];
    const int*   edge_index= (const int*)d_in[19];
    const int*   batch     = (const int*)d_in[20];
    float* out = (float*)d_out;
    (void)bn_beta;   // cancels exactly under PairNorm centering

    const int* src = edge_index;
    const int* dst = edge_index + NEDGES;

    cudaFuncSetAttribute(tf32_gemm<0>, cudaFuncAttributeMaxDynamicSharedMemorySize, GEMM_SMEM_BYTES);
    cudaFuncSetAttribute(tf32_gemm<2>, cudaFuncAttributeMaxDynamicSharedMemorySize, GEMM_SMEM_BYTES);
    cudaFuncSetAttribute(hgemm<0>, cudaFuncAttributeMaxDynamicSharedMemorySize, HG_SMEM_BYTES);
    cudaFuncSetAttribute(hgemm<1>, cudaFuncAttributeMaxDynamicSharedMemorySize, HG_SMEM_BYTES);

    float *p_h0, *p_h1, *p_tmp, *p_z, *p_stats, *p_gsum, *p_gsq,
          *p_sc, *p_cnt, *p_wexp, *p_wsum, *p_wf;
    __half *p_aeffh, *p_tmph;
    __half2 *p_w1p, *p_w2p;
    int *p_deg, *p_rowstart, *p_cursor, *p_eid, *p_csrc, *p_gstart;
    cudaGetSymbolAddress((void**)&p_h0, g_h0);
    cudaGetSymbolAddress((void**)&p_h1, g_h1);
    cudaGetSymbolAddress((void**)&p_tmp, g_tmp);
    cudaGetSymbolAddress((void**)&p_z, g_z);
    cudaGetSymbolAddress((void**)&p_aeffh, g_aeffh);
    cudaGetSymbolAddress((void**)&p_tmph, g_tmph);
    cudaGetSymbolAddress((void**)&p_w1p, g_w1p);
    cudaGetSymbolAddress((void**)&p_w2p, g_w2p);
    cudaGetSymbolAddress((void**)&p_stats, g_stats);
    cudaGetSymbolAddress((void**)&p_gsum, g_gsum);
    cudaGetSymbolAddress((void**)&p_gsq, g_gsq);
    cudaGetSymbolAddress((void**)&p_sc, g_sc);
    cudaGetSymbolAddress((void**)&p_cnt, g_cnt);
    cudaGetSymbolAddress((void**)&p_wexp, g_wexp);
    cudaGetSymbolAddress((void**)&p_wsum, g_wsum);
    cudaGetSymbolAddress((void**)&p_wf, g_wf);
    cudaGetSymbolAddress((void**)&p_deg, g_deg);
    cudaGetSymbolAddress((void**)&p_rowstart, g_rowstart);
    cudaGetSymbolAddress((void**)&p_cursor, g_cursor);
    cudaGetSymbolAddress((void**)&p_eid, g_csr_eid);
    cudaGetSymbolAddress((void**)&p_csrc, g_csr_src);
    cudaGetSymbolAddress((void**)&p_gstart, g_gstart);

    // ----- CSR build
    cudaMemsetAsync(p_deg, 0, NNODES * sizeof(int));
    deg_kernel<<<(NEDGES + 255) / 256, 256>>>(dst, p_deg);
    csr_scan_kernel<<<1, 1024>>>(p_deg, p_rowstart, p_cursor);
    csr_fill_kernel<<<(NEDGES + 255) / 256, 256>>>(src, dst, p_cursor, p_eid, p_csrc);

    // ----- graph ranges + counts
    cudaMemsetAsync(p_gstart, 0x7F, (NGRAPH + 1) * sizeof(int));
    gstart_min_kernel<<<(NNODES + 255) / 256, 256>>>(batch, p_gstart);
    gstart_fix_kernel<<<1, 1024>>>(p_gstart, p_cnt);

    // ----- weight prep
    wfuse_kernel<<<dim3(NLAYER, 7), HID>>>(edge_w, edge_b, conv_w, conv_b, p_wf);
    wpack_kernel<<<(NLAYER * 128 * 256) / 256, 256>>>(mlp_w1, mlp_w2, p_w1p, p_w2p);

    // ----- node embedding (tf32 path)
    launch_tf32(0, NNODES, HID, NODE_F, x, node_w, node_b, p_h0);

    float* h_cur = p_h0;
    float* h_nxt = p_h1;
    dim3 hgrid(2, (NNODES + 127) / 128);

    for (int i = 0; i < NLAYER; i++) {
        gine_gather_fused<<<1024, 256>>>(
            h_cur, edge_attr, p_rowstart, p_eid, p_csrc,
            p_wf + (size_t)i * 7 * HID, eps + i, p_aeffh);

        // tmp = relu(aeff @ w1 + b1)  [fp16 tensor cores, half output]
        hgemm<1><<<hgrid, 256, HG_SMEM_BYTES>>>(
            NNODES, p_aeffh, p_w1p + (size_t)i * 32768,
            mlp_b1 + (size_t)i * HID, nullptr, p_tmph);
        // z = tmp @ w2 + b2  [fp16 tensor cores, float output]
        hgemm<0><<<hgrid, 256, HG_SMEM_BYTES>>>(
            NNODES, p_tmph, p_w2p + (size_t)i * 32768,
            mlp_b2 + (size_t)i * HID, p_z, nullptr);

        // fused BN + PairNorm (affine-collapsed)
        cudaMemsetAsync(p_stats, 0, 2 * HID * sizeof(float));
        graph_stats_kernel<<<NGRAPH, HID>>>(p_z, p_gstart, p_gsum, p_gsq, p_stats);
        graph_msq_kernel<<<NGRAPH, HID>>>(p_stats, bn_gamma + (size_t)i * HID,
                                          p_cnt, p_gsum, p_gsq, p_sc);
        final_norm_kernel<<<NNODES, HID>>>(p_z, p_stats, bn_gamma + (size_t)i * HID,
                                           p_gsum, p_sc, batch, h_nxt);

        float* t = h_cur; h_cur = h_nxt; h_nxt = t;
    }

    // attention hidden (tf32 path)
    launch_tf32(2, NNODES, EDIM, HID, h_cur, att_w1, att_b1, p_tmp);

    cudaMemsetAsync(p_wsum, 0, NGRAPH * sizeof(float));
    attn_score_kernel<<<(NNODES * 32 + 255) / 256, 256>>>(p_tmp, att_w2, att_b2, batch, p_wexp, p_wsum);

    pool_graph_kernel<<<NGRAPH, HID>>>(h_cur, p_wexp, p_wsum, p_gstart, p_cnt, out);

    (void)in_sizes; (void)n_in; (void)out_size;
}

// round 6
// speedup vs baseline: 4.7465x; 1.1716x over previous
#include <cuda_runtime.h>
#include <cuda_fp16.h>
#include <math.h>
#include <stdint.h>

#define NNODES 100000
#define NEDGES 320000
#define NGRAPH 2048
#define HID    256
#define EDIM   128
#define NODE_F 48
#define EDGE_F 6
#define NLAYER 8

// ---------------- scratch (device globals) ----------------------------------
__device__ __half  g_hh0[(size_t)NNODES * HID];      // h (half, ping)
__device__ __half  g_hh1[(size_t)NNODES * HID];      // h (half, pong)
__device__ __half  g_zh [(size_t)NNODES * HID];      // z (half)
__device__ __half  g_aeffh[(size_t)NNODES * HID];
__device__ __half  g_tmph [(size_t)NNODES * HID];
__device__ float   g_hfin[(size_t)NNODES * HID];     // final h fp32 (attn/pool)
__device__ float   g_tmp [(size_t)NNODES * HID];     // attention s1 fp32
__device__ __half2 g_w1p[(size_t)NLAYER * (HID / 2) * HID];
__device__ __half2 g_w2p[(size_t)NLAYER * (HID / 2) * HID];
__device__ float   g_stats[2 * HID];
__device__ float   g_gsum[(size_t)NGRAPH * HID];
__device__ float   g_gsq [(size_t)NGRAPH * HID];
__device__ float   g_sc  [NGRAPH];
__device__ float   g_cnt [NGRAPH];
__device__ float   g_wexp[NNODES];
__device__ float   g_wsum[NGRAPH];
__device__ float   g_wf  [(size_t)NLAYER * 7 * HID];
__device__ int     g_deg [NNODES];
__device__ int     g_rowstart[NNODES + 1];
__device__ int     g_cursor[NNODES];
__device__ int     g_csr_eid[NEDGES];
__device__ int     g_csr_src[NEDGES];
__device__ int     g_gstart[NGRAPH + 1];

// ---------------- common helpers ---------------------------------------------
__device__ __forceinline__ uint32_t f2tf32(float x) {
    uint32_t r;
    asm volatile("cvt.rna.tf32.f32 %0, %1;" : "=r"(r) : "f"(x));
    return r;
}
__device__ __forceinline__ void cp16s(uint32_t d, const void* src, bool pred) {
    int sz = pred ? 16 : 0;
    asm volatile("cp.async.cg.shared.global [%0], [%1], 16, %2;" :: "r"(d), "l"(src), "r"(sz));
}
__device__ __forceinline__ void cp_commit() { asm volatile("cp.async.commit_group;"); }
template <int Np>
__device__ __forceinline__ void cp_wait() { asm volatile("cp.async.wait_group %0;" :: "n"(Np)); }

extern __shared__ char smemc[];

// ===================== fp16 tensor-core GEMM (K=256, N=256) ===================
// MODE 1: half C, relu.  MODE 2: half C, no act.
#define HA_STRIDE 40
#define HA_TILE   (128 * HA_STRIDE)
#define HB_STRIDE 132
#define HB_TILE   (16 * HB_STRIDE)
#define HG_SMEM_BYTES (2 * HA_TILE * 2 + 2 * HB_TILE * 4)

__device__ __forceinline__ void mma_f16(float* c, const uint32_t* a, const uint32_t* b) {
    asm volatile(
        "mma.sync.aligned.m16n8k16.row.col.f32.f16.f16.f32 "
        "{%0,%1,%2,%3}, {%4,%5,%6,%7}, {%8,%9}, {%0,%1,%2,%3};"
        : "+f"(c[0]), "+f"(c[1]), "+f"(c[2]), "+f"(c[3])
        : "r"(a[0]), "r"(a[1]), "r"(a[2]), "r"(a[3]), "r"(b[0]), "r"(b[1]));
}

__device__ __forceinline__ void hg_fillA(uint32_t sb, int buf, const __half* A,
                                         int m0, int k0, int M, int tid)
{
#pragma unroll
    for (int it = 0; it < 2; it++) {
        int f4 = tid + it * 256;
        int r = f4 >> 2;
        int c = (f4 & 3) * 8;
        int gm = m0 + r;
        bool p = gm < M;
        cp16s(sb + (buf * HA_TILE + r * HA_STRIDE + c) * 2,
              A + (size_t)(p ? gm : 0) * 256 + k0 + c, p);
    }
}
__device__ __forceinline__ void hg_fillB(uint32_t sb, int buf, const __half2* Bp,
                                         int n0, int k0, int tid)
{
    uint32_t bbase = sb + 2 * HA_TILE * 2;
#pragma unroll
    for (int it = 0; it < 2; it++) {
        int f4 = tid + it * 256;
        int pr = f4 >> 5;
        int c2 = (f4 & 31) * 4;
        cp16s(bbase + (buf * HB_TILE + pr * HB_STRIDE + c2) * 4,
              Bp + (size_t)((k0 >> 1) + pr) * 256 + n0 + c2, true);
    }
}

template <int MODE>
__global__ __launch_bounds__(256, 2) void hgemm(
    int M, const __half* __restrict__ A, const __half2* __restrict__ Bp,
    const float* __restrict__ bias, __half* __restrict__ Ch)
{
    const __half* hA = (const __half*)smemc;
    const __half2* hB = (const __half2*)(smemc + 2 * HA_TILE * 2);
    uint32_t sb = (uint32_t)__cvta_generic_to_shared(smemc);

    const int tid = threadIdx.x;
    const int warp = tid >> 5;
    const int lane = tid & 31;
    const int g = lane >> 2;
    const int tq = lane & 3;
    const int m0 = blockIdx.y * 128;
    const int n0 = blockIdx.x * 128;
    const int wm = (warp >> 1) * 32;
    const int wn = (warp & 1) * 64;

    float acc[2][8][4];
#pragma unroll
    for (int i = 0; i < 2; i++)
#pragma unroll
        for (int j = 0; j < 8; j++)
#pragma unroll
            for (int r = 0; r < 4; r++) acc[i][j][r] = 0.0f;

    hg_fillA(sb, 0, A, m0, 0, M, tid);
    hg_fillB(sb, 0, Bp, n0, 0, tid);
    cp_commit();

    int buf = 0;
#pragma unroll 1
    for (int i = 0; i < 8; i++) {
        if (i + 1 < 8) {
            hg_fillA(sb, buf ^ 1, A, m0, (i + 1) * 32, M, tid);
            hg_fillB(sb, buf ^ 1, Bp, n0, (i + 1) * 32, tid);
            cp_commit();
            cp_wait<1>();
        } else {
            cp_wait<0>();
        }
        __syncthreads();

        const __half* Ab = hA + buf * HA_TILE;
        const __half2* Bb = hB + buf * HB_TILE;
#pragma unroll
        for (int kk = 0; kk < 2; kk++) {
            uint32_t af[2][4];
#pragma unroll
            for (int mi = 0; mi < 2; mi++) {
                const __half* p = Ab + (wm + mi * 16 + g) * HA_STRIDE + kk * 16 + 2 * tq;
                af[mi][0] = *(const uint32_t*)(p);
                af[mi][1] = *(const uint32_t*)(p + 8 * HA_STRIDE);
                af[mi][2] = *(const uint32_t*)(p + 8);
                af[mi][3] = *(const uint32_t*)(p + 8 * HA_STRIDE + 8);
            }
            uint32_t bf[8][2];
#pragma unroll
            for (int ni = 0; ni < 8; ni++) {
                const __half2* p = Bb + (kk * 8 + tq) * HB_STRIDE + wn + ni * 8 + g;
                bf[ni][0] = *(const uint32_t*)(p);
                bf[ni][1] = *(const uint32_t*)(p + 4 * HB_STRIDE);
            }
#pragma unroll
            for (int mi = 0; mi < 2; mi++)
#pragma unroll
                for (int ni = 0; ni < 8; ni++)
                    mma_f16(acc[mi][ni], af[mi], bf[ni]);
        }
        __syncthreads();
        buf ^= 1;
    }

#pragma unroll
    for (int mi = 0; mi < 2; mi++) {
        int r0 = m0 + wm + mi * 16 + g;
        int r1 = r0 + 8;
#pragma unroll
        for (int ni = 0; ni < 8; ni++) {
            int col = n0 + wn + ni * 8 + tq * 2;
            float b0 = __ldg(bias + col);
            float b1 = __ldg(bias + col + 1);
            float v0 = acc[mi][ni][0] + b0;
            float v1 = acc[mi][ni][1] + b1;
            float v2 = acc[mi][ni][2] + b0;
            float v3 = acc[mi][ni][3] + b1;
            if (MODE == 1) {
                v0 = fmaxf(v0, 0.f); v1 = fmaxf(v1, 0.f);
                v2 = fmaxf(v2, 0.f); v3 = fmaxf(v3, 0.f);
            }
            if (r0 < M) *(__half2*)(Ch + (size_t)r0 * 256 + col) = __floats2half2_rn(v0, v1);
            if (r1 < M) *(__half2*)(Ch + (size_t)r1 * 256 + col) = __floats2half2_rn(v2, v3);
        }
    }
}

// ---------------- weight pack ---------------------------------------------------
__global__ void wpack_kernel(const float* __restrict__ w1, const float* __restrict__ w2,
                             __half2* __restrict__ w1p, __half2* __restrict__ w2p)
{
    int idx = blockIdx.x * 256 + threadIdx.x;
    int l = idx >> 15;
    int rem = idx & 32767;
    int p = rem >> 8;
    int n = rem & 255;
    size_t base = (size_t)l * 65536 + (size_t)(2 * p) * 256 + n;
    w1p[idx] = __floats2half2_rn(__ldg(w1 + base), __ldg(w1 + base + 256));
    w2p[idx] = __floats2half2_rn(__ldg(w2 + base), __ldg(w2 + base + 256));
}

// ===================== mma.sync TF32 GEMM (node embed + attention) ============
// MODE 0: fp32 out, no act.  MODE 2: fp32 out, tanh.  MODE 3: half out, no act.
#define GA_STRIDE 36
#define GB_STRIDE 132
#define A_TILE_W (128 * GA_STRIDE)
#define B_TILE_W (32 * GB_STRIDE)
#define GEMM_SMEM_BYTES ((2 * A_TILE_W + 2 * B_TILE_W) * 4)

__device__ __forceinline__ void cp16(float* dst, const float* src, bool pred) {
    cp16s((uint32_t)__cvta_generic_to_shared(dst), src, pred);
}
__device__ __forceinline__ void mma_tf32(float* c, const uint32_t* a, const uint32_t* b) {
    asm volatile(
        "mma.sync.aligned.m16n8k8.row.col.f32.tf32.tf32.f32 "
        "{%0,%1,%2,%3}, {%4,%5,%6,%7}, {%8,%9}, {%0,%1,%2,%3};"
        : "+f"(c[0]), "+f"(c[1]), "+f"(c[2]), "+f"(c[3])
        : "r"(a[0]), "r"(a[1]), "r"(a[2]), "r"(a[3]), "r"(b[0]), "r"(b[1]));
}

template <int ACT>
__global__ __launch_bounds__(256, 2) void tf32_gemm(
    int M, int N, int K,
    const float* __restrict__ A, const float* __restrict__ B,
    const float* __restrict__ bias, float* __restrict__ C, __half* __restrict__ Chh)
{
    float* sm = (float*)smemc;
    float* As = sm;
    float* Bs = sm + 2 * A_TILE_W;

    const int tid = threadIdx.x;
    const int warp = tid >> 5;
    const int lane = tid & 31;
    const int g = lane >> 2;
    const int tq = lane & 3;
    const int m0 = blockIdx.y * 128;
    const int n0 = blockIdx.x * 128;
    const int wm = (warp >> 1) * 32;
    const int wn = (warp & 1) * 64;

    float acc[2][8][4];
#pragma unroll
    for (int i = 0; i < 2; i++)
#pragma unroll
        for (int j = 0; j < 8; j++)
#pragma unroll
            for (int r = 0; r < 4; r++) acc[i][j][r] = 0.0f;

    const int arow = tid >> 3;
    const int ac4 = tid & 7;
    const int brow = tid >> 5;
    const int bc4 = tid & 31;
    const int nk = (K + 31) / 32;

    {
#pragma unroll
        for (int it = 0; it < 4; it++) {
            int row = arow + it * 32;
            int gm = m0 + row;
            int gk = ac4 * 4;
            bool p = (gm < M) && (gk < K);
            const float* src = A + (size_t)(p ? gm : 0) * K + (p ? gk : 0);
            cp16(As + row * GA_STRIDE + ac4 * 4, src, p);
        }
#pragma unroll
        for (int it = 0; it < 4; it++) {
            int row = brow + it * 8;
            bool p = (row < K);
            const float* src = B + (size_t)(p ? row : 0) * N + n0 + bc4 * 4;
            cp16(Bs + row * GB_STRIDE + bc4 * 4, src, p);
        }
        cp_commit();
    }

    int buf = 0;
    for (int i = 0; i < nk; i++) {
        if (i + 1 < nk) {
            const int kc = i + 1;
            float* Ad = As + (buf ^ 1) * A_TILE_W;
            float* Bd = Bs + (buf ^ 1) * B_TILE_W;
#pragma unroll
            for (int it = 0; it < 4; it++) {
                int row = arow + it * 32;
                int gm = m0 + row;
                int gk = kc * 32 + ac4 * 4;
                bool p = (gm < M) && (gk < K);
                const float* src = A + (size_t)(p ? gm : 0) * K + (p ? gk : 0);
                cp16(Ad + row * GA_STRIDE + ac4 * 4, src, p);
            }
#pragma unroll
            for (int it = 0; it < 4; it++) {
                int row = brow + it * 8;
                int gk = kc * 32 + row;
                bool p = (gk < K);
                const float* src = B + (size_t)(p ? gk : 0) * N + n0 + bc4 * 4;
                cp16(Bd + row * GB_STRIDE + bc4 * 4, src, p);
            }
            cp_commit();
            cp_wait<1>();
        } else {
            cp_wait<0>();
        }
        __syncthreads();

        const float* Ab = As + buf * A_TILE_W;
        const float* Bb = Bs + buf * B_TILE_W;
#pragma unroll
        for (int kk = 0; kk < 4; kk++) {
            const int k = kk * 8;
            uint32_t af[2][4];
#pragma unroll
            for (int mi = 0; mi < 2; mi++) {
                const float* p = Ab + (wm + mi * 16 + g) * GA_STRIDE + k + tq;
                af[mi][0] = f2tf32(p[0]);
                af[mi][1] = f2tf32(p[8 * GA_STRIDE]);
                af[mi][2] = f2tf32(p[4]);
                af[mi][3] = f2tf32(p[8 * GA_STRIDE + 4]);
            }
            uint32_t bf[8][2];
#pragma unroll
            for (int ni = 0; ni < 8; ni++) {
                const float* p = Bb + (k + tq) * GB_STRIDE + wn + ni * 8 + g;
                bf[ni][0] = f2tf32(p[0]);
                bf[ni][1] = f2tf32(p[4 * GB_STRIDE]);
            }
#pragma unroll
            for (int mi = 0; mi < 2; mi++)
#pragma unroll
                for (int ni = 0; ni < 8; ni++)
                    mma_tf32(acc[mi][ni], af[mi], bf[ni]);
        }
        __syncthreads();
        buf ^= 1;
    }

#pragma unroll
    for (int mi = 0; mi < 2; mi++) {
        int r0 = m0 + wm + mi * 16 + g;
        int r1 = r0 + 8;
#pragma unroll
        for (int ni = 0; ni < 8; ni++) {
            int col = n0 + wn + ni * 8 + tq * 2;
            float b0 = __ldg(bias + col);
            float b1 = __ldg(bias + col + 1);
            float v0 = acc[mi][ni][0] + b0;
            float v1 = acc[mi][ni][1] + b1;
            float v2 = acc[mi][ni][2] + b0;
            float v3 = acc[mi][ni][3] + b1;
            if (ACT == 2) {
                v0 = tanhf(v0); v1 = tanhf(v1);
                v2 = tanhf(v2); v3 = tanhf(v3);
            }
            if (ACT == 3) {
                if (r0 < M) *(__half2*)(Chh + (size_t)r0 * N + col) = __floats2half2_rn(v0, v1);
                if (r1 < M) *(__half2*)(Chh + (size_t)r1 * N + col) = __floats2half2_rn(v2, v3);
            } else {
                if (r0 < M) *(float2*)(C + (size_t)r0 * N + col) = make_float2(v0, v1);
                if (r1 < M) *(float2*)(C + (size_t)r1 * N + col) = make_float2(v2, v3);
            }
        }
    }
}

// ---------------- fused edge weights ------------------------------------------
__global__ void wfuse_kernel(const float* __restrict__ edge_w,
                             const float* __restrict__ edge_b,
                             const float* __restrict__ conv_w,
                             const float* __restrict__ conv_b,
                             float* __restrict__ wf)
{
    int layer = blockIdx.x;
    int k = blockIdx.y;
    int c = threadIdx.x;
    const float* cw = conv_w + (size_t)layer * EDIM * HID;
    float s = 0.f;
    if (k < EDGE_F) {
        for (int j = 0; j < EDIM; j++)
            s = fmaf(__ldg(edge_w + k * EDIM + j), __ldg(cw + (size_t)j * HID + c), s);
    } else {
        for (int j = 0; j < EDIM; j++)
            s = fmaf(__ldg(edge_b + j), __ldg(cw + (size_t)j * HID + c), s);
        s += __ldg(conv_b + (size_t)layer * HID + c);
    }
    wf[((size_t)layer * 7 + k) * HID + c] = s;
}

// ---------------- CSR build ----------------------------------------------------
__global__ void deg_kernel(const int* __restrict__ dst, int* __restrict__ deg)
{
    int e = blockIdx.x * blockDim.x + threadIdx.x;
    if (e < NEDGES) atomicAdd(&deg[__ldg(dst + e)], 1);
}

__global__ void csr_scan_kernel(const int* __restrict__ deg,
                                int* __restrict__ rowstart,
                                int* __restrict__ cursor)
{
    const int CH = (NNODES + 1023) / 1024;
    __shared__ int ssum[1024];
    int t = threadIdx.x;
    int lo = t * CH;
    int hi = min(lo + CH, NNODES);
    int s = 0;
    for (int i = lo; i < hi; i++) s += deg[i];
    ssum[t] = s;
    __syncthreads();
    for (int off = 1; off < 1024; off <<= 1) {
        int v = (t >= off) ? ssum[t - off] : 0;
        __syncthreads();
        ssum[t] += v;
        __syncthreads();
    }
    int run = ssum[t] - s;
    for (int i = lo; i < hi; i++) {
        rowstart[i] = run;
        cursor[i] = run;
        run += deg[i];
    }
    if (hi == NNODES) rowstart[NNODES] = run;
}

__global__ void csr_fill_kernel(const int* __restrict__ src,
                                const int* __restrict__ dst,
                                int* __restrict__ cursor,
                                int* __restrict__ csr_eid,
                                int* __restrict__ csr_src)
{
    int e = blockIdx.x * blockDim.x + threadIdx.x;
    if (e >= NEDGES) return;
    int d = __ldg(dst + e);
    int p = atomicAdd(&cursor[d], 1);
    csr_eid[p] = e;
    csr_src[p] = __ldg(src + e);
}

// ---------------- graph ranges --------------------------------------------------
__global__ void gstart_min_kernel(const int* __restrict__ batch, int* __restrict__ gstart)
{
    int n = blockIdx.x * blockDim.x + threadIdx.x;
    if (n < NNODES) atomicMin(&gstart[__ldg(batch + n)], n);
}

__global__ void gstart_fix_kernel(int* __restrict__ gstart, float* __restrict__ cnt)
{
    __shared__ int sg[NGRAPH + 1];
    int t = threadIdx.x;
    for (int i = t; i <= NGRAPH; i += 1024) sg[i] = gstart[i];
    __syncthreads();
    if (t == 0) {
        sg[NGRAPH] = NNODES;
        for (int g2 = NGRAPH - 1; g2 >= 0; g2--)
            if (sg[g2] > sg[g2 + 1]) sg[g2] = sg[g2 + 1];
    }
    __syncthreads();
    for (int i = t; i <= NGRAPH; i += 1024) gstart[i] = sg[i];
    for (int i = t; i < NGRAPH; i += 1024)
        cnt[i] = fmaxf((float)(sg[i + 1] - sg[i]), 1.0f);
}

// ---------------- GINE gather (half h in, half aeff out) ----------------------
__device__ __forceinline__ float4 h4load(const uint2* hp, int idx) {
    uint2 u = __ldg(hp + idx);
    float2 f0 = __half22float2(*(__half2*)&u.x);
    float2 f1 = __half22float2(*(__half2*)&u.y);
    return make_float4(f0.x, f0.y, f1.x, f1.y);
}

__global__ __launch_bounds__(256) void gine_gather_fused(
    const __half* __restrict__ h,
    const float* __restrict__ ea,
    const int* __restrict__ rowstart,
    const int* __restrict__ csr_eid,
    const int* __restrict__ csr_src,
    const float* __restrict__ wf,
    const float* __restrict__ eps_ptr,
    __half* __restrict__ aeffh)
{
    const int lane = threadIdx.x & 31;
    const int warp_g = (blockIdx.x * blockDim.x + threadIdx.x) >> 5;
    const int nwarps = (gridDim.x * blockDim.x) >> 5;
    const float alpha = 1.0f + __ldg(eps_ptr);

    float4 w0[EDGE_F], w1[EDGE_F];
#pragma unroll
    for (int k = 0; k < EDGE_F; k++) {
        w0[k] = __ldg((const float4*)(wf + k * HID) + lane);
        w1[k] = __ldg((const float4*)(wf + k * HID) + 32 + lane);
    }
    float4 bf0 = __ldg((const float4*)(wf + EDGE_F * HID) + lane);
    float4 bf1 = __ldg((const float4*)(wf + EDGE_F * HID) + 32 + lane);

    for (int n = warp_g; n < NNODES; n += nwarps) {
        const uint2* hn = (const uint2*)(h + (size_t)n * HID);
        float4 a0 = h4load(hn, lane);
        float4 a1 = h4load(hn, 32 + lane);
        a0.x *= alpha; a0.y *= alpha; a0.z *= alpha; a0.w *= alpha;
        a1.x *= alpha; a1.y *= alpha; a1.z *= alpha; a1.w *= alpha;

        int lo = __ldg(rowstart + n), hi = __ldg(rowstart + n + 1);
        for (int j = lo; j < hi; j++) {
            int eid = __ldg(csr_eid + j);
            int s = __ldg(csr_src + j);
            const float* er = ea + (size_t)eid * EDGE_F;
            float e0 = __ldg(er + 0), e1 = __ldg(er + 1), e2 = __ldg(er + 2);
            float e3 = __ldg(er + 3), e4 = __ldg(er + 4), e5 = __ldg(er + 5);

            float4 ee0 = bf0, ee1 = bf1;
            ee0.x = fmaf(e0, w0[0].x, ee0.x); ee0.y = fmaf(e0, w0[0].y, ee0.y);
            ee0.z = fmaf(e0, w0[0].z, ee0.z); ee0.w = fmaf(e0, w0[0].w, ee0.w);
            ee1.x = fmaf(e0, w1[0].x, ee1.x); ee1.y = fmaf(e0, w1[0].y, ee1.y);
            ee1.z = fmaf(e0, w1[0].z, ee1.z); ee1.w = fmaf(e0, w1[0].w, ee1.w);
            ee0.x = fmaf(e1, w0[1].x, ee0.x); ee0.y = fmaf(e1, w0[1].y, ee0.y);
            ee0.z = fmaf(e1, w0[1].z, ee0.z); ee0.w = fmaf(e1, w0[1].w, ee0.w);
            ee1.x = fmaf(e1, w1[1].x, ee1.x); ee1.y = fmaf(e1, w1[1].y, ee1.y);
            ee1.z = fmaf(e1, w1[1].z, ee1.z); ee1.w = fmaf(e1, w1[1].w, ee1.w);
            ee0.x = fmaf(e2, w0[2].x, ee0.x); ee0.y = fmaf(e2, w0[2].y, ee0.y);
            ee0.z = fmaf(e2, w0[2].z, ee0.z); ee0.w = fmaf(e2, w0[2].w, ee0.w);
            ee1.x = fmaf(e2, w1[2].x, ee1.x); ee1.y = fmaf(e2, w1[2].y, ee1.y);
            ee1.z = fmaf(e2, w1[2].z, ee1.z); ee1.w = fmaf(e2, w1[2].w, ee1.w);
            ee0.x = fmaf(e3, w0[3].x, ee0.x); ee0.y = fmaf(e3, w0[3].y, ee0.y);
            ee0.z = fmaf(e3, w0[3].z, ee0.z); ee0.w = fmaf(e3, w0[3].w, ee0.w);
            ee1.x = fmaf(e3, w1[3].x, ee1.x); ee1.y = fmaf(e3, w1[3].y, ee1.y);
            ee1.z = fmaf(e3, w1[3].z, ee1.z); ee1.w = fmaf(e3, w1[3].w, ee1.w);
            ee0.x = fmaf(e4, w0[4].x, ee0.x); ee0.y = fmaf(e4, w0[4].y, ee0.y);
            ee0.z = fmaf(e4, w0[4].z, ee0.z); ee0.w = fmaf(e4, w0[4].w, ee0.w);
            ee1.x = fmaf(e4, w1[4].x, ee1.x); ee1.y = fmaf(e4, w1[4].y, ee1.y);
            ee1.z = fmaf(e4, w1[4].z, ee1.z); ee1.w = fmaf(e4, w1[4].w, ee1.w);
            ee0.x = fmaf(e5, w0[5].x, ee0.x); ee0.y = fmaf(e5, w0[5].y, ee0.y);
            ee0.z = fmaf(e5, w0[5].z, ee0.z); ee0.w = fmaf(e5, w0[5].w, ee0.w);
            ee1.x = fmaf(e5, w1[5].x, ee1.x); ee1.y = fmaf(e5, w1[5].y, ee1.y);
            ee1.z = fmaf(e5, w1[5].z, ee1.z); ee1.w = fmaf(e5, w1[5].w, ee1.w);

            const uint2* hp = (const uint2*)(h + (size_t)s * HID);
            float4 h0 = h4load(hp, lane);
            float4 h1 = h4load(hp, 32 + lane);
            a0.x += fmaxf(h0.x + ee0.x, 0.f); a0.y += fmaxf(h0.y + ee0.y, 0.f);
            a0.z += fmaxf(h0.z + ee0.z, 0.f); a0.w += fmaxf(h0.w + ee0.w, 0.f);
            a1.x += fmaxf(h1.x + ee1.x, 0.f); a1.y += fmaxf(h1.y + ee1.y, 0.f);
            a1.z += fmaxf(h1.z + ee1.z, 0.f); a1.w += fmaxf(h1.w + ee1.w, 0.f);
        }
        __half2* ap = (__half2*)(aeffh + (size_t)n * HID);
        ap[lane * 2]          = __floats2half2_rn(a0.x, a0.y);
        ap[lane * 2 + 1]      = __floats2half2_rn(a0.z, a0.w);
        ap[64 + lane * 2]     = __floats2half2_rn(a1.x, a1.y);
        ap[64 + lane * 2 + 1] = __floats2half2_rn(a1.z, a1.w);
    }
}

// ---------------- per-graph stats + global BN stats (half z) -------------------
__global__ void graph_stats_kernel(const __half* __restrict__ zh,
                                   const int* __restrict__ gstart,
                                   float* __restrict__ gsum,
                                   float* __restrict__ gsq,
                                   float* __restrict__ stats)
{
    int g = blockIdx.x;
    int c = threadIdx.x;
    int lo = gstart[g], hi = gstart[g + 1];
    float s = 0.f, q = 0.f;
    for (int n = lo; n < hi; n++) {
        float v = __half2float(__ldg(zh + (size_t)n * HID + c));
        s += v;
        q = fmaf(v, v, q);
    }
    gsum[(size_t)g * HID + c] = s;
    gsq[(size_t)g * HID + c] = q;
    atomicAdd(&stats[c], s);
    atomicAdd(&stats[HID + c], q);
}

// ---------------- per-graph msq -> scale; gsum -> mean --------------------------
__global__ void graph_msq_kernel(const float* __restrict__ stats,
                                 const float* __restrict__ gamma,
                                 const float* __restrict__ cnt,
                                 float* __restrict__ gsum,
                                 const float* __restrict__ gsq,
                                 float* __restrict__ sc)
{
    __shared__ float red[HID];
    int g = blockIdx.x;
    int c = threadIdx.x;
    const float invN = 1.0f / (float)NNODES;
    float mu = __ldg(stats + c) * invN;
    float var = __ldg(stats + HID + c) * invN - mu * mu;
    float ac = __ldg(gamma + c) * rsqrtf(var + 1e-5f);
    float cg = cnt[g];
    size_t i = (size_t)g * HID + c;
    float S = gsum[i], Q = gsq[i];
    float m = S / cg;
    gsum[i] = m;
    red[c] = ac * ac * (Q - cg * m * m);
    __syncthreads();
    for (int o = HID / 2; o > 0; o >>= 1) {
        if (c < o) red[c] += red[c + o];
        __syncthreads();
    }
    if (c == 0) sc[g] = rsqrtf(1e-5f + red[0] / cg);
}

// ---------------- fused BN+PairNorm normalize + ReLU ----------------------------
template <bool LAST>
__global__ void final_norm_kernel(const __half* __restrict__ zh,
                                  const float* __restrict__ stats,
                                  const float* __restrict__ gamma,
                                  const float* __restrict__ gmean,
                                  const float* __restrict__ sc,
                                  const int* __restrict__ batch,
                                  __half* __restrict__ houth,
                                  float* __restrict__ houtf)
{
    int r = blockIdx.x;
    int c = threadIdx.x;
    int g = __ldg(batch + r);
    const float invN = 1.0f / (float)NNODES;
    float mu = __ldg(stats + c) * invN;
    float var = __ldg(stats + HID + c) * invN - mu * mu;
    float ac = __ldg(gamma + c) * rsqrtf(var + 1e-5f);
    size_t i = (size_t)r * HID + c;
    float zv = __half2float(zh[i]);
    float v = ac * (zv - __ldg(gmean + (size_t)g * HID + c)) * __ldg(sc + g);
    v = fmaxf(v, 0.f);
    houth[i] = __float2half(v);
    if (LAST) houtf[i] = v;
}

// ---------------- attention score ------------------------------------------------
__global__ void attn_score_kernel(const float* __restrict__ s1,
                                  const float* __restrict__ w2,
                                  const float* __restrict__ b2,
                                  const int* __restrict__ batch,
                                  float* __restrict__ wexp,
                                  float* __restrict__ wsum)
{
    int row = (blockIdx.x * blockDim.x + threadIdx.x) >> 5;
    int lane = threadIdx.x & 31;
    if (row >= NNODES) return;
    float acc = 0.f;
#pragma unroll
    for (int k = lane; k < EDIM; k += 32)
        acc = fmaf(__ldg(s1 + (size_t)row * EDIM + k), __ldg(w2 + k), acc);
#pragma unroll
    for (int o = 16; o > 0; o >>= 1) acc += __shfl_down_sync(0xffffffffu, acc, o);
    if (lane == 0) {
        float w = expf(acc + __ldg(b2));
        wexp[row] = w;
        atomicAdd(&wsum[__ldg(batch + row)], w);
    }
}

// ---------------- pooling ----------------------------------------------------------
__global__ void pool_graph_kernel(const float* __restrict__ h,
                                  const float* __restrict__ wexp,
                                  const float* __restrict__ wsum,
                                  const int* __restrict__ gstart,
                                  const float* __restrict__ cnt,
                                  float* __restrict__ out)
{
    int g = blockIdx.x;
    int c = threadIdx.x;
    int lo = gstart[g], hi = gstart[g + 1];
    float inv_ws = 1.0f / (wsum[g] + 1e-8f);
    float s = 0.f, mx = 0.f, att = 0.f;
    for (int n = lo; n < hi; n++) {
        float v = __ldg(h + (size_t)n * HID + c);
        float coeff = __ldg(wexp + n) * inv_ws;
        s += v;
        mx = fmaxf(mx, v);
        att = fmaf(v, coeff, att);
    }
    float* og = out + (size_t)g * (3 * HID);
    og[c] = s / cnt[g];
    og[HID + c] = mx;
    og[2 * HID + c] = att;
}

// ---------------- host launch --------------------------------------------------------
extern "C" void kernel_launch(void* const* d_in, const int* in_sizes, int n_in,
                              void* d_out, int out_size)
{
    const float* x         = (const float*)d_in[0];
    const float* edge_attr = (const float*)d_in[1];
    const float* node_w    = (const float*)d_in[2];
    const float* node_b    = (const float*)d_in[3];
    const float* edge_w    = (const float*)d_in[4];
    const float* edge_b    = (const float*)d_in[5];
    const float* conv_w    = (const float*)d_in[6];
    const float* conv_b    = (const float*)d_in[7];
    const float* mlp_w1    = (const float*)d_in[8];
    const float* mlp_b1    = (const float*)d_in[9];
    const float* mlp_w2    = (const float*)d_in[10];
    const float* mlp_b2    = (const float*)d_in[11];
    const float* eps       = (const float*)d_in[12];
    const float* bn_gamma  = (const float*)d_in[13];
    const float* bn_beta   = (const float*)d_in[14];
    const float* att_w1    = (const float*)d_in[15];
    const float* att_b1    = (const float*)d_in[16];
    const float* att_w2    = (const float*)d_in[17];
    const float* att_b2    = (const float*)d_in[18];
    const int*   edge_index= (const int*)d_in[19];
    const int*   batch     = (const int*)d_in[20];
    float* out = (float*)d_out;
    (void)bn_beta;   // cancels exactly under PairNorm centering

    const int* src = edge_index;
    const int* dst = edge_index + NEDGES;

    cudaFuncSetAttribute(tf32_gemm<2>, cudaFuncAttributeMaxDynamicSharedMemorySize, GEMM_SMEM_BYTES);
    cudaFuncSetAttribute(tf32_gemm<3>, cudaFuncAttributeMaxDynamicSharedMemorySize, GEMM_SMEM_BYTES);
    cudaFuncSetAttribute(hgemm<1>, cudaFuncAttributeMaxDynamicSharedMemorySize, HG_SMEM_BYTES);
    cudaFuncSetAttribute(hgemm<2>, cudaFuncAttributeMaxDynamicSharedMemorySize, HG_SMEM_BYTES);

    float *p_hfin, *p_tmp, *p_stats, *p_gsum, *p_gsq,
          *p_sc, *p_cnt, *p_wexp, *p_wsum, *p_wf;
    __half *p_hh0, *p_hh1, *p_zh, *p_aeffh, *p_tmph;
    __half2 *p_w1p, *p_w2p;
    int *p_deg, *p_rowstart, *p_cursor, *p_eid, *p_csrc, *p_gstart;
    cudaGetSymbolAddress((void**)&p_hh0, g_hh0);
    cudaGetSymbolAddress((void**)&p_hh1, g_hh1);
    cudaGetSymbolAddress((void**)&p_zh, g_zh);
    cudaGetSymbolAddress((void**)&p_aeffh, g_aeffh);
    cudaGetSymbolAddress((void**)&p_tmph, g_tmph);
    cudaGetSymbolAddress((void**)&p_hfin, g_hfin);
    cudaGetSymbolAddress((void**)&p_tmp, g_tmp);
    cudaGetSymbolAddress((void**)&p_w1p, g_w1p);
    cudaGetSymbolAddress((void**)&p_w2p, g_w2p);
    cudaGetSymbolAddress((void**)&p_stats, g_stats);
    cudaGetSymbolAddress((void**)&p_gsum, g_gsum);
    cudaGetSymbolAddress((void**)&p_gsq, g_gsq);
    cudaGetSymbolAddress((void**)&p_sc, g_sc);
    cudaGetSymbolAddress((void**)&p_cnt, g_cnt);
    cudaGetSymbolAddress((void**)&p_wexp, g_wexp);
    cudaGetSymbolAddress((void**)&p_wsum, g_wsum);
    cudaGetSymbolAddress((void**)&p_wf, g_wf);
    cudaGetSymbolAddress((void**)&p_deg, g_deg);
    cudaGetSymbolAddress((void**)&p_rowstart, g_rowstart);
    cudaGetSymbolAddress((void**)&p_cursor, g_cursor);
    cudaGetSymbolAddress((void**)&p_eid, g_csr_eid);
    cudaGetSymbolAddress((void**)&p_csrc, g_csr_src);
    cudaGetSymbolAddress((void**)&p_gstart, g_gstart);

    // ----- CSR build
    cudaMemsetAsync(p_deg, 0, NNODES * sizeof(int));
    deg_kernel<<<(NEDGES + 255) / 256, 256>>>(dst, p_deg);
    csr_scan_kernel<<<1, 1024>>>(p_deg, p_rowstart, p_cursor);
    csr_fill_kernel<<<(NEDGES + 255) / 256, 256>>>(src, dst, p_cursor, p_eid, p_csrc);

    // ----- graph ranges + counts
    cudaMemsetAsync(p_gstart, 0x7F, (NGRAPH + 1) * sizeof(int));
    gstart_min_kernel<<<(NNODES + 255) / 256, 256>>>(batch, p_gstart);
    gstart_fix_kernel<<<1, 1024>>>(p_gstart, p_cnt);

    // ----- weight prep
    wfuse_kernel<<<dim3(NLAYER, 7), HID>>>(edge_w, edge_b, conv_w, conv_b, p_wf);
    wpack_kernel<<<(NLAYER * 128 * 256) / 256, 256>>>(mlp_w1, mlp_w2, p_w1p, p_w2p);

    // ----- node embedding (tf32, half output)
    {
        dim3 grid(HID / 128, (NNODES + 127) / 128);
        tf32_gemm<3><<<grid, 256, GEMM_SMEM_BYTES>>>(NNODES, HID, NODE_F, x, node_w,
                                                     node_b, nullptr, p_hh0);
    }

    __half* h_cur = p_hh0;
    __half* h_nxt = p_hh1;
    dim3 hgrid(2, (NNODES + 127) / 128);

    for (int i = 0; i < NLAYER; i++) {
        gine_gather_fused<<<1024, 256>>>(
            h_cur, edge_attr, p_rowstart, p_eid, p_csrc,
            p_wf + (size_t)i * 7 * HID, eps + i, p_aeffh);

        hgemm<1><<<hgrid, 256, HG_SMEM_BYTES>>>(
            NNODES, p_aeffh, p_w1p + (size_t)i * 32768,
            mlp_b1 + (size_t)i * HID, p_tmph);
        hgemm<2><<<hgrid, 256, HG_SMEM_BYTES>>>(
            NNODES, p_tmph, p_w2p + (size_t)i * 32768,
            mlp_b2 + (size_t)i * HID, p_zh);

        cudaMemsetAsync(p_stats, 0, 2 * HID * sizeof(float));
        graph_stats_kernel<<<NGRAPH, HID>>>(p_zh, p_gstart, p_gsum, p_gsq, p_stats);
        graph_msq_kernel<<<NGRAPH, HID>>>(p_stats, bn_gamma + (size_t)i * HID,
                                          p_cnt, p_gsum, p_gsq, p_sc);
        if (i == NLAYER - 1)
            final_norm_kernel<true><<<NNODES, HID>>>(p_zh, p_stats, bn_gamma + (size_t)i * HID,
                                                     p_gsum, p_sc, batch, h_nxt, p_hfin);
        else
            final_norm_kernel<false><<<NNODES, HID>>>(p_zh, p_stats, bn_gamma + (size_t)i * HID,
                                                      p_gsum, p_sc, batch, h_nxt, nullptr);

        __half* t = h_cur; h_cur = h_nxt; h_nxt = t;
    }

    // attention hidden: s1 = tanh(hfin @ att_w1 + att_b1)  (tf32, fp32 out)
    {
        dim3 grid(EDIM / 128, (NNODES + 127) / 128);
        tf32_gemm<2><<<grid, 256, GEMM_SMEM_BYTES>>>(NNODES, EDIM, HID, p_hfin, att_w1,
                                                     att_b1, p_tmp, nullptr);
    }

    cudaMemsetAsync(p_wsum, 0, NGRAPH * sizeof(float));
    attn_score_kernel<<<(NNODES * 32 + 255) / 256, 256>>>(p_tmp, att_w2, att_b2, batch, p_wexp, p_wsum);

    pool_graph_kernel<<<NGRAPH, HID>>>(p_hfin, p_wexp, p_wsum, p_gstart, p_cnt, out);

    (void)in_sizes; (void)n_in; (void)out_size;
}

// round 7
// speedup vs baseline: 4.8211x; 1.0157x over previous
#include <cuda_runtime.h>
#include <cuda_fp16.h>
#include <math.h>
#include <stdint.h>

#define NNODES 100000
#define NEDGES 320000
#define NGRAPH 2048
#define HID    256
#define EDIM   128
#define NODE_F 48
#define EDGE_F 6
#define NLAYER 8

// ---------------- scratch (device globals) ----------------------------------
__device__ __half  g_hh0[(size_t)NNODES * HID];
__device__ __half  g_hh1[(size_t)NNODES * HID];
__device__ __half  g_zh [(size_t)NNODES * HID];
__device__ __half  g_aeffh[(size_t)NNODES * HID];
__device__ __half  g_tmph [(size_t)NNODES * HID];   // MLP tmp; reused as s1
__device__ __half2 g_w1p[(size_t)NLAYER * (HID / 2) * HID];
__device__ __half2 g_w2p[(size_t)NLAYER * (HID / 2) * HID];
__device__ __half2 g_w1a[(size_t)(HID / 2) * EDIM];  // attention w1 packed
__device__ float   g_stats[2 * HID];
__device__ float   g_gsum[(size_t)NGRAPH * HID];
__device__ float   g_gsq [(size_t)NGRAPH * HID];
__device__ float   g_sc  [NGRAPH];
__device__ float   g_cnt [NGRAPH];
__device__ float   g_wexp[NNODES];
__device__ float   g_wsum[NGRAPH];
__device__ float   g_wf  [(size_t)NLAYER * 7 * HID];
__device__ int     g_deg [NNODES];
__device__ int     g_rowstart[NNODES + 1];
__device__ int     g_cursor[NNODES];
__device__ int     g_csr_eid[NEDGES];
__device__ int     g_csr_src[NEDGES];
__device__ int     g_gstart[NGRAPH + 1];

// ---------------- common helpers ---------------------------------------------
__device__ __forceinline__ uint32_t f2tf32(float x) {
    uint32_t r;
    asm volatile("cvt.rna.tf32.f32 %0, %1;" : "=r"(r) : "f"(x));
    return r;
}
__device__ __forceinline__ void cp16s(uint32_t d, const void* src, bool pred) {
    int sz = pred ? 16 : 0;
    asm volatile("cp.async.cg.shared.global [%0], [%1], 16, %2;" :: "r"(d), "l"(src), "r"(sz));
}
__device__ __forceinline__ void cp_commit() { asm volatile("cp.async.commit_group;"); }
template <int Np>
__device__ __forceinline__ void cp_wait() { asm volatile("cp.async.wait_group %0;" :: "n"(Np)); }

extern __shared__ char smemc[];

// ===================== fp16 tensor-core GEMM v2 (K=256, BK=64) ================
// A [M,256] half row-major. Bp [128][WN] half2 k-pair packed.
// MODE 1: relu->half. MODE 2: none->half. MODE 3: tanh->half.
#define HA_STRIDE 72                       // halves per A smem row (64 + 8 pad)
#define HA_TILE_BYTES (128 * HA_STRIDE * 2)

__device__ __forceinline__ void mma_f16(float* c, const uint32_t* a, const uint32_t* b) {
    asm volatile(
        "mma.sync.aligned.m16n8k16.row.col.f32.f16.f16.f32 "
        "{%0,%1,%2,%3}, {%4,%5,%6,%7}, {%8,%9}, {%0,%1,%2,%3};"
        : "+f"(c[0]), "+f"(c[1]), "+f"(c[2]), "+f"(c[3])
        : "r"(a[0]), "r"(a[1]), "r"(a[2]), "r"(a[3]), "r"(b[0]), "r"(b[1]));
}
__device__ __forceinline__ void ldsm4(uint32_t* r, uint32_t addr) {
    asm volatile("ldmatrix.sync.aligned.m8n8.x4.shared.b16 {%0,%1,%2,%3}, [%4];"
                 : "=r"(r[0]), "=r"(r[1]), "=r"(r[2]), "=r"(r[3]) : "r"(addr));
}

template <int MODE, int WN>
__global__ __launch_bounds__(256, 2) void hgemm(
    int M, const __half* __restrict__ A, const __half2* __restrict__ Bp,
    const float* __restrict__ bias, __half* __restrict__ Ch)
{
    constexpr int HB2_STRIDE = WN + 4;                   // half2 per B smem row
    constexpr int HB_TILE2 = 32 * HB2_STRIDE;            // half2 per buf
    const __half2* hB = (const __half2*)(smemc + 2 * HA_TILE_BYTES);
    uint32_t sb = (uint32_t)__cvta_generic_to_shared(smemc);
    uint32_t sbB = sb + 2 * HA_TILE_BYTES;

    const int tid = threadIdx.x;
    const int warp = tid >> 5;
    const int lane = tid & 31;
    const int g = lane >> 2;
    const int tq = lane & 3;
    const int m0 = blockIdx.y * 128;
    const int n0 = blockIdx.x * 128;
    const int wm = (warp >> 1) * 32;
    const int wn = (warp & 1) * 64;

    // ldmatrix lane address components (quadrant mapping)
    const int lrow = ((lane >> 3) & 1) * 8 + (lane & 7);
    const int lcol = (lane >> 4) * 8;

    float acc[2][8][4];
#pragma unroll
    for (int i = 0; i < 2; i++)
#pragma unroll
        for (int j = 0; j < 8; j++)
#pragma unroll
            for (int r = 0; r < 4; r++) acc[i][j][r] = 0.0f;

    // fill helpers (BK=64)
    auto fillA = [&](int buf, int k0) {
#pragma unroll
        for (int it = 0; it < 4; it++) {
            int chunk = tid + it * 256;           // 1024 chunks of 16B
            int r = chunk >> 3;
            int c = (chunk & 7) * 8;              // half index in 64
            int gm = m0 + r;
            bool p = gm < M;
            cp16s(sb + buf * HA_TILE_BYTES + (r * HA_STRIDE + c) * 2,
                  A + (size_t)(p ? gm : 0) * 256 + k0 + c, p);
        }
    };
    auto fillB = [&](int buf, int k0) {
        constexpr int CPT = WN / 32;              // chunks per thread (8 or 4)
#pragma unroll
        for (int it = 0; it < CPT; it++) {
            int chunk = tid + it * 256;
            int pr = chunk / (WN / 4);
            int c2 = (chunk % (WN / 4)) * 4;
            cp16s(sbB + (buf * HB_TILE2 + pr * HB2_STRIDE + c2) * 4,
                  Bp + (size_t)((k0 >> 1) + pr) * WN + n0 + c2, true);
        }
    };

    fillA(0, 0);
    fillB(0, 0);
    cp_commit();

    int buf = 0;
#pragma unroll 1
    for (int i = 0; i < 4; i++) {
        if (i + 1 < 4) {
            fillA(buf ^ 1, (i + 1) * 64);
            fillB(buf ^ 1, (i + 1) * 64);
            cp_commit();
            cp_wait<1>();
        } else {
            cp_wait<0>();
        }
        __syncthreads();

        uint32_t abase = sb + buf * HA_TILE_BYTES;
        const __half2* Bb = hB + buf * HB_TILE2;
#pragma unroll
        for (int kk = 0; kk < 4; kk++) {
            uint32_t af[2][4];
#pragma unroll
            for (int mi = 0; mi < 2; mi++) {
                uint32_t addr = abase + ((wm + mi * 16 + lrow) * HA_STRIDE + kk * 16 + lcol) * 2;
                ldsm4(af[mi], addr);
            }
            uint32_t bf[8][2];
#pragma unroll
            for (int ni = 0; ni < 8; ni++) {
                const __half2* p = Bb + (kk * 8 + tq) * HB2_STRIDE + wn + ni * 8 + g;
                bf[ni][0] = *(const uint32_t*)(p);
                bf[ni][1] = *(const uint32_t*)(p + 4 * HB2_STRIDE);
            }
#pragma unroll
            for (int mi = 0; mi < 2; mi++)
#pragma unroll
                for (int ni = 0; ni < 8; ni++)
                    mma_f16(acc[mi][ni], af[mi], bf[ni]);
        }
        __syncthreads();
        buf ^= 1;
    }

#pragma unroll
    for (int mi = 0; mi < 2; mi++) {
        int r0 = m0 + wm + mi * 16 + g;
        int r1 = r0 + 8;
#pragma unroll
        for (int ni = 0; ni < 8; ni++) {
            int col = n0 + wn + ni * 8 + tq * 2;
            float b0 = __ldg(bias + col);
            float b1 = __ldg(bias + col + 1);
            float v0 = acc[mi][ni][0] + b0;
            float v1 = acc[mi][ni][1] + b1;
            float v2 = acc[mi][ni][2] + b0;
            float v3 = acc[mi][ni][3] + b1;
            if (MODE == 1) {
                v0 = fmaxf(v0, 0.f); v1 = fmaxf(v1, 0.f);
                v2 = fmaxf(v2, 0.f); v3 = fmaxf(v3, 0.f);
            } else if (MODE == 3) {
                v0 = tanhf(v0); v1 = tanhf(v1);
                v2 = tanhf(v2); v3 = tanhf(v3);
            }
            if (r0 < M) *(__half2*)(Ch + (size_t)r0 * WN + col - n0 + (size_t)n0) = __floats2half2_rn(v0, v1);
            if (r1 < M) *(__half2*)(Ch + (size_t)r1 * WN + col - n0 + (size_t)n0) = __floats2half2_rn(v2, v3);
        }
    }
}

// NOTE: output row stride equals WN (256 for MLP tensors, 128 for s1).

// ---------------- weight pack (MLP) -------------------------------------------
__global__ void wpack_kernel(const float* __restrict__ w1, const float* __restrict__ w2,
                             __half2* __restrict__ w1p, __half2* __restrict__ w2p)
{
    int idx = blockIdx.x * 256 + threadIdx.x;
    int l = idx >> 15;
    int rem = idx & 32767;
    int p = rem >> 8;
    int n = rem & 255;
    size_t base = (size_t)l * 65536 + (size_t)(2 * p) * 256 + n;
    w1p[idx] = __floats2half2_rn(__ldg(w1 + base), __ldg(w1 + base + 256));
    w2p[idx] = __floats2half2_rn(__ldg(w2 + base), __ldg(w2 + base + 256));
}

// ---------------- weight pack (attention w1: [256,128] -> [128][128] half2) ----
__global__ void wpack_att_kernel(const float* __restrict__ w, __half2* __restrict__ wp)
{
    int idx = blockIdx.x * 256 + threadIdx.x;   // [0, 128*128)
    int p = idx >> 7;
    int n = idx & 127;
    size_t base = (size_t)(2 * p) * 128 + n;
    wp[idx] = __floats2half2_rn(__ldg(w + base), __ldg(w + base + 128));
}

// ===================== mma.sync TF32 GEMM (node embed only) ===================
#define GA_STRIDE 36
#define GB_STRIDE 132
#define A_TILE_W (128 * GA_STRIDE)
#define B_TILE_W (32 * GB_STRIDE)
#define GEMM_SMEM_BYTES ((2 * A_TILE_W + 2 * B_TILE_W) * 4)

__device__ __forceinline__ void cp16(float* dst, const float* src, bool pred) {
    cp16s((uint32_t)__cvta_generic_to_shared(dst), src, pred);
}
__device__ __forceinline__ void mma_tf32(float* c, const uint32_t* a, const uint32_t* b) {
    asm volatile(
        "mma.sync.aligned.m16n8k8.row.col.f32.tf32.tf32.f32 "
        "{%0,%1,%2,%3}, {%4,%5,%6,%7}, {%8,%9}, {%0,%1,%2,%3};"
        : "+f"(c[0]), "+f"(c[1]), "+f"(c[2]), "+f"(c[3])
        : "r"(a[0]), "r"(a[1]), "r"(a[2]), "r"(a[3]), "r"(b[0]), "r"(b[1]));
}

__global__ __launch_bounds__(256, 2) void tf32_gemm_h(
    int M, int N, int K,
    const float* __restrict__ A, const float* __restrict__ B,
    const float* __restrict__ bias, __half* __restrict__ Chh)
{
    float* sm = (float*)smemc;
    float* As = sm;
    float* Bs = sm + 2 * A_TILE_W;

    const int tid = threadIdx.x;
    const int warp = tid >> 5;
    const int lane = tid & 31;
    const int g = lane >> 2;
    const int tq = lane & 3;
    const int m0 = blockIdx.y * 128;
    const int n0 = blockIdx.x * 128;
    const int wm = (warp >> 1) * 32;
    const int wn = (warp & 1) * 64;

    float acc[2][8][4];
#pragma unroll
    for (int i = 0; i < 2; i++)
#pragma unroll
        for (int j = 0; j < 8; j++)
#pragma unroll
            for (int r = 0; r < 4; r++) acc[i][j][r] = 0.0f;

    const int arow = tid >> 3;
    const int ac4 = tid & 7;
    const int brow = tid >> 5;
    const int bc4 = tid & 31;
    const int nk = (K + 31) / 32;

    {
#pragma unroll
        for (int it = 0; it < 4; it++) {
            int row = arow + it * 32;
            int gm = m0 + row;
            int gk = ac4 * 4;
            bool p = (gm < M) && (gk < K);
            const float* src = A + (size_t)(p ? gm : 0) * K + (p ? gk : 0);
            cp16(As + row * GA_STRIDE + ac4 * 4, src, p);
        }
#pragma unroll
        for (int it = 0; it < 4; it++) {
            int row = brow + it * 8;
            bool p = (row < K);
            const float* src = B + (size_t)(p ? row : 0) * N + n0 + bc4 * 4;
            cp16(Bs + row * GB_STRIDE + bc4 * 4, src, p);
        }
        cp_commit();
    }

    int buf = 0;
    for (int i = 0; i < nk; i++) {
        if (i + 1 < nk) {
            const int kc = i + 1;
            float* Ad = As + (buf ^ 1) * A_TILE_W;
            float* Bd = Bs + (buf ^ 1) * B_TILE_W;
#pragma unroll
            for (int it = 0; it < 4; it++) {
                int row = arow + it * 32;
                int gm = m0 + row;
                int gk = kc * 32 + ac4 * 4;
                bool p = (gm < M) && (gk < K);
                const float* src = A + (size_t)(p ? gm : 0) * K + (p ? gk : 0);
                cp16(Ad + row * GA_STRIDE + ac4 * 4, src, p);
            }
#pragma unroll
            for (int it = 0; it < 4; it++) {
                int row = brow + it * 8;
                int gk = kc * 32 + row;
                bool p = (gk < K);
                const float* src = B + (size_t)(p ? gk : 0) * N + n0 + bc4 * 4;
                cp16(Bd + row * GB_STRIDE + bc4 * 4, src, p);
            }
            cp_commit();
            cp_wait<1>();
        } else {
            cp_wait<0>();
        }
        __syncthreads();

        const float* Ab = As + buf * A_TILE_W;
        const float* Bb = Bs + buf * B_TILE_W;
#pragma unroll
        for (int kk = 0; kk < 4; kk++) {
            const int k = kk * 8;
            uint32_t af[2][4];
#pragma unroll
            for (int mi = 0; mi < 2; mi++) {
                const float* p = Ab + (wm + mi * 16 + g) * GA_STRIDE + k + tq;
                af[mi][0] = f2tf32(p[0]);
                af[mi][1] = f2tf32(p[8 * GA_STRIDE]);
                af[mi][2] = f2tf32(p[4]);
                af[mi][3] = f2tf32(p[8 * GA_STRIDE + 4]);
            }
            uint32_t bf[8][2];
#pragma unroll
            for (int ni = 0; ni < 8; ni++) {
                const float* p = Bb + (k + tq) * GB_STRIDE + wn + ni * 8 + g;
                bf[ni][0] = f2tf32(p[0]);
                bf[ni][1] = f2tf32(p[4 * GB_STRIDE]);
            }
#pragma unroll
            for (int mi = 0; mi < 2; mi++)
#pragma unroll
                for (int ni = 0; ni < 8; ni++)
                    mma_tf32(acc[mi][ni], af[mi], bf[ni]);
        }
        __syncthreads();
        buf ^= 1;
    }

#pragma unroll
    for (int mi = 0; mi < 2; mi++) {
        int r0 = m0 + wm + mi * 16 + g;
        int r1 = r0 + 8;
#pragma unroll
        for (int ni = 0; ni < 8; ni++) {
            int col = n0 + wn + ni * 8 + tq * 2;
            float b0 = __ldg(bias + col);
            float b1 = __ldg(bias + col + 1);
            float v0 = acc[mi][ni][0] + b0;
            float v1 = acc[mi][ni][1] + b1;
            float v2 = acc[mi][ni][2] + b0;
            float v3 = acc[mi][ni][3] + b1;
            if (r0 < M) *(__half2*)(Chh + (size_t)r0 * N + col) = __floats2half2_rn(v0, v1);
            if (r1 < M) *(__half2*)(Chh + (size_t)r1 * N + col) = __floats2half2_rn(v2, v3);
        }
    }
}

// ---------------- fused edge weights ------------------------------------------
__global__ void wfuse_kernel(const float* __restrict__ edge_w,
                             const float* __restrict__ edge_b,
                             const float* __restrict__ conv_w,
                             const float* __restrict__ conv_b,
                             float* __restrict__ wf)
{
    int layer = blockIdx.x;
    int k = blockIdx.y;
    int c = threadIdx.x;
    const float* cw = conv_w + (size_t)layer * EDIM * HID;
    float s = 0.f;
    if (k < EDGE_F) {
        for (int j = 0; j < EDIM; j++)
            s = fmaf(__ldg(edge_w + k * EDIM + j), __ldg(cw + (size_t)j * HID + c), s);
    } else {
        for (int j = 0; j < EDIM; j++)
            s = fmaf(__ldg(edge_b + j), __ldg(cw + (size_t)j * HID + c), s);
        s += __ldg(conv_b + (size_t)layer * HID + c);
    }
    wf[((size_t)layer * 7 + k) * HID + c] = s;
}

// ---------------- CSR build ----------------------------------------------------
__global__ void deg_kernel(const int* __restrict__ dst, int* __restrict__ deg)
{
    int e = blockIdx.x * blockDim.x + threadIdx.x;
    if (e < NEDGES) atomicAdd(&deg[__ldg(dst + e)], 1);
}

__global__ void csr_scan_kernel(const int* __restrict__ deg,
                                int* __restrict__ rowstart,
                                int* __restrict__ cursor)
{
    const int CH = (NNODES + 1023) / 1024;
    __shared__ int ssum[1024];
    int t = threadIdx.x;
    int lo = t * CH;
    int hi = min(lo + CH, NNODES);
    int s = 0;
    for (int i = lo; i < hi; i++) s += deg[i];
    ssum[t] = s;
    __syncthreads();
    for (int off = 1; off < 1024; off <<= 1) {
        int v = (t >= off) ? ssum[t - off] : 0;
        __syncthreads();
        ssum[t] += v;
        __syncthreads();
    }
    int run = ssum[t] - s;
    for (int i = lo; i < hi; i++) {
        rowstart[i] = run;
        cursor[i] = run;
        run += deg[i];
    }
    if (hi == NNODES) rowstart[NNODES] = run;
}

__global__ void csr_fill_kernel(const int* __restrict__ src,
                                const int* __restrict__ dst,
                                int* __restrict__ cursor,
                                int* __restrict__ csr_eid,
                                int* __restrict__ csr_src)
{
    int e = blockIdx.x * blockDim.x + threadIdx.x;
    if (e >= NEDGES) return;
    int d = __ldg(dst + e);
    int p = atomicAdd(&cursor[d], 1);
    csr_eid[p] = e;
    csr_src[p] = __ldg(src + e);
}

// ---------------- graph ranges --------------------------------------------------
__global__ void gstart_min_kernel(const int* __restrict__ batch, int* __restrict__ gstart)
{
    int n = blockIdx.x * blockDim.x + threadIdx.x;
    if (n < NNODES) atomicMin(&gstart[__ldg(batch + n)], n);
}

__global__ void gstart_fix_kernel(int* __restrict__ gstart, float* __restrict__ cnt)
{
    __shared__ int sg[NGRAPH + 1];
    int t = threadIdx.x;
    for (int i = t; i <= NGRAPH; i += 1024) sg[i] = gstart[i];
    __syncthreads();
    if (t == 0) {
        sg[NGRAPH] = NNODES;
        for (int g2 = NGRAPH - 1; g2 >= 0; g2--)
            if (sg[g2] > sg[g2 + 1]) sg[g2] = sg[g2 + 1];
    }
    __syncthreads();
    for (int i = t; i <= NGRAPH; i += 1024) gstart[i] = sg[i];
    for (int i = t; i < NGRAPH; i += 1024)
        cnt[i] = fmaxf((float)(sg[i + 1] - sg[i]), 1.0f);
}

// ---------------- GINE gather (half h in, half aeff out) ----------------------
__device__ __forceinline__ float4 h4load(const uint2* hp, int idx) {
    uint2 u = __ldg(hp + idx);
    float2 f0 = __half22float2(*(__half2*)&u.x);
    float2 f1 = __half22float2(*(__half2*)&u.y);
    return make_float4(f0.x, f0.y, f1.x, f1.y);
}

__global__ __launch_bounds__(256) void gine_gather_fused(
    const __half* __restrict__ h,
    const float* __restrict__ ea,
    const int* __restrict__ rowstart,
    const int* __restrict__ csr_eid,
    const int* __restrict__ csr_src,
    const float* __restrict__ wf,
    const float* __restrict__ eps_ptr,
    __half* __restrict__ aeffh)
{
    const int lane = threadIdx.x & 31;
    const int warp_g = (blockIdx.x * blockDim.x + threadIdx.x) >> 5;
    const int nwarps = (gridDim.x * blockDim.x) >> 5;
    const float alpha = 1.0f + __ldg(eps_ptr);

    float4 w0[EDGE_F], w1[EDGE_F];
#pragma unroll
    for (int k = 0; k < EDGE_F; k++) {
        w0[k] = __ldg((const float4*)(wf + k * HID) + lane);
        w1[k] = __ldg((const float4*)(wf + k * HID) + 32 + lane);
    }
    float4 bf0 = __ldg((const float4*)(wf + EDGE_F * HID) + lane);
    float4 bf1 = __ldg((const float4*)(wf + EDGE_F * HID) + 32 + lane);

    for (int n = warp_g; n < NNODES; n += nwarps) {
        const uint2* hn = (const uint2*)(h + (size_t)n * HID);
        float4 a0 = h4load(hn, lane);
        float4 a1 = h4load(hn, 32 + lane);
        a0.x *= alpha; a0.y *= alpha; a0.z *= alpha; a0.w *= alpha;
        a1.x *= alpha; a1.y *= alpha; a1.z *= alpha; a1.w *= alpha;

        int lo = __ldg(rowstart + n), hi = __ldg(rowstart + n + 1);
        for (int j = lo; j < hi; j++) {
            int eid = __ldg(csr_eid + j);
            int s = __ldg(csr_src + j);
            const float* er = ea + (size_t)eid * EDGE_F;
            float e0 = __ldg(er + 0), e1 = __ldg(er + 1), e2 = __ldg(er + 2);
            float e3 = __ldg(er + 3), e4 = __ldg(er + 4), e5 = __ldg(er + 5);

            float4 ee0 = bf0, ee1 = bf1;
            ee0.x = fmaf(e0, w0[0].x, ee0.x); ee0.y = fmaf(e0, w0[0].y, ee0.y);
            ee0.z = fmaf(e0, w0[0].z, ee0.z); ee0.w = fmaf(e0, w0[0].w, ee0.w);
            ee1.x = fmaf(e0, w1[0].x, ee1.x); ee1.y = fmaf(e0, w1[0].y, ee1.y);
            ee1.z = fmaf(e0, w1[0].z, ee1.z); ee1.w = fmaf(e0, w1[0].w, ee1.w);
            ee0.x = fmaf(e1, w0[1].x, ee0.x); ee0.y = fmaf(e1, w0[1].y, ee0.y);
            ee0.z = fmaf(e1, w0[1].z, ee0.z); ee0.w = fmaf(e1, w0[1].w, ee0.w);
            ee1.x = fmaf(e1, w1[1].x, ee1.x); ee1.y = fmaf(e1, w1[1].y, ee1.y);
            ee1.z = fmaf(e1, w1[1].z, ee1.z); ee1.w = fmaf(e1, w1[1].w, ee1.w);
            ee0.x = fmaf(e2, w0[2].x, ee0.x); ee0.y = fmaf(e2, w0[2].y, ee0.y);
            ee0.z = fmaf(e2, w0[2].z, ee0.z); ee0.w = fmaf(e2, w0[2].w, ee0.w);
            ee1.x = fmaf(e2, w1[2].x, ee1.x); ee1.y = fmaf(e2, w1[2].y, ee1.y);
            ee1.z = fmaf(e2, w1[2].z, ee1.z); ee1.w = fmaf(e2, w1[2].w, ee1.w);
            ee0.x = fmaf(e3, w0[3].x, ee0.x); ee0.y = fmaf(e3, w0[3].y, ee0.y);
            ee0.z = fmaf(e3, w0[3].z, ee0.z); ee0.w = fmaf(e3, w0[3].w, ee0.w);
            ee1.x = fmaf(e3, w1[3].x, ee1.x); ee1.y = fmaf(e3, w1[3].y, ee1.y);
            ee1.z = fmaf(e3, w1[3].z, ee1.z); ee1.w = fmaf(e3, w1[3].w, ee1.w);
            ee0.x = fmaf(e4, w0[4].x, ee0.x); ee0.y = fmaf(e4, w0[4].y, ee0.y);
            ee0.z = fmaf(e4, w0[4].z, ee0.z); ee0.w = fmaf(e4, w0[4].w, ee0.w);
            ee1.x = fmaf(e4, w1[4].x, ee1.x); ee1.y = fmaf(e4, w1[4].y, ee1.y);
            ee1.z = fmaf(e4, w1[4].z, ee1.z); ee1.w = fmaf(e4, w1[4].w, ee1.w);
            ee0.x = fmaf(e5, w0[5].x, ee0.x); ee0.y = fmaf(e5, w0[5].y, ee0.y);
            ee0.z = fmaf(e5, w0[5].z, ee0.z); ee0.w = fmaf(e5, w0[5].w, ee0.w);
            ee1.x = fmaf(e5, w1[5].x, ee1.x); ee1.y = fmaf(e5, w1[5].y, ee1.y);
            ee1.z = fmaf(e5, w1[5].z, ee1.z); ee1.w = fmaf(e5, w1[5].w, ee1.w);

            const uint2* hp = (const uint2*)(h + (size_t)s * HID);
            float4 h0 = h4load(hp, lane);
            float4 h1 = h4load(hp, 32 + lane);
            a0.x += fmaxf(h0.x + ee0.x, 0.f); a0.y += fmaxf(h0.y + ee0.y, 0.f);
            a0.z += fmaxf(h0.z + ee0.z, 0.f); a0.w += fmaxf(h0.w + ee0.w, 0.f);
            a1.x += fmaxf(h1.x + ee1.x, 0.f); a1.y += fmaxf(h1.y + ee1.y, 0.f);
            a1.z += fmaxf(h1.z + ee1.z, 0.f); a1.w += fmaxf(h1.w + ee1.w, 0.f);
        }
        __half2* ap = (__half2*)(aeffh + (size_t)n * HID);
        ap[lane * 2]          = __floats2half2_rn(a0.x, a0.y);
        ap[lane * 2 + 1]      = __floats2half2_rn(a0.z, a0.w);
        ap[64 + lane * 2]     = __floats2half2_rn(a1.x, a1.y);
        ap[64 + lane * 2 + 1] = __floats2half2_rn(a1.z, a1.w);
    }
}

// ---------------- per-graph stats + global BN stats ----------------------------
__global__ void graph_stats_kernel(const __half* __restrict__ zh,
                                   const int* __restrict__ gstart,
                                   float* __restrict__ gsum,
                                   float* __restrict__ gsq,
                                   float* __restrict__ stats)
{
    int g = blockIdx.x;
    int c = threadIdx.x;
    int lo = gstart[g], hi = gstart[g + 1];
    float s = 0.f, q = 0.f;
    for (int n = lo; n < hi; n++) {
        float v = __half2float(__ldg(zh + (size_t)n * HID + c));
        s += v;
        q = fmaf(v, v, q);
    }
    gsum[(size_t)g * HID + c] = s;
    gsq[(size_t)g * HID + c] = q;
    atomicAdd(&stats[c], s);
    atomicAdd(&stats[HID + c], q);
}

// ---------------- per-graph msq -> scale; gsum -> mean --------------------------
__global__ void graph_msq_kernel(const float* __restrict__ stats,
                                 const float* __restrict__ gamma,
                                 const float* __restrict__ cnt,
                                 float* __restrict__ gsum,
                                 const float* __restrict__ gsq,
                                 float* __restrict__ sc)
{
    __shared__ float red[HID];
    int g = blockIdx.x;
    int c = threadIdx.x;
    const float invN = 1.0f / (float)NNODES;
    float mu = __ldg(stats + c) * invN;
    float var = __ldg(stats + HID + c) * invN - mu * mu;
    float ac = __ldg(gamma + c) * rsqrtf(var + 1e-5f);
    float cg = cnt[g];
    size_t i = (size_t)g * HID + c;
    float S = gsum[i], Q = gsq[i];
    float m = S / cg;
    gsum[i] = m;
    red[c] = ac * ac * (Q - cg * m * m);
    __syncthreads();
    for (int o = HID / 2; o > 0; o >>= 1) {
        if (c < o) red[c] += red[c + o];
        __syncthreads();
    }
    if (c == 0) sc[g] = rsqrtf(1e-5f + red[0] / cg);
}

// ---------------- fused BN+PairNorm normalize + ReLU ----------------------------
__global__ void final_norm_kernel(const __half* __restrict__ zh,
                                  const float* __restrict__ stats,
                                  const float* __restrict__ gamma,
                                  const float* __restrict__ gmean,
                                  const float* __restrict__ sc,
                                  const int* __restrict__ batch,
                                  __half* __restrict__ houth)
{
    int r = blockIdx.x;
    int c = threadIdx.x;
    int g = __ldg(batch + r);
    const float invN = 1.0f / (float)NNODES;
    float mu = __ldg(stats + c) * invN;
    float var = __ldg(stats + HID + c) * invN - mu * mu;
    float ac = __ldg(gamma + c) * rsqrtf(var + 1e-5f);
    size_t i = (size_t)r * HID + c;
    float zv = __half2float(zh[i]);
    float v = ac * (zv - __ldg(gmean + (size_t)g * HID + c)) * __ldg(sc + g);
    houth[i] = __float2half(fmaxf(v, 0.f));
}

// ---------------- attention score (half s1) -------------------------------------
__global__ void attn_score_kernel(const __half* __restrict__ s1,
                                  const float* __restrict__ w2,
                                  const float* __restrict__ b2,
                                  const int* __restrict__ batch,
                                  float* __restrict__ wexp,
                                  float* __restrict__ wsum)
{
    int row = (blockIdx.x * blockDim.x + threadIdx.x) >> 5;
    int lane = threadIdx.x & 31;
    if (row >= NNODES) return;
    const __half2* s = (const __half2*)(s1 + (size_t)row * EDIM);
    float acc = 0.f;
#pragma unroll
    for (int k = lane; k < EDIM / 2; k += 32) {
        float2 f = __half22float2(__ldg(s + k));
        acc = fmaf(f.x, __ldg(w2 + 2 * k), acc);
        acc = fmaf(f.y, __ldg(w2 + 2 * k + 1), acc);
    }
#pragma unroll
    for (int o = 16; o > 0; o >>= 1) acc += __shfl_down_sync(0xffffffffu, acc, o);
    if (lane == 0) {
        float w = expf(acc + __ldg(b2));
        wexp[row] = w;
        atomicAdd(&wsum[__ldg(batch + row)], w);
    }
}

// ---------------- pooling (half h) ----------------------------------------------
__global__ void pool_graph_kernel(const __half* __restrict__ h,
                                  const float* __restrict__ wexp,
                                  const float* __restrict__ wsum,
                                  const int* __restrict__ gstart,
                                  const float* __restrict__ cnt,
                                  float* __restrict__ out)
{
    int g = blockIdx.x;
    int c = threadIdx.x;
    int lo = gstart[g], hi = gstart[g + 1];
    float inv_ws = 1.0f / (wsum[g] + 1e-8f);
    float s = 0.f, mx = 0.f, att = 0.f;
    for (int n = lo; n < hi; n++) {
        float v = __half2float(__ldg(h + (size_t)n * HID + c));
        float coeff = __ldg(wexp + n) * inv_ws;
        s += v;
        mx = fmaxf(mx, v);
        att = fmaf(v, coeff, att);
    }
    float* og = out + (size_t)g * (3 * HID);
    og[c] = s / cnt[g];
    og[HID + c] = mx;
    og[2 * HID + c] = att;
}

// ---------------- host launch --------------------------------------------------------
extern "C" void kernel_launch(void* const* d_in, const int* in_sizes, int n_in,
                              void* d_out, int out_size)
{
    const float* x         = (const float*)d_in[0];
    const float* edge_attr = (const float*)d_in[1];
    const float* node_w    = (const float*)d_in[2];
    const float* node_b    = (const float*)d_in[3];
    const float* edge_w    = (const float*)d_in[4];
    const float* edge_b    = (const float*)d_in[5];
    const float* conv_w    = (const float*)d_in[6];
    const float* conv_b    = (const float*)d_in[7];
    const float* mlp_w1    = (const float*)d_in[8];
    const float* mlp_b1    = (const float*)d_in[9];
    const float* mlp_w2    = (const float*)d_in[10];
    const float* mlp_b2    = (const float*)d_in[11];
    const float* eps       = (const float*)d_in[12];
    const float* bn_gamma  = (const float*)d_in[13];
    const float* bn_beta   = (const float*)d_in[14];
    const float* att_w1    = (const float*)d_in[15];
    const float* att_b1    = (const float*)d_in[16];
    const float* att_w2    = (const float*)d_in[17];
    const float* att_b2    = (const float*)d_in[18];
    const int*   edge_index= (const int*)d_in[19];
    const int*   batch     = (const int*)d_in[20];
    float* out = (float*)d_out;
    (void)bn_beta;   // cancels exactly under PairNorm centering

    const int* src = edge_index;
    const int* dst = edge_index + NEDGES;

    const int HG_SMEM_256 = 2 * HA_TILE_BYTES + 2 * 32 * (256 + 4) * 4;  // 103424
    const int HG_SMEM_128 = 2 * HA_TILE_BYTES + 2 * 32 * (128 + 4) * 4;  // 70656

    cudaFuncSetAttribute(tf32_gemm_h, cudaFuncAttributeMaxDynamicSharedMemorySize, GEMM_SMEM_BYTES);
    cudaFuncSetAttribute(hgemm<1, 256>, cudaFuncAttributeMaxDynamicSharedMemorySize, HG_SMEM_256);
    cudaFuncSetAttribute(hgemm<2, 256>, cudaFuncAttributeMaxDynamicSharedMemorySize, HG_SMEM_256);
    cudaFuncSetAttribute(hgemm<3, 128>, cudaFuncAttributeMaxDynamicSharedMemorySize, HG_SMEM_128);

    float *p_stats, *p_gsum, *p_gsq, *p_sc, *p_cnt, *p_wexp, *p_wsum, *p_wf;
    __half *p_hh0, *p_hh1, *p_zh, *p_aeffh, *p_tmph;
    __half2 *p_w1p, *p_w2p, *p_w1a;
    int *p_deg, *p_rowstart, *p_cursor, *p_eid, *p_csrc, *p_gstart;
    cudaGetSymbolAddress((void**)&p_hh0, g_hh0);
    cudaGetSymbolAddress((void**)&p_hh1, g_hh1);
    cudaGetSymbolAddress((void**)&p_zh, g_zh);
    cudaGetSymbolAddress((void**)&p_aeffh, g_aeffh);
    cudaGetSymbolAddress((void**)&p_tmph, g_tmph);
    cudaGetSymbolAddress((void**)&p_w1p, g_w1p);
    cudaGetSymbolAddress((void**)&p_w2p, g_w2p);
    cudaGetSymbolAddress((void**)&p_w1a, g_w1a);
    cudaGetSymbolAddress((void**)&p_stats, g_stats);
    cudaGetSymbolAddress((void**)&p_gsum, g_gsum);
    cudaGetSymbolAddress((void**)&p_gsq, g_gsq);
    cudaGetSymbolAddress((void**)&p_sc, g_sc);
    cudaGetSymbolAddress((void**)&p_cnt, g_cnt);
    cudaGetSymbolAddress((void**)&p_wexp, g_wexp);
    cudaGetSymbolAddress((void**)&p_wsum, g_wsum);
    cudaGetSymbolAddress((void**)&p_wf, g_wf);
    cudaGetSymbolAddress((void**)&p_deg, g_deg);
    cudaGetSymbolAddress((void**)&p_rowstart, g_rowstart);
    cudaGetSymbolAddress((void**)&p_cursor, g_cursor);
    cudaGetSymbolAddress((void**)&p_eid, g_csr_eid);
    cudaGetSymbolAddress((void**)&p_csrc, g_csr_src);
    cudaGetSymbolAddress((void**)&p_gstart, g_gstart);

    // ----- CSR build
    cudaMemsetAsync(p_deg, 0, NNODES * sizeof(int));
    deg_kernel<<<(NEDGES + 255) / 256, 256>>>(dst, p_deg);
    csr_scan_kernel<<<1, 1024>>>(p_deg, p_rowstart, p_cursor);
    csr_fill_kernel<<<(NEDGES + 255) / 256, 256>>>(src, dst, p_cursor, p_eid, p_csrc);

    // ----- graph ranges + counts
    cudaMemsetAsync(p_gstart, 0x7F, (NGRAPH + 1) * sizeof(int));
    gstart_min_kernel<<<(NNODES + 255) / 256, 256>>>(batch, p_gstart);
    gstart_fix_kernel<<<1, 1024>>>(p_gstart, p_cnt);

    // ----- weight prep
    wfuse_kernel<<<dim3(NLAYER, 7), HID>>>(edge_w, edge_b, conv_w, conv_b, p_wf);
    wpack_kernel<<<(NLAYER * 128 * 256) / 256, 256>>>(mlp_w1, mlp_w2, p_w1p, p_w2p);
    wpack_att_kernel<<<(128 * 128) / 256, 256>>>(att_w1, p_w1a);

    // ----- node embedding (tf32, half output)
    {
        dim3 grid(HID / 128, (NNODES + 127) / 128);
        tf32_gemm_h<<<grid, 256, GEMM_SMEM_BYTES>>>(NNODES, HID, NODE_F, x, node_w,
                                                    node_b, p_hh0);
    }

    __half* h_cur = p_hh0;
    __half* h_nxt = p_hh1;
    dim3 hgrid(2, (NNODES + 127) / 128);

    for (int i = 0; i < NLAYER; i++) {
        gine_gather_fused<<<1024, 256>>>(
            h_cur, edge_attr, p_rowstart, p_eid, p_csrc,
            p_wf + (size_t)i * 7 * HID, eps + i, p_aeffh);

        hgemm<1, 256><<<hgrid, 256, HG_SMEM_256>>>(
            NNODES, p_aeffh, p_w1p + (size_t)i * 32768,
            mlp_b1 + (size_t)i * HID, p_tmph);
        hgemm<2, 256><<<hgrid, 256, HG_SMEM_256>>>(
            NNODES, p_tmph, p_w2p + (size_t)i * 32768,
            mlp_b2 + (size_t)i * HID, p_zh);

        cudaMemsetAsync(p_stats, 0, 2 * HID * sizeof(float));
        graph_stats_kernel<<<NGRAPH, HID>>>(p_zh, p_gstart, p_gsum, p_gsq, p_stats);
        graph_msq_kernel<<<NGRAPH, HID>>>(p_stats, bn_gamma + (size_t)i * HID,
                                          p_cnt, p_gsum, p_gsq, p_sc);
        final_norm_kernel<<<NNODES, HID>>>(p_zh, p_stats, bn_gamma + (size_t)i * HID,
                                           p_gsum, p_sc, batch, h_nxt);

        __half* t = h_cur; h_cur = h_nxt; h_nxt = t;
    }

    // attention hidden: s1 = tanh(h @ att_w1 + att_b1)  (fp16, half out, N=128)
    {
        dim3 agrid(1, (NNODES + 127) / 128);
        hgemm<3, 128><<<agrid, 256, HG_SMEM_128>>>(NNODES, h_cur, p_w1a, att_b1, p_tmph);
    }

    cudaMemsetAsync(p_wsum, 0, NGRAPH * sizeof(float));
    attn_score_kernel<<<(NNODES * 32 + 255) / 256, 256>>>(p_tmph, att_w2, att_b2, batch, p_wexp, p_wsum);

    pool_graph_kernel<<<NGRAPH, HID>>>(h_cur, p_wexp, p_wsum, p_gstart, p_cnt, out);

    (void)in_sizes; (void)n_in; (void)out_size;
}

// round 8
// speedup vs baseline: 4.9951x; 1.0361x over previous
#include <cuda_runtime.h>
#include <cuda_fp16.h>
#include <math.h>
#include <stdint.h>

#define NNODES 100000
#define NEDGES 320000
#define NGRAPH 2048
#define HID    256
#define EDIM   128
#define NODE_F 48
#define EDGE_F 6
#define NLAYER 8

// ---------------- scratch (device globals) ----------------------------------
__device__ __half  g_hh0[(size_t)NNODES * HID];
__device__ __half  g_hh1[(size_t)NNODES * HID];
__device__ __half  g_zh [(size_t)NNODES * HID];
__device__ __half  g_aeffh[(size_t)NNODES * HID];
__device__ __half  g_s1h [(size_t)NNODES * EDIM];
__device__ __half2 g_w1p[(size_t)NLAYER * (HID / 2) * HID];
__device__ __half2 g_w2p[(size_t)NLAYER * (HID / 2) * HID];
__device__ __half2 g_w1a[(size_t)(HID / 2) * EDIM];
__device__ float   g_stats[2 * HID];
__device__ float   g_gsum[(size_t)NGRAPH * HID];
__device__ float   g_gsq [(size_t)NGRAPH * HID];
__device__ float   g_sc  [NGRAPH];
__device__ float   g_cnt [NGRAPH];
__device__ float   g_wexp[NNODES];
__device__ float   g_wsum[NGRAPH];
__device__ float   g_wf  [(size_t)NLAYER * 7 * HID];
__device__ int     g_deg [NNODES];
__device__ int     g_rowstart[NNODES + 1];
__device__ int     g_cursor[NNODES];
__device__ int     g_csr_eid[NEDGES];
__device__ int     g_csr_src[NEDGES];
__device__ int     g_gstart[NGRAPH + 1];

// ---------------- common helpers ---------------------------------------------
__device__ __forceinline__ uint32_t f2tf32(float x) {
    uint32_t r;
    asm volatile("cvt.rna.tf32.f32 %0, %1;" : "=r"(r) : "f"(x));
    return r;
}
__device__ __forceinline__ void cp16s(uint32_t d, const void* src, bool pred) {
    int sz = pred ? 16 : 0;
    asm volatile("cp.async.cg.shared.global [%0], [%1], 16, %2;" :: "r"(d), "l"(src), "r"(sz));
}
__device__ __forceinline__ void cp_commit() { asm volatile("cp.async.commit_group;"); }
template <int Np>
__device__ __forceinline__ void cp_wait() { asm volatile("cp.async.wait_group %0;" :: "n"(Np)); }
__device__ __forceinline__ void mma_f16(float* c, const uint32_t* a, const uint32_t* b) {
    asm volatile(
        "mma.sync.aligned.m16n8k16.row.col.f32.f16.f16.f32 "
        "{%0,%1,%2,%3}, {%4,%5,%6,%7}, {%8,%9}, {%0,%1,%2,%3};"
        : "+f"(c[0]), "+f"(c[1]), "+f"(c[2]), "+f"(c[3])
        : "r"(a[0]), "r"(a[1]), "r"(a[2]), "r"(a[3]), "r"(b[0]), "r"(b[1]));
}
__device__ __forceinline__ void ldsm4(uint32_t* r, uint32_t addr) {
    asm volatile("ldmatrix.sync.aligned.m8n8.x4.shared.b16 {%0,%1,%2,%3}, [%4];"
                 : "=r"(r[0]), "=r"(r[1]), "=r"(r[2]), "=r"(r[3]) : "r"(addr));
}

extern __shared__ char smemc[];

// ===================== fused MLP: z = (relu(A@W1+b1))@W2 + b2 =================
// A [M,256] half. W1p/W2p [128][256] half2 k-pair packed. 512 threads, 1 CTA/SM.
#define FA_STRIDE 72                            // halves (64 + 8 pad)
#define FA_TILE_BYTES (128 * FA_STRIDE * 2)     // 18432
#define FB2_STRIDE 260                          // half2 per pair-row (256 + 4)
#define FB_TILE2 (32 * FB2_STRIDE)              // 8320 half2
#define FTMP_STRIDE 264                         // halves (256 + 8 pad)
#define OFF_B (2 * FA_TILE_BYTES)               // 36864
#define OFF_TMP (OFF_B + 2 * FB_TILE2 * 4)      // 103424
#define FUSED_SMEM (OFF_TMP + 128 * FTMP_STRIDE * 2)  // 171008

__global__ __launch_bounds__(512, 1) void fused_mlp(
    int M, const __half* __restrict__ A,
    const __half2* __restrict__ W1p, const __half2* __restrict__ W2p,
    const float* __restrict__ b1, const float* __restrict__ b2,
    __half* __restrict__ Z)
{
    uint32_t sb = (uint32_t)__cvta_generic_to_shared(smemc);
    const __half2* hB = (const __half2*)(smemc + OFF_B);
    __half* tmp = (__half*)(smemc + OFF_TMP);
    uint32_t sbT = sb + OFF_TMP;

    const int tid = threadIdx.x;
    const int warp = tid >> 5;
    const int lane = tid & 31;
    const int g = lane >> 2;
    const int tq = lane & 3;
    const int m0 = blockIdx.x * 128;
    const int wm = (warp & 3) * 32;
    const int wn = (warp >> 2) * 64;
    const int lrow = ((lane >> 3) & 1) * 8 + (lane & 7);
    const int lcol = (lane >> 4) * 8;

    float acc[2][8][4];
#pragma unroll
    for (int i = 0; i < 2; i++)
#pragma unroll
        for (int j = 0; j < 8; j++)
#pragma unroll
            for (int r = 0; r < 4; r++) acc[i][j][r] = 0.0f;

    auto fillA = [&](int buf, int k0) {
#pragma unroll
        for (int it = 0; it < 2; it++) {
            int chunk = tid + it * 512;           // 1024 x 16B
            int r = chunk >> 3, c = (chunk & 7) * 8;
            bool p = (m0 + r) < M;
            cp16s(sb + buf * FA_TILE_BYTES + (r * FA_STRIDE + c) * 2,
                  A + (size_t)(p ? m0 + r : 0) * 256 + k0 + c, p);
        }
    };
    auto fillB = [&](int buf, int k0, const __half2* W) {
#pragma unroll
        for (int it = 0; it < 4; it++) {
            int chunk = tid + it * 512;           // 2048 x 16B
            int pr = chunk >> 6, c2 = (chunk & 63) * 4;
            cp16s(sb + OFF_B + (buf * FB_TILE2 + pr * FB2_STRIDE + c2) * 4,
                  W + (size_t)((k0 >> 1) + pr) * 256 + c2, true);
        }
    };

    // ---------------- phase 1: acc = A @ W1
    fillA(0, 0);
    fillB(0, 0, W1p);
    cp_commit();

    int buf = 0;
#pragma unroll 1
    for (int i = 0; i < 4; i++) {
        if (i < 3) {
            fillA(buf ^ 1, (i + 1) * 64);
            fillB(buf ^ 1, (i + 1) * 64, W1p);
        } else {
            fillB(buf ^ 1, 0, W2p);               // prefetch W2 chunk 0
        }
        cp_commit();
        cp_wait<1>();
        __syncthreads();

        uint32_t abase = sb + buf * FA_TILE_BYTES;
        const __half2* Bb = hB + buf * FB_TILE2;
#pragma unroll
        for (int kk = 0; kk < 4; kk++) {
            uint32_t af[2][4];
#pragma unroll
            for (int mi = 0; mi < 2; mi++)
                ldsm4(af[mi], abase + ((wm + mi * 16 + lrow) * FA_STRIDE + kk * 16 + lcol) * 2);
            uint32_t bf[8][2];
#pragma unroll
            for (int ni = 0; ni < 8; ni++) {
                const __half2* p = Bb + (kk * 8 + tq) * FB2_STRIDE + wn + ni * 8 + g;
                bf[ni][0] = *(const uint32_t*)(p);
                bf[ni][1] = *(const uint32_t*)(p + 4 * FB2_STRIDE);
            }
#pragma unroll
            for (int mi = 0; mi < 2; mi++)
#pragma unroll
                for (int ni = 0; ni < 8; ni++)
                    mma_f16(acc[mi][ni], af[mi], bf[ni]);
        }
        __syncthreads();
        buf ^= 1;
    }

    // ---------------- phase 1 epilogue: tmp = relu(acc + b1) (half, smem)
#pragma unroll
    for (int mi = 0; mi < 2; mi++) {
        int r0 = wm + mi * 16 + g;
        int r1 = r0 + 8;
#pragma unroll
        for (int ni = 0; ni < 8; ni++) {
            int col = wn + ni * 8 + tq * 2;
            float c0 = __ldg(b1 + col);
            float c1 = __ldg(b1 + col + 1);
            float v0 = fmaxf(acc[mi][ni][0] + c0, 0.f);
            float v1 = fmaxf(acc[mi][ni][1] + c1, 0.f);
            float v2 = fmaxf(acc[mi][ni][2] + c0, 0.f);
            float v3 = fmaxf(acc[mi][ni][3] + c1, 0.f);
            *(__half2*)(tmp + r0 * FTMP_STRIDE + col) = __floats2half2_rn(v0, v1);
            *(__half2*)(tmp + r1 * FTMP_STRIDE + col) = __floats2half2_rn(v2, v3);
            acc[mi][ni][0] = 0.f; acc[mi][ni][1] = 0.f;
            acc[mi][ni][2] = 0.f; acc[mi][ni][3] = 0.f;
        }
    }

    // ---------------- phase 2: acc = tmp @ W2
#pragma unroll 1
    for (int i = 0; i < 4; i++) {
        if (i < 3) {
            fillB(buf ^ 1, (i + 1) * 64, W2p);
            cp_commit();
            cp_wait<1>();
        } else {
            cp_wait<0>();
        }
        __syncthreads();   // first iteration also orders tmp writes before reads

        const __half2* Bb = hB + buf * FB_TILE2;
#pragma unroll
        for (int kk = 0; kk < 4; kk++) {
            uint32_t af[2][4];
#pragma unroll
            for (int mi = 0; mi < 2; mi++)
                ldsm4(af[mi], sbT + ((wm + mi * 16 + lrow) * FTMP_STRIDE + i * 64 + kk * 16 + lcol) * 2);
            uint32_t bf[8][2];
#pragma unroll
            for (int ni = 0; ni < 8; ni++) {
                const __half2* p = Bb + (kk * 8 + tq) * FB2_STRIDE + wn + ni * 8 + g;
                bf[ni][0] = *(const uint32_t*)(p);
                bf[ni][1] = *(const uint32_t*)(p + 4 * FB2_STRIDE);
            }
#pragma unroll
            for (int mi = 0; mi < 2; mi++)
#pragma unroll
                for (int ni = 0; ni < 8; ni++)
                    mma_f16(acc[mi][ni], af[mi], bf[ni]);
        }
        __syncthreads();
        buf ^= 1;
    }

    // ---------------- phase 2 epilogue: Z = acc + b2 (half, global)
#pragma unroll
    for (int mi = 0; mi < 2; mi++) {
        int r0 = m0 + wm + mi * 16 + g;
        int r1 = r0 + 8;
#pragma unroll
        for (int ni = 0; ni < 8; ni++) {
            int col = wn + ni * 8 + tq * 2;
            float c0 = __ldg(b2 + col);
            float c1 = __ldg(b2 + col + 1);
            if (r0 < M) *(__half2*)(Z + (size_t)r0 * 256 + col) =
                __floats2half2_rn(acc[mi][ni][0] + c0, acc[mi][ni][1] + c1);
            if (r1 < M) *(__half2*)(Z + (size_t)r1 * 256 + col) =
                __floats2half2_rn(acc[mi][ni][2] + c0, acc[mi][ni][3] + c1);
        }
    }
}

// ===================== fp16 GEMM (attention, WN=128, tanh) ====================
#define HA_STRIDE 72
#define HA_TILE_BYTES (128 * HA_STRIDE * 2)

__global__ __launch_bounds__(256, 2) void hgemm_att(
    int M, const __half* __restrict__ A, const __half2* __restrict__ Bp,
    const float* __restrict__ bias, __half* __restrict__ Ch)
{
    constexpr int WN = 128;
    constexpr int HB2_STRIDE = WN + 4;
    constexpr int HB_TILE2 = 32 * HB2_STRIDE;
    const __half2* hB = (const __half2*)(smemc + 2 * HA_TILE_BYTES);
    uint32_t sb = (uint32_t)__cvta_generic_to_shared(smemc);
    uint32_t sbB = sb + 2 * HA_TILE_BYTES;

    const int tid = threadIdx.x;
    const int warp = tid >> 5;
    const int lane = tid & 31;
    const int g = lane >> 2;
    const int tq = lane & 3;
    const int m0 = blockIdx.y * 128;
    const int wm = (warp >> 1) * 32;
    const int wn = (warp & 1) * 64;
    const int lrow = ((lane >> 3) & 1) * 8 + (lane & 7);
    const int lcol = (lane >> 4) * 8;

    float acc[2][8][4];
#pragma unroll
    for (int i = 0; i < 2; i++)
#pragma unroll
        for (int j = 0; j < 8; j++)
#pragma unroll
            for (int r = 0; r < 4; r++) acc[i][j][r] = 0.0f;

    auto fillA = [&](int buf, int k0) {
#pragma unroll
        for (int it = 0; it < 4; it++) {
            int chunk = tid + it * 256;
            int r = chunk >> 3, c = (chunk & 7) * 8;
            bool p = (m0 + r) < M;
            cp16s(sb + buf * HA_TILE_BYTES + (r * HA_STRIDE + c) * 2,
                  A + (size_t)(p ? m0 + r : 0) * 256 + k0 + c, p);
        }
    };
    auto fillB = [&](int buf, int k0) {
#pragma unroll
        for (int it = 0; it < 4; it++) {
            int chunk = tid + it * 256;
            int pr = chunk >> 5, c2 = (chunk & 31) * 4;
            cp16s(sbB + (buf * HB_TILE2 + pr * HB2_STRIDE + c2) * 4,
                  Bp + (size_t)((k0 >> 1) + pr) * WN + c2, true);
        }
    };

    fillA(0, 0);
    fillB(0, 0);
    cp_commit();

    int buf = 0;
#pragma unroll 1
    for (int i = 0; i < 4; i++) {
        if (i + 1 < 4) {
            fillA(buf ^ 1, (i + 1) * 64);
            fillB(buf ^ 1, (i + 1) * 64);
            cp_commit();
            cp_wait<1>();
        } else {
            cp_wait<0>();
        }
        __syncthreads();

        uint32_t abase = sb + buf * HA_TILE_BYTES;
        const __half2* Bb = hB + buf * HB_TILE2;
#pragma unroll
        for (int kk = 0; kk < 4; kk++) {
            uint32_t af[2][4];
#pragma unroll
            for (int mi = 0; mi < 2; mi++)
                ldsm4(af[mi], abase + ((wm + mi * 16 + lrow) * HA_STRIDE + kk * 16 + lcol) * 2);
            uint32_t bf[8][2];
#pragma unroll
            for (int ni = 0; ni < 8; ni++) {
                const __half2* p = Bb + (kk * 8 + tq) * HB2_STRIDE + wn + ni * 8 + g;
                bf[ni][0] = *(const uint32_t*)(p);
                bf[ni][1] = *(const uint32_t*)(p + 4 * HB2_STRIDE);
            }
#pragma unroll
            for (int mi = 0; mi < 2; mi++)
#pragma unroll
                for (int ni = 0; ni < 8; ni++)
                    mma_f16(acc[mi][ni], af[mi], bf[ni]);
        }
        __syncthreads();
        buf ^= 1;
    }

#pragma unroll
    for (int mi = 0; mi < 2; mi++) {
        int r0 = m0 + wm + mi * 16 + g;
        int r1 = r0 + 8;
#pragma unroll
        for (int ni = 0; ni < 8; ni++) {
            int col = wn + ni * 8 + tq * 2;
            float b0 = __ldg(bias + col);
            float b1 = __ldg(bias + col + 1);
            float v0 = tanhf(acc[mi][ni][0] + b0);
            float v1 = tanhf(acc[mi][ni][1] + b1);
            float v2 = tanhf(acc[mi][ni][2] + b0);
            float v3 = tanhf(acc[mi][ni][3] + b1);
            if (r0 < M) *(__half2*)(Ch + (size_t)r0 * WN + col) = __floats2half2_rn(v0, v1);
            if (r1 < M) *(__half2*)(Ch + (size_t)r1 * WN + col) = __floats2half2_rn(v2, v3);
        }
    }
}

// ---------------- weight packs ---------------------------------------------------
__global__ void wpack_kernel(const float* __restrict__ w1, const float* __restrict__ w2,
                             __half2* __restrict__ w1p, __half2* __restrict__ w2p)
{
    int idx = blockIdx.x * 256 + threadIdx.x;
    int l = idx >> 15;
    int rem = idx & 32767;
    int p = rem >> 8;
    int n = rem & 255;
    size_t base = (size_t)l * 65536 + (size_t)(2 * p) * 256 + n;
    w1p[idx] = __floats2half2_rn(__ldg(w1 + base), __ldg(w1 + base + 256));
    w2p[idx] = __floats2half2_rn(__ldg(w2 + base), __ldg(w2 + base + 256));
}
__global__ void wpack_att_kernel(const float* __restrict__ w, __half2* __restrict__ wp)
{
    int idx = blockIdx.x * 256 + threadIdx.x;
    int p = idx >> 7;
    int n = idx & 127;
    size_t base = (size_t)(2 * p) * 128 + n;
    wp[idx] = __floats2half2_rn(__ldg(w + base), __ldg(w + base + 128));
}

// ===================== mma.sync TF32 GEMM (node embed) ========================
#define GA_STRIDE 36
#define GB_STRIDE 132
#define A_TILE_W (128 * GA_STRIDE)
#define B_TILE_W (32 * GB_STRIDE)
#define GEMM_SMEM_BYTES ((2 * A_TILE_W + 2 * B_TILE_W) * 4)

__device__ __forceinline__ void cp16(float* dst, const float* src, bool pred) {
    cp16s((uint32_t)__cvta_generic_to_shared(dst), src, pred);
}
__device__ __forceinline__ void mma_tf32(float* c, const uint32_t* a, const uint32_t* b) {
    asm volatile(
        "mma.sync.aligned.m16n8k8.row.col.f32.tf32.tf32.f32 "
        "{%0,%1,%2,%3}, {%4,%5,%6,%7}, {%8,%9}, {%0,%1,%2,%3};"
        : "+f"(c[0]), "+f"(c[1]), "+f"(c[2]), "+f"(c[3])
        : "r"(a[0]), "r"(a[1]), "r"(a[2]), "r"(a[3]), "r"(b[0]), "r"(b[1]));
}

__global__ __launch_bounds__(256, 2) void tf32_gemm_h(
    int M, int N, int K,
    const float* __restrict__ A, const float* __restrict__ B,
    const float* __restrict__ bias, __half* __restrict__ Chh)
{
    float* sm = (float*)smemc;
    float* As = sm;
    float* Bs = sm + 2 * A_TILE_W;

    const int tid = threadIdx.x;
    const int warp = tid >> 5;
    const int lane = tid & 31;
    const int g = lane >> 2;
    const int tq = lane & 3;
    const int m0 = blockIdx.y * 128;
    const int n0 = blockIdx.x * 128;
    const int wm = (warp >> 1) * 32;
    const int wn = (warp & 1) * 64;

    float acc[2][8][4];
#pragma unroll
    for (int i = 0; i < 2; i++)
#pragma unroll
        for (int j = 0; j < 8; j++)
#pragma unroll
            for (int r = 0; r < 4; r++) acc[i][j][r] = 0.0f;

    const int arow = tid >> 3;
    const int ac4 = tid & 7;
    const int brow = tid >> 5;
    const int bc4 = tid & 31;
    const int nk = (K + 31) / 32;

    {
#pragma unroll
        for (int it = 0; it < 4; it++) {
            int row = arow + it * 32;
            int gm = m0 + row;
            int gk = ac4 * 4;
            bool p = (gm < M) && (gk < K);
            const float* src = A + (size_t)(p ? gm : 0) * K + (p ? gk : 0);
            cp16(As + row * GA_STRIDE + ac4 * 4, src, p);
        }
#pragma unroll
        for (int it = 0; it < 4; it++) {
            int row = brow + it * 8;
            bool p = (row < K);
            const float* src = B + (size_t)(p ? row : 0) * N + n0 + bc4 * 4;
            cp16(Bs + row * GB_STRIDE + bc4 * 4, src, p);
        }
        cp_commit();
    }

    int buf = 0;
    for (int i = 0; i < nk; i++) {
        if (i + 1 < nk) {
            const int kc = i + 1;
            float* Ad = As + (buf ^ 1) * A_TILE_W;
            float* Bd = Bs + (buf ^ 1) * B_TILE_W;
#pragma unroll
            for (int it = 0; it < 4; it++) {
                int row = arow + it * 32;
                int gm = m0 + row;
                int gk = kc * 32 + ac4 * 4;
                bool p = (gm < M) && (gk < K);
                const float* src = A + (size_t)(p ? gm : 0) * K + (p ? gk : 0);
                cp16(Ad + row * GA_STRIDE + ac4 * 4, src, p);
            }
#pragma unroll
            for (int it = 0; it < 4; it++) {
                int row = brow + it * 8;
                int gk = kc * 32 + row;
                bool p = (gk < K);
                const float* src = B + (size_t)(p ? gk : 0) * N + n0 + bc4 * 4;
                cp16(Bd + row * GB_STRIDE + bc4 * 4, src, p);
            }
            cp_commit();
            cp_wait<1>();
        } else {
            cp_wait<0>();
        }
        __syncthreads();

        const float* Ab = As + buf * A_TILE_W;
        const float* Bb = Bs + buf * B_TILE_W;
#pragma unroll
        for (int kk = 0; kk < 4; kk++) {
            const int k = kk * 8;
            uint32_t af[2][4];
#pragma unroll
            for (int mi = 0; mi < 2; mi++) {
                const float* p = Ab + (wm + mi * 16 + g) * GA_STRIDE + k + tq;
                af[mi][0] = f2tf32(p[0]);
                af[mi][1] = f2tf32(p[8 * GA_STRIDE]);
                af[mi][2] = f2tf32(p[4]);
                af[mi][3] = f2tf32(p[8 * GA_STRIDE + 4]);
            }
            uint32_t bf[8][2];
#pragma unroll
            for (int ni = 0; ni < 8; ni++) {
                const float* p = Bb + (k + tq) * GB_STRIDE + wn + ni * 8 + g;
                bf[ni][0] = f2tf32(p[0]);
                bf[ni][1] = f2tf32(p[4 * GB_STRIDE]);
            }
#pragma unroll
            for (int mi = 0; mi < 2; mi++)
#pragma unroll
                for (int ni = 0; ni < 8; ni++)
                    mma_tf32(acc[mi][ni], af[mi], bf[ni]);
        }
        __syncthreads();
        buf ^= 1;
    }

#pragma unroll
    for (int mi = 0; mi < 2; mi++) {
        int r0 = m0 + wm + mi * 16 + g;
        int r1 = r0 + 8;
#pragma unroll
        for (int ni = 0; ni < 8; ni++) {
            int col = n0 + wn + ni * 8 + tq * 2;
            float b0 = __ldg(bias + col);
            float b1 = __ldg(bias + col + 1);
            if (r0 < M) *(__half2*)(Chh + (size_t)r0 * N + col) =
                __floats2half2_rn(acc[mi][ni][0] + b0, acc[mi][ni][1] + b1);
            if (r1 < M) *(__half2*)(Chh + (size_t)r1 * N + col) =
                __floats2half2_rn(acc[mi][ni][2] + b0, acc[mi][ni][3] + b1);
        }
    }
}

// ---------------- fused edge weights ------------------------------------------
__global__ void wfuse_kernel(const float* __restrict__ edge_w,
                             const float* __restrict__ edge_b,
                             const float* __restrict__ conv_w,
                             const float* __restrict__ conv_b,
                             float* __restrict__ wf)
{
    int layer = blockIdx.x;
    int k = blockIdx.y;
    int c = threadIdx.x;
    const float* cw = conv_w + (size_t)layer * EDIM * HID;
    float s = 0.f;
    if (k < EDGE_F) {
        for (int j = 0; j < EDIM; j++)
            s = fmaf(__ldg(edge_w + k * EDIM + j), __ldg(cw + (size_t)j * HID + c), s);
    } else {
        for (int j = 0; j < EDIM; j++)
            s = fmaf(__ldg(edge_b + j), __ldg(cw + (size_t)j * HID + c), s);
        s += __ldg(conv_b + (size_t)layer * HID + c);
    }
    wf[((size_t)layer * 7 + k) * HID + c] = s;
}

// ---------------- CSR build ----------------------------------------------------
__global__ void deg_kernel(const int* __restrict__ dst, int* __restrict__ deg)
{
    int e = blockIdx.x * blockDim.x + threadIdx.x;
    if (e < NEDGES) atomicAdd(&deg[__ldg(dst + e)], 1);
}

__global__ void csr_scan_kernel(const int* __restrict__ deg,
                                int* __restrict__ rowstart,
                                int* __restrict__ cursor)
{
    const int CH = (NNODES + 1023) / 1024;
    __shared__ int ssum[1024];
    int t = threadIdx.x;
    int lo = t * CH;
    int hi = min(lo + CH, NNODES);
    int s = 0;
    for (int i = lo; i < hi; i++) s += deg[i];
    ssum[t] = s;
    __syncthreads();
    for (int off = 1; off < 1024; off <<= 1) {
        int v = (t >= off) ? ssum[t - off] : 0;
        __syncthreads();
        ssum[t] += v;
        __syncthreads();
    }
    int run = ssum[t] - s;
    for (int i = lo; i < hi; i++) {
        rowstart[i] = run;
        cursor[i] = run;
        run += deg[i];
    }
    if (hi == NNODES) rowstart[NNODES] = run;
}

__global__ void csr_fill_kernel(const int* __restrict__ src,
                                const int* __restrict__ dst,
                                int* __restrict__ cursor,
                                int* __restrict__ csr_eid,
                                int* __restrict__ csr_src)
{
    int e = blockIdx.x * blockDim.x + threadIdx.x;
    if (e >= NEDGES) return;
    int d = __ldg(dst + e);
    int p = atomicAdd(&cursor[d], 1);
    csr_eid[p] = e;
    csr_src[p] = __ldg(src + e);
}

// ---------------- graph ranges --------------------------------------------------
__global__ void gstart_min_kernel(const int* __restrict__ batch, int* __restrict__ gstart)
{
    int n = blockIdx.x * blockDim.x + threadIdx.x;
    if (n < NNODES) atomicMin(&gstart[__ldg(batch + n)], n);
}

__global__ void gstart_fix_kernel(int* __restrict__ gstart, float* __restrict__ cnt)
{
    __shared__ int sg[NGRAPH + 1];
    int t = threadIdx.x;
    for (int i = t; i <= NGRAPH; i += 1024) sg[i] = gstart[i];
    __syncthreads();
    if (t == 0) {
        sg[NGRAPH] = NNODES;
        for (int g2 = NGRAPH - 1; g2 >= 0; g2--)
            if (sg[g2] > sg[g2 + 1]) sg[g2] = sg[g2 + 1];
    }
    __syncthreads();
    for (int i = t; i <= NGRAPH; i += 1024) gstart[i] = sg[i];
    for (int i = t; i < NGRAPH; i += 1024)
        cnt[i] = fmaxf((float)(sg[i + 1] - sg[i]), 1.0f);
}

// ---------------- GINE gather (also zeroes BN stats from block 0) --------------
__device__ __forceinline__ float4 h4load(const uint2* hp, int idx) {
    uint2 u = __ldg(hp + idx);
    float2 f0 = __half22float2(*(__half2*)&u.x);
    float2 f1 = __half22float2(*(__half2*)&u.y);
    return make_float4(f0.x, f0.y, f1.x, f1.y);
}

__global__ __launch_bounds__(256) void gine_gather_fused(
    const __half* __restrict__ h,
    const float* __restrict__ ea,
    const int* __restrict__ rowstart,
    const int* __restrict__ csr_eid,
    const int* __restrict__ csr_src,
    const float* __restrict__ wf,
    const float* __restrict__ eps_ptr,
    __half* __restrict__ aeffh,
    float* __restrict__ stats)
{
    if (blockIdx.x == 0) {
        stats[threadIdx.x] = 0.f;
        stats[256 + threadIdx.x] = 0.f;
    }

    const int lane = threadIdx.x & 31;
    const int warp_g = (blockIdx.x * blockDim.x + threadIdx.x) >> 5;
    const int nwarps = (gridDim.x * blockDim.x) >> 5;
    const float alpha = 1.0f + __ldg(eps_ptr);

    float4 w0[EDGE_F], w1[EDGE_F];
#pragma unroll
    for (int k = 0; k < EDGE_F; k++) {
        w0[k] = __ldg((const float4*)(wf + k * HID) + lane);
        w1[k] = __ldg((const float4*)(wf + k * HID) + 32 + lane);
    }
    float4 bf0 = __ldg((const float4*)(wf + EDGE_F * HID) + lane);
    float4 bf1 = __ldg((const float4*)(wf + EDGE_F * HID) + 32 + lane);

    for (int n = warp_g; n < NNODES; n += nwarps) {
        const uint2* hn = (const uint2*)(h + (size_t)n * HID);
        float4 a0 = h4load(hn, lane);
        float4 a1 = h4load(hn, 32 + lane);
        a0.x *= alpha; a0.y *= alpha; a0.z *= alpha; a0.w *= alpha;
        a1.x *= alpha; a1.y *= alpha; a1.z *= alpha; a1.w *= alpha;

        int lo = __ldg(rowstart + n), hi = __ldg(rowstart + n + 1);
        for (int j = lo; j < hi; j++) {
            int eid = __ldg(csr_eid + j);
            int s = __ldg(csr_src + j);
            const float* er = ea + (size_t)eid * EDGE_F;
            float e0 = __ldg(er + 0), e1 = __ldg(er + 1), e2 = __ldg(er + 2);
            float e3 = __ldg(er + 3), e4 = __ldg(er + 4), e5 = __ldg(er + 5);

            float4 ee0 = bf0, ee1 = bf1;
            ee0.x = fmaf(e0, w0[0].x, ee0.x); ee0.y = fmaf(e0, w0[0].y, ee0.y);
            ee0.z = fmaf(e0, w0[0].z, ee0.z); ee0.w = fmaf(e0, w0[0].w, ee0.w);
            ee1.x = fmaf(e0, w1[0].x, ee1.x); ee1.y = fmaf(e0, w1[0].y, ee1.y);
            ee1.z = fmaf(e0, w1[0].z, ee1.z); ee1.w = fmaf(e0, w1[0].w, ee1.w);
            ee0.x = fmaf(e1, w0[1].x, ee0.x); ee0.y = fmaf(e1, w0[1].y, ee0.y);
            ee0.z = fmaf(e1, w0[1].z, ee0.z); ee0.w = fmaf(e1, w0[1].w, ee0.w);
            ee1.x = fmaf(e1, w1[1].x, ee1.x); ee1.y = fmaf(e1, w1[1].y, ee1.y);
            ee1.z = fmaf(e1, w1[1].z, ee1.z); ee1.w = fmaf(e1, w1[1].w, ee1.w);
            ee0.x = fmaf(e2, w0[2].x, ee0.x); ee0.y = fmaf(e2, w0[2].y, ee0.y);
            ee0.z = fmaf(e2, w0[2].z, ee0.z); ee0.w = fmaf(e2, w0[2].w, ee0.w);
            ee1.x = fmaf(e2, w1[2].x, ee1.x); ee1.y = fmaf(e2, w1[2].y, ee1.y);
            ee1.z = fmaf(e2, w1[2].z, ee1.z); ee1.w = fmaf(e2, w1[2].w, ee1.w);
            ee0.x = fmaf(e3, w0[3].x, ee0.x); ee0.y = fmaf(e3, w0[3].y, ee0.y);
            ee0.z = fmaf(e3, w0[3].z, ee0.z); ee0.w = fmaf(e3, w0[3].w, ee0.w);
            ee1.x = fmaf(e3, w1[3].x, ee1.x); ee1.y = fmaf(e3, w1[3].y, ee1.y);
            ee1.z = fmaf(e3, w1[3].z, ee1.z); ee1.w = fmaf(e3, w1[3].w, ee1.w);
            ee0.x = fmaf(e4, w0[4].x, ee0.x); ee0.y = fmaf(e4, w0[4].y, ee0.y);
            ee0.z = fmaf(e4, w0[4].z, ee0.z); ee0.w = fmaf(e4, w0[4].w, ee0.w);
            ee1.x = fmaf(e4, w1[4].x, ee1.x); ee1.y = fmaf(e4, w1[4].y, ee1.y);
            ee1.z = fmaf(e4, w1[4].z, ee1.z); ee1.w = fmaf(e4, w1[4].w, ee1.w);
            ee0.x = fmaf(e5, w0[5].x, ee0.x); ee0.y = fmaf(e5, w0[5].y, ee0.y);
            ee0.z = fmaf(e5, w0[5].z, ee0.z); ee0.w = fmaf(e5, w0[5].w, ee0.w);
            ee1.x = fmaf(e5, w1[5].x, ee1.x); ee1.y = fmaf(e5, w1[5].y, ee1.y);
            ee1.z = fmaf(e5, w1[5].z, ee1.z); ee1.w = fmaf(e5, w1[5].w, ee1.w);

            const uint2* hp = (const uint2*)(h + (size_t)s * HID);
            float4 h0 = h4load(hp, lane);
            float4 h1 = h4load(hp, 32 + lane);
            a0.x += fmaxf(h0.x + ee0.x, 0.f); a0.y += fmaxf(h0.y + ee0.y, 0.f);
            a0.z += fmaxf(h0.z + ee0.z, 0.f); a0.w += fmaxf(h0.w + ee0.w, 0.f);
            a1.x += fmaxf(h1.x + ee1.x, 0.f); a1.y += fmaxf(h1.y + ee1.y, 0.f);
            a1.z += fmaxf(h1.z + ee1.z, 0.f); a1.w += fmaxf(h1.w + ee1.w, 0.f);
        }
        __half2* ap = (__half2*)(aeffh + (size_t)n * HID);
        ap[lane * 2]          = __floats2half2_rn(a0.x, a0.y);
        ap[lane * 2 + 1]      = __floats2half2_rn(a0.z, a0.w);
        ap[64 + lane * 2]     = __floats2half2_rn(a1.x, a1.y);
        ap[64 + lane * 2 + 1] = __floats2half2_rn(a1.z, a1.w);
    }
}

// ---------------- per-graph stats + global BN stats ----------------------------
__global__ void graph_stats_kernel(const __half* __restrict__ zh,
                                   const int* __restrict__ gstart,
                                   float* __restrict__ gsum,
                                   float* __restrict__ gsq,
                                   float* __restrict__ stats)
{
    int g = blockIdx.x;
    int c = threadIdx.x;
    int lo = gstart[g], hi = gstart[g + 1];
    float s = 0.f, q = 0.f;
    for (int n = lo; n < hi; n++) {
        float v = __half2float(__ldg(zh + (size_t)n * HID + c));
        s += v;
        q = fmaf(v, v, q);
    }
    gsum[(size_t)g * HID + c] = s;
    gsq[(size_t)g * HID + c] = q;
    atomicAdd(&stats[c], s);
    atomicAdd(&stats[HID + c], q);
}

// ---------------- per-graph msq -> scale; gsum -> mean --------------------------
__global__ void graph_msq_kernel(const float* __restrict__ stats,
                                 const float* __restrict__ gamma,
                                 const float* __restrict__ cnt,
                                 float* __restrict__ gsum,
                                 const float* __restrict__ gsq,
                                 float* __restrict__ sc)
{
    __shared__ float red[HID];
    int g = blockIdx.x;
    int c = threadIdx.x;
    const float invN = 1.0f / (float)NNODES;
    float mu = __ldg(stats + c) * invN;
    float var = __ldg(stats + HID + c) * invN - mu * mu;
    float ac = __ldg(gamma + c) * rsqrtf(var + 1e-5f);
    float cg = cnt[g];
    size_t i = (size_t)g * HID + c;
    float S = gsum[i], Q = gsq[i];
    float m = S / cg;
    gsum[i] = m;
    red[c] = ac * ac * (Q - cg * m * m);
    __syncthreads();
    for (int o = HID / 2; o > 0; o >>= 1) {
        if (c < o) red[c] += red[c + o];
        __syncthreads();
    }
    if (c == 0) sc[g] = rsqrtf(1e-5f + red[0] / cg);
}

// ---------------- fused BN+PairNorm normalize + ReLU ----------------------------
__global__ void final_norm_kernel(const __half* __restrict__ zh,
                                  const float* __restrict__ stats,
                                  const float* __restrict__ gamma,
                                  const float* __restrict__ gmean,
                                  const float* __restrict__ sc,
                                  const int* __restrict__ batch,
                                  __half* __restrict__ houth)
{
    int r = blockIdx.x;
    int c = threadIdx.x;
    int g = __ldg(batch + r);
    const float invN = 1.0f / (float)NNODES;
    float mu = __ldg(stats + c) * invN;
    float var = __ldg(stats + HID + c) * invN - mu * mu;
    float ac = __ldg(gamma + c) * rsqrtf(var + 1e-5f);
    size_t i = (size_t)r * HID + c;
    float zv = __half2float(zh[i]);
    float v = ac * (zv - __ldg(gmean + (size_t)g * HID + c)) * __ldg(sc + g);
    houth[i] = __float2half(fmaxf(v, 0.f));
}

// ---------------- attention score (half s1) -------------------------------------
__global__ void attn_score_kernel(const __half* __restrict__ s1,
                                  const float* __restrict__ w2,
                                  const float* __restrict__ b2,
                                  const int* __restrict__ batch,
                                  float* __restrict__ wexp,
                                  float* __restrict__ wsum)
{
    int row = (blockIdx.x * blockDim.x + threadIdx.x) >> 5;
    int lane = threadIdx.x & 31;
    if (row >= NNODES) return;
    const __half2* s = (const __half2*)(s1 + (size_t)row * EDIM);
    float acc = 0.f;
#pragma unroll
    for (int k = lane; k < EDIM / 2; k += 32) {
        float2 f = __half22float2(__ldg(s + k));
        acc = fmaf(f.x, __ldg(w2 + 2 * k), acc);
        acc = fmaf(f.y, __ldg(w2 + 2 * k + 1), acc);
    }
#pragma unroll
    for (int o = 16; o > 0; o >>= 1) acc += __shfl_down_sync(0xffffffffu, acc, o);
    if (lane == 0) {
        float w = expf(acc + __ldg(b2));
        wexp[row] = w;
        atomicAdd(&wsum[__ldg(batch + row)], w);
    }
}

// ---------------- pooling (half h) ----------------------------------------------
__global__ void pool_graph_kernel(const __half* __restrict__ h,
                                  const float* __restrict__ wexp,
                                  const float* __restrict__ wsum,
                                  const int* __restrict__ gstart,
                                  const float* __restrict__ cnt,
                                  float* __restrict__ out)
{
    int g = blockIdx.x;
    int c = threadIdx.x;
    int lo = gstart[g], hi = gstart[g + 1];
    float inv_ws = 1.0f / (wsum[g] + 1e-8f);
    float s = 0.f, mx = 0.f, att = 0.f;
    for (int n = lo; n < hi; n++) {
        float v = __half2float(__ldg(h + (size_t)n * HID + c));
        float coeff = __ldg(wexp + n) * inv_ws;
        s += v;
        mx = fmaxf(mx, v);
        att = fmaf(v, coeff, att);
    }
    float* og = out + (size_t)g * (3 * HID);
    og[c] = s / cnt[g];
    og[HID + c] = mx;
    og[2 * HID + c] = att;
}

// ---------------- host launch --------------------------------------------------------
extern "C" void kernel_launch(void* const* d_in, const int* in_sizes, int n_in,
                              void* d_out, int out_size)
{
    const float* x         = (const float*)d_in[0];
    const float* edge_attr = (const float*)d_in[1];
    const float* node_w    = (const float*)d_in[2];
    const float* node_b    = (const float*)d_in[3];
    const float* edge_w    = (const float*)d_in[4];
    const float* edge_b    = (const float*)d_in[5];
    const float* conv_w    = (const float*)d_in[6];
    const float* conv_b    = (const float*)d_in[7];
    const float* mlp_w1    = (const float*)d_in[8];
    const float* mlp_b1    = (const float*)d_in[9];
    const float* mlp_w2    = (const float*)d_in[10];
    const float* mlp_b2    = (const float*)d_in[11];
    const float* eps       = (const float*)d_in[12];
    const float* bn_gamma  = (const float*)d_in[13];
    const float* bn_beta   = (const float*)d_in[14];
    const float* att_w1    = (const float*)d_in[15];
    const float* att_b1    = (const float*)d_in[16];
    const float* att_w2    = (const float*)d_in[17];
    const float* att_b2    = (const float*)d_in[18];
    const int*   edge_index= (const int*)d_in[19];
    const int*   batch     = (const int*)d_in[20];
    float* out = (float*)d_out;
    (void)bn_beta;   // cancels exactly under PairNorm centering

    const int* src = edge_index;
    const int* dst = edge_index + NEDGES;

    const int HG_SMEM_128 = 2 * HA_TILE_BYTES + 2 * 32 * (128 + 4) * 4;

    cudaFuncSetAttribute(tf32_gemm_h, cudaFuncAttributeMaxDynamicSharedMemorySize, GEMM_SMEM_BYTES);
    cudaFuncSetAttribute(fused_mlp, cudaFuncAttributeMaxDynamicSharedMemorySize, FUSED_SMEM);
    cudaFuncSetAttribute(hgemm_att, cudaFuncAttributeMaxDynamicSharedMemorySize, HG_SMEM_128);

    float *p_stats, *p_gsum, *p_gsq, *p_sc, *p_cnt, *p_wexp, *p_wsum, *p_wf;
    __half *p_hh0, *p_hh1, *p_zh, *p_aeffh, *p_s1h;
    __half2 *p_w1p, *p_w2p, *p_w1a;
    int *p_deg, *p_rowstart, *p_cursor, *p_eid, *p_csrc, *p_gstart;
    cudaGetSymbolAddress((void**)&p_hh0, g_hh0);
    cudaGetSymbolAddress((void**)&p_hh1, g_hh1);
    cudaGetSymbolAddress((void**)&p_zh, g_zh);
    cudaGetSymbolAddress((void**)&p_aeffh, g_aeffh);
    cudaGetSymbolAddress((void**)&p_s1h, g_s1h);
    cudaGetSymbolAddress((void**)&p_w1p, g_w1p);
    cudaGetSymbolAddress((void**)&p_w2p, g_w2p);
    cudaGetSymbolAddress((void**)&p_w1a, g_w1a);
    cudaGetSymbolAddress((void**)&p_stats, g_stats);
    cudaGetSymbolAddress((void**)&p_gsum, g_gsum);
    cudaGetSymbolAddress((void**)&p_gsq, g_gsq);
    cudaGetSymbolAddress((void**)&p_sc, g_sc);
    cudaGetSymbolAddress((void**)&p_cnt, g_cnt);
    cudaGetSymbolAddress((void**)&p_wexp, g_wexp);
    cudaGetSymbolAddress((void**)&p_wsum, g_wsum);
    cudaGetSymbolAddress((void**)&p_wf, g_wf);
    cudaGetSymbolAddress((void**)&p_deg, g_deg);
    cudaGetSymbolAddress((void**)&p_rowstart, g_rowstart);
    cudaGetSymbolAddress((void**)&p_cursor, g_cursor);
    cudaGetSymbolAddress((void**)&p_eid, g_csr_eid);
    cudaGetSymbolAddress((void**)&p_csrc, g_csr_src);
    cudaGetSymbolAddress((void**)&p_gstart, g_gstart);

    // ----- CSR build
    cudaMemsetAsync(p_deg, 0, NNODES * sizeof(int));
    deg_kernel<<<(NEDGES + 255) / 256, 256>>>(dst, p_deg);
    csr_scan_kernel<<<1, 1024>>>(p_deg, p_rowstart, p_cursor);
    csr_fill_kernel<<<(NEDGES + 255) / 256, 256>>>(src, dst, p_cursor, p_eid, p_csrc);

    // ----- graph ranges + counts
    cudaMemsetAsync(p_gstart, 0x7F, (NGRAPH + 1) * sizeof(int));
    gstart_min_kernel<<<(NNODES + 255) / 256, 256>>>(batch, p_gstart);
    gstart_fix_kernel<<<1, 1024>>>(p_gstart, p_cnt);

    // ----- weight prep
    wfuse_kernel<<<dim3(NLAYER, 7), HID>>>(edge_w, edge_b, conv_w, conv_b, p_wf);
    wpack_kernel<<<(NLAYER * 128 * 256) / 256, 256>>>(mlp_w1, mlp_w2, p_w1p, p_w2p);
    wpack_att_kernel<<<(128 * 128) / 256, 256>>>(att_w1, p_w1a);

    // ----- node embedding (tf32, half output)
    {
        dim3 grid(HID / 128, (NNODES + 127) / 128);
        tf32_gemm_h<<<grid, 256, GEMM_SMEM_BYTES>>>(NNODES, HID, NODE_F, x, node_w,
                                                    node_b, p_hh0);
    }

    __half* h_cur = p_hh0;
    __half* h_nxt = p_hh1;
    const int mgrid = (NNODES + 127) / 128;

    for (int i = 0; i < NLAYER; i++) {
        gine_gather_fused<<<1024, 256>>>(
            h_cur, edge_attr, p_rowstart, p_eid, p_csrc,
            p_wf + (size_t)i * 7 * HID, eps + i, p_aeffh, p_stats);

        fused_mlp<<<mgrid, 512, FUSED_SMEM>>>(
            NNODES, p_aeffh,
            p_w1p + (size_t)i * 32768, p_w2p + (size_t)i * 32768,
            mlp_b1 + (size_t)i * HID, mlp_b2 + (size_t)i * HID, p_zh);

        graph_stats_kernel<<<NGRAPH, HID>>>(p_zh, p_gstart, p_gsum, p_gsq, p_stats);
        graph_msq_kernel<<<NGRAPH, HID>>>(p_stats, bn_gamma + (size_t)i * HID,
                                          p_cnt, p_gsum, p_gsq, p_sc);
        final_norm_kernel<<<NNODES, HID>>>(p_zh, p_stats, bn_gamma + (size_t)i * HID,
                                           p_gsum, p_sc, batch, h_nxt);

        __half* t = h_cur; h_cur = h_nxt; h_nxt = t;
    }

    // attention hidden: s1 = tanh(h @ att_w1 + att_b1)
    {
        dim3 agrid(1, (NNODES + 127) / 128);
        hgemm_att<<<agrid, 256, HG_SMEM_128>>>(NNODES, h_cur, p_w1a, att_b1, p_s1h);
    }

    cudaMemsetAsync(p_wsum, 0, NGRAPH * sizeof(float));
    attn_score_kernel<<<(NNODES * 32 + 255) / 256, 256>>>(p_s1h, att_w2, att_b2, batch, p_wexp, p_wsum);

    pool_graph_kernel<<<NGRAPH, HID>>>(h_cur, p_wexp, p_wsum, p_gstart, p_cnt, out);

    (void)in_sizes; (void)n_in; (void)out_size;
}

// round 9
// speedup vs baseline: 6.1941x; 1.2400x over previous
#include <cuda_runtime.h>
#include <cuda_fp16.h>
#include <math.h>
#include <stdint.h>

#define NNODES 100000
#define NEDGES 320000
#define NGRAPH 2048
#define HID    256
#define EDIM   128
#define NODE_F 48
#define EDGE_F 6
#define NLAYER 8
#define NBLKD  ((NNODES + 255) / 256)   // 391

// ---------------- scratch (device globals) ----------------------------------
__device__ __half  g_hh0[(size_t)NNODES * HID];
__device__ __half  g_hh1[(size_t)NNODES * HID];
__device__ __half  g_zh [(size_t)NNODES * HID];
__device__ __half  g_aeffh[(size_t)NNODES * HID];
__device__ __half  g_s1h [(size_t)NNODES * EDIM];
__device__ __half2 g_w1p[(size_t)NLAYER * (HID / 2) * HID];
__device__ __half2 g_w2p[(size_t)NLAYER * (HID / 2) * HID];
__device__ __half2 g_w1a[(size_t)(HID / 2) * EDIM];
__device__ float   g_stats[2 * HID];
__device__ float   g_gsum[(size_t)NGRAPH * HID];
__device__ float   g_gsq [(size_t)NGRAPH * HID];
__device__ float   g_cnt [NGRAPH];
__device__ float   g_wexp[NNODES];
__device__ float   g_wsum[NGRAPH];
__device__ float   g_wf  [(size_t)NLAYER * 7 * HID];
__device__ int     g_deg [NNODES];
__device__ int     g_bsum[NBLKD];
__device__ int     g_boffs[NBLKD];
__device__ int     g_rowstart[NNODES + 1];
__device__ int     g_cursor[NNODES];
__device__ int     g_csr_eid[NEDGES];
__device__ int     g_csr_src[NEDGES];
__device__ int     g_gstart[NGRAPH + 1];

// ---------------- common helpers ---------------------------------------------
__device__ __forceinline__ uint32_t f2tf32(float x) {
    uint32_t r;
    asm volatile("cvt.rna.tf32.f32 %0, %1;" : "=r"(r) : "f"(x));
    return r;
}
__device__ __forceinline__ void cp16s(uint32_t d, const void* src, bool pred) {
    int sz = pred ? 16 : 0;
    asm volatile("cp.async.cg.shared.global [%0], [%1], 16, %2;" :: "r"(d), "l"(src), "r"(sz));
}
__device__ __forceinline__ void cp_commit() { asm volatile("cp.async.commit_group;"); }
template <int Np>
__device__ __forceinline__ void cp_wait() { asm volatile("cp.async.wait_group %0;" :: "n"(Np)); }
__device__ __forceinline__ void mma_f16(float* c, const uint32_t* a, const uint32_t* b) {
    asm volatile(
        "mma.sync.aligned.m16n8k16.row.col.f32.f16.f16.f32 "
        "{%0,%1,%2,%3}, {%4,%5,%6,%7}, {%8,%9}, {%0,%1,%2,%3};"
        : "+f"(c[0]), "+f"(c[1]), "+f"(c[2]), "+f"(c[3])
        : "r"(a[0]), "r"(a[1]), "r"(a[2]), "r"(a[3]), "r"(b[0]), "r"(b[1]));
}
__device__ __forceinline__ void ldsm4(uint32_t* r, uint32_t addr) {
    asm volatile("ldmatrix.sync.aligned.m8n8.x4.shared.b16 {%0,%1,%2,%3}, [%4];"
                 : "=r"(r[0]), "=r"(r[1]), "=r"(r[2]), "=r"(r[3]) : "r"(addr));
}

extern __shared__ char smemc[];

// ===================== fused MLP + stats ========================================
// z = (relu(A@W1+b1))@W2 + b2 ; also accumulates per-graph (S,Q) and chip stats.
#define FA_STRIDE 72
#define FA_TILE_BYTES (128 * FA_STRIDE * 2)
#define FB2_STRIDE 260
#define FB_TILE2 (32 * FB2_STRIDE)
#define FTMP_STRIDE 264
#define OFF_B (2 * FA_TILE_BYTES)
#define OFF_TMP (OFF_B + 2 * FB_TILE2 * 4)
#define FUSED_SMEM (OFF_TMP + 128 * FTMP_STRIDE * 2)   // 171008

__global__ __launch_bounds__(512, 1) void fused_mlp(
    int M, const __half* __restrict__ A,
    const __half2* __restrict__ W1p, const __half2* __restrict__ W2p,
    const float* __restrict__ b1, const float* __restrict__ b2,
    const int* __restrict__ batchp,
    float* __restrict__ gsum, float* __restrict__ gsq, float* __restrict__ stats,
    __half* __restrict__ Z)
{
    uint32_t sb = (uint32_t)__cvta_generic_to_shared(smemc);
    const __half2* hB = (const __half2*)(smemc + OFF_B);
    __half* tmp = (__half*)(smemc + OFF_TMP);
    uint32_t sbT = sb + OFF_TMP;

    const int tid = threadIdx.x;
    const int warp = tid >> 5;
    const int lane = tid & 31;
    const int g = lane >> 2;
    const int tq = lane & 3;
    const int m0 = blockIdx.x * 128;
    const int wm = (warp & 3) * 32;
    const int wn = (warp >> 2) * 64;
    const int lrow = ((lane >> 3) & 1) * 8 + (lane & 7);
    const int lcol = (lane >> 4) * 8;

    float acc[2][8][4];
#pragma unroll
    for (int i = 0; i < 2; i++)
#pragma unroll
        for (int j = 0; j < 8; j++)
#pragma unroll
            for (int r = 0; r < 4; r++) acc[i][j][r] = 0.0f;

    auto fillA = [&](int buf, int k0) {
#pragma unroll
        for (int it = 0; it < 2; it++) {
            int chunk = tid + it * 512;
            int r = chunk >> 3, c = (chunk & 7) * 8;
            bool p = (m0 + r) < M;
            cp16s(sb + buf * FA_TILE_BYTES + (r * FA_STRIDE + c) * 2,
                  A + (size_t)(p ? m0 + r : 0) * 256 + k0 + c, p);
        }
    };
    auto fillB = [&](int buf, int k0, const __half2* W) {
#pragma unroll
        for (int it = 0; it < 4; it++) {
            int chunk = tid + it * 512;
            int pr = chunk >> 6, c2 = (chunk & 63) * 4;
            cp16s(sb + OFF_B + (buf * FB_TILE2 + pr * FB2_STRIDE + c2) * 4,
                  W + (size_t)((k0 >> 1) + pr) * 256 + c2, true);
        }
    };

    // ---------------- phase 1: acc = A @ W1
    fillA(0, 0);
    fillB(0, 0, W1p);
    cp_commit();

    int buf = 0;
#pragma unroll 1
    for (int i = 0; i < 4; i++) {
        if (i < 3) {
            fillA(buf ^ 1, (i + 1) * 64);
            fillB(buf ^ 1, (i + 1) * 64, W1p);
        } else {
            fillB(buf ^ 1, 0, W2p);
        }
        cp_commit();
        cp_wait<1>();
        __syncthreads();

        uint32_t abase = sb + buf * FA_TILE_BYTES;
        const __half2* Bb = hB + buf * FB_TILE2;
#pragma unroll
        for (int kk = 0; kk < 4; kk++) {
            uint32_t af[2][4];
#pragma unroll
            for (int mi = 0; mi < 2; mi++)
                ldsm4(af[mi], abase + ((wm + mi * 16 + lrow) * FA_STRIDE + kk * 16 + lcol) * 2);
            uint32_t bf[8][2];
#pragma unroll
            for (int ni = 0; ni < 8; ni++) {
                const __half2* p = Bb + (kk * 8 + tq) * FB2_STRIDE + wn + ni * 8 + g;
                bf[ni][0] = *(const uint32_t*)(p);
                bf[ni][1] = *(const uint32_t*)(p + 4 * FB2_STRIDE);
            }
#pragma unroll
            for (int mi = 0; mi < 2; mi++)
#pragma unroll
                for (int ni = 0; ni < 8; ni++)
                    mma_f16(acc[mi][ni], af[mi], bf[ni]);
        }
        __syncthreads();
        buf ^= 1;
    }

    // stash batch ids in the (now idle) A region
    if (tid < 128)
        ((int*)smemc)[tid] = (m0 + tid < M) ? __ldg(batchp + m0 + tid) : 0;

    // ---------------- phase 1 epilogue: tmp = relu(acc + b1)
#pragma unroll
    for (int mi = 0; mi < 2; mi++) {
        int r0 = wm + mi * 16 + g;
        int r1 = r0 + 8;
#pragma unroll
        for (int ni = 0; ni < 8; ni++) {
            int col = wn + ni * 8 + tq * 2;
            float c0 = __ldg(b1 + col);
            float c1 = __ldg(b1 + col + 1);
            float v0 = fmaxf(acc[mi][ni][0] + c0, 0.f);
            float v1 = fmaxf(acc[mi][ni][1] + c1, 0.f);
            float v2 = fmaxf(acc[mi][ni][2] + c0, 0.f);
            float v3 = fmaxf(acc[mi][ni][3] + c1, 0.f);
            *(__half2*)(tmp + r0 * FTMP_STRIDE + col) = __floats2half2_rn(v0, v1);
            *(__half2*)(tmp + r1 * FTMP_STRIDE + col) = __floats2half2_rn(v2, v3);
            acc[mi][ni][0] = 0.f; acc[mi][ni][1] = 0.f;
            acc[mi][ni][2] = 0.f; acc[mi][ni][3] = 0.f;
        }
    }

    // ---------------- phase 2: acc = tmp @ W2
#pragma unroll 1
    for (int i = 0; i < 4; i++) {
        if (i < 3) {
            fillB(buf ^ 1, (i + 1) * 64, W2p);
            cp_commit();
            cp_wait<1>();
        } else {
            cp_wait<0>();
        }
        __syncthreads();

        const __half2* Bb = hB + buf * FB_TILE2;
#pragma unroll
        for (int kk = 0; kk < 4; kk++) {
            uint32_t af[2][4];
#pragma unroll
            for (int mi = 0; mi < 2; mi++)
                ldsm4(af[mi], sbT + ((wm + mi * 16 + lrow) * FTMP_STRIDE + i * 64 + kk * 16 + lcol) * 2);
            uint32_t bf[8][2];
#pragma unroll
            for (int ni = 0; ni < 8; ni++) {
                const __half2* p = Bb + (kk * 8 + tq) * FB2_STRIDE + wn + ni * 8 + g;
                bf[ni][0] = *(const uint32_t*)(p);
                bf[ni][1] = *(const uint32_t*)(p + 4 * FB2_STRIDE);
            }
#pragma unroll
            for (int mi = 0; mi < 2; mi++)
#pragma unroll
                for (int ni = 0; ni < 8; ni++)
                    mma_f16(acc[mi][ni], af[mi], bf[ni]);
        }
        __syncthreads();
        buf ^= 1;
    }

    // ---------------- phase 2 epilogue: Z(global) + z(tmp smem)
#pragma unroll
    for (int mi = 0; mi < 2; mi++) {
        int rr0 = wm + mi * 16 + g;
        int rr1 = rr0 + 8;
        int r0 = m0 + rr0;
        int r1 = m0 + rr1;
#pragma unroll
        for (int ni = 0; ni < 8; ni++) {
            int col = wn + ni * 8 + tq * 2;
            float c0 = __ldg(b2 + col);
            float c1 = __ldg(b2 + col + 1);
            __half2 z0 = __floats2half2_rn(acc[mi][ni][0] + c0, acc[mi][ni][1] + c1);
            __half2 z1 = __floats2half2_rn(acc[mi][ni][2] + c0, acc[mi][ni][3] + c1);
            *(__half2*)(tmp + rr0 * FTMP_STRIDE + col) = z0;
            *(__half2*)(tmp + rr1 * FTMP_STRIDE + col) = z1;
            if (r0 < M) *(__half2*)(Z + (size_t)r0 * 256 + col) = z0;
            if (r1 < M) *(__half2*)(Z + (size_t)r1 * 256 + col) = z1;
        }
    }
    __syncthreads();

    // ---------------- phase 3: per-graph + chip stats from smem z
    {
        const int c = tid & 255;
        const int rbeg = (tid >> 8) * 64;
        const int* sbatch = (const int*)smemc;
        float ts = 0.f, tqs = 0.f;
        int curg = -1;
        float s = 0.f, q = 0.f;
        for (int r = rbeg; r < rbeg + 64; r++) {
            if (m0 + r >= M) break;
            int gg = sbatch[r];
            if (gg != curg) {
                if (curg >= 0) {
                    atomicAdd(gsum + (size_t)curg * 256 + c, s);
                    atomicAdd(gsq + (size_t)curg * 256 + c, q);
                }
                curg = gg; s = 0.f; q = 0.f;
            }
            float v = __half2float(tmp[r * FTMP_STRIDE + c]);
            s += v; q = fmaf(v, v, q);
            ts += v; tqs = fmaf(v, v, tqs);
        }
        if (curg >= 0) {
            atomicAdd(gsum + (size_t)curg * 256 + c, s);
            atomicAdd(gsq + (size_t)curg * 256 + c, q);
        }
        atomicAdd(stats + c, ts);
        atomicAdd(stats + 256 + c, tqs);
    }
}

// ===================== merged msq + normalize (block per graph) ================
__global__ void msq_norm_kernel(const float* __restrict__ stats,
                                const float* __restrict__ gamma,
                                const float* __restrict__ cnt,
                                const float* __restrict__ gsum,
                                const float* __restrict__ gsq,
                                const int* __restrict__ gstart,
                                const __half* __restrict__ zh,
                                __half* __restrict__ hout)
{
    __shared__ float red[HID];
    int gb = blockIdx.x;
    int c = threadIdx.x;
    const float invN = 1.0f / (float)NNODES;
    float mu = __ldg(stats + c) * invN;
    float var = __ldg(stats + HID + c) * invN - mu * mu;
    float ac = __ldg(gamma + c) * rsqrtf(var + 1e-5f);
    float cg = cnt[gb];
    size_t gi = (size_t)gb * HID + c;
    float S = gsum[gi], Q = gsq[gi];
    float m = S / cg;
    red[c] = ac * ac * (Q - cg * m * m);
    __syncthreads();
    for (int o = HID / 2; o > 0; o >>= 1) {
        if (c < o) red[c] += red[c + o];
        __syncthreads();
    }
    float sc = rsqrtf(1e-5f + red[0] / cg);
    int lo = gstart[gb], hi = gstart[gb + 1];
    float acs = ac * sc;
    float ms = m;
    for (int n = lo; n < hi; n++) {
        size_t i = (size_t)n * HID + c;
        float v = acs * (__half2float(zh[i]) - ms);
        hout[i] = __float2half(fmaxf(v, 0.f));
    }
}

// ===================== fp16 GEMM (attention, tanh) =============================
#define HA_STRIDE 72
#define HA_TILE_BYTES (128 * HA_STRIDE * 2)

__global__ __launch_bounds__(256, 2) void hgemm_att(
    int M, const __half* __restrict__ A, const __half2* __restrict__ Bp,
    const float* __restrict__ bias, __half* __restrict__ Ch)
{
    constexpr int WN = 128;
    constexpr int HB2_STRIDE = WN + 4;
    constexpr int HB_TILE2 = 32 * HB2_STRIDE;
    const __half2* hB = (const __half2*)(smemc + 2 * HA_TILE_BYTES);
    uint32_t sb = (uint32_t)__cvta_generic_to_shared(smemc);
    uint32_t sbB = sb + 2 * HA_TILE_BYTES;

    const int tid = threadIdx.x;
    const int warp = tid >> 5;
    const int lane = tid & 31;
    const int g = lane >> 2;
    const int tq = lane & 3;
    const int m0 = blockIdx.y * 128;
    const int wm = (warp >> 1) * 32;
    const int wn = (warp & 1) * 64;
    const int lrow = ((lane >> 3) & 1) * 8 + (lane & 7);
    const int lcol = (lane >> 4) * 8;

    float acc[2][8][4];
#pragma unroll
    for (int i = 0; i < 2; i++)
#pragma unroll
        for (int j = 0; j < 8; j++)
#pragma unroll
            for (int r = 0; r < 4; r++) acc[i][j][r] = 0.0f;

    auto fillA = [&](int buf, int k0) {
#pragma unroll
        for (int it = 0; it < 4; it++) {
            int chunk = tid + it * 256;
            int r = chunk >> 3, c = (chunk & 7) * 8;
            bool p = (m0 + r) < M;
            cp16s(sb + buf * HA_TILE_BYTES + (r * HA_STRIDE + c) * 2,
                  A + (size_t)(p ? m0 + r : 0) * 256 + k0 + c, p);
        }
    };
    auto fillB = [&](int buf, int k0) {
#pragma unroll
        for (int it = 0; it < 4; it++) {
            int chunk = tid + it * 256;
            int pr = chunk >> 5, c2 = (chunk & 31) * 4;
            cp16s(sbB + (buf * HB_TILE2 + pr * HB2_STRIDE + c2) * 4,
                  Bp + (size_t)((k0 >> 1) + pr) * WN + c2, true);
        }
    };

    fillA(0, 0);
    fillB(0, 0);
    cp_commit();

    int buf = 0;
#pragma unroll 1
    for (int i = 0; i < 4; i++) {
        if (i + 1 < 4) {
            fillA(buf ^ 1, (i + 1) * 64);
            fillB(buf ^ 1, (i + 1) * 64);
            cp_commit();
            cp_wait<1>();
        } else {
            cp_wait<0>();
        }
        __syncthreads();

        uint32_t abase = sb + buf * HA_TILE_BYTES;
        const __half2* Bb = hB + buf * HB_TILE2;
#pragma unroll
        for (int kk = 0; kk < 4; kk++) {
            uint32_t af[2][4];
#pragma unroll
            for (int mi = 0; mi < 2; mi++)
                ldsm4(af[mi], abase + ((wm + mi * 16 + lrow) * HA_STRIDE + kk * 16 + lcol) * 2);
            uint32_t bf[8][2];
#pragma unroll
            for (int ni = 0; ni < 8; ni++) {
                const __half2* p = Bb + (kk * 8 + tq) * HB2_STRIDE + wn + ni * 8 + g;
                bf[ni][0] = *(const uint32_t*)(p);
                bf[ni][1] = *(const uint32_t*)(p + 4 * HB2_STRIDE);
            }
#pragma unroll
            for (int mi = 0; mi < 2; mi++)
#pragma unroll
                for (int ni = 0; ni < 8; ni++)
                    mma_f16(acc[mi][ni], af[mi], bf[ni]);
        }
        __syncthreads();
        buf ^= 1;
    }

#pragma unroll
    for (int mi = 0; mi < 2; mi++) {
        int r0 = m0 + wm + mi * 16 + g;
        int r1 = r0 + 8;
#pragma unroll
        for (int ni = 0; ni < 8; ni++) {
            int col = wn + ni * 8 + tq * 2;
            float b0 = __ldg(bias + col);
            float b1 = __ldg(bias + col + 1);
            float v0 = tanhf(acc[mi][ni][0] + b0);
            float v1 = tanhf(acc[mi][ni][1] + b1);
            float v2 = tanhf(acc[mi][ni][2] + b0);
            float v3 = tanhf(acc[mi][ni][3] + b1);
            if (r0 < M) *(__half2*)(Ch + (size_t)r0 * WN + col) = __floats2half2_rn(v0, v1);
            if (r1 < M) *(__half2*)(Ch + (size_t)r1 * WN + col) = __floats2half2_rn(v2, v3);
        }
    }
}

// ---------------- weight packs ---------------------------------------------------
__global__ void wpack_kernel(const float* __restrict__ w1, const float* __restrict__ w2,
                             __half2* __restrict__ w1p, __half2* __restrict__ w2p)
{
    int idx = blockIdx.x * 256 + threadIdx.x;
    int l = idx >> 15;
    int rem = idx & 32767;
    int p = rem >> 8;
    int n = rem & 255;
    size_t base = (size_t)l * 65536 + (size_t)(2 * p) * 256 + n;
    w1p[idx] = __floats2half2_rn(__ldg(w1 + base), __ldg(w1 + base + 256));
    w2p[idx] = __floats2half2_rn(__ldg(w2 + base), __ldg(w2 + base + 256));
}
__global__ void wpack_att_kernel(const float* __restrict__ w, __half2* __restrict__ wp)
{
    int idx = blockIdx.x * 256 + threadIdx.x;
    int p = idx >> 7;
    int n = idx & 127;
    size_t base = (size_t)(2 * p) * 128 + n;
    wp[idx] = __floats2half2_rn(__ldg(w + base), __ldg(w + base + 128));
}

// ===================== mma.sync TF32 GEMM (node embed) ========================
#define GA_STRIDE 36
#define GB_STRIDE 132
#define A_TILE_W (128 * GA_STRIDE)
#define B_TILE_W (32 * GB_STRIDE)
#define GEMM_SMEM_BYTES ((2 * A_TILE_W + 2 * B_TILE_W) * 4)

__device__ __forceinline__ void cp16(float* dst, const float* src, bool pred) {
    cp16s((uint32_t)__cvta_generic_to_shared(dst), src, pred);
}
__device__ __forceinline__ void mma_tf32(float* c, const uint32_t* a, const uint32_t* b) {
    asm volatile(
        "mma.sync.aligned.m16n8k8.row.col.f32.tf32.tf32.f32 "
        "{%0,%1,%2,%3}, {%4,%5,%6,%7}, {%8,%9}, {%0,%1,%2,%3};"
        : "+f"(c[0]), "+f"(c[1]), "+f"(c[2]), "+f"(c[3])
        : "r"(a[0]), "r"(a[1]), "r"(a[2]), "r"(a[3]), "r"(b[0]), "r"(b[1]));
}

__global__ __launch_bounds__(256, 2) void tf32_gemm_h(
    int M, int N, int K,
    const float* __restrict__ A, const float* __restrict__ B,
    const float* __restrict__ bias, __half* __restrict__ Chh)
{
    float* sm = (float*)smemc;
    float* As = sm;
    float* Bs = sm + 2 * A_TILE_W;

    const int tid = threadIdx.x;
    const int warp = tid >> 5;
    const int lane = tid & 31;
    const int g = lane >> 2;
    const int tq = lane & 3;
    const int m0 = blockIdx.y * 128;
    const int n0 = blockIdx.x * 128;
    const int wm = (warp >> 1) * 32;
    const int wn = (warp & 1) * 64;

    float acc[2][8][4];
#pragma unroll
    for (int i = 0; i < 2; i++)
#pragma unroll
        for (int j = 0; j < 8; j++)
#pragma unroll
            for (int r = 0; r < 4; r++) acc[i][j][r] = 0.0f;

    const int arow = tid >> 3;
    const int ac4 = tid & 7;
    const int brow = tid >> 5;
    const int bc4 = tid & 31;
    const int nk = (K + 31) / 32;

    {
#pragma unroll
        for (int it = 0; it < 4; it++) {
            int row = arow + it * 32;
            int gm = m0 + row;
            int gk = ac4 * 4;
            bool p = (gm < M) && (gk < K);
            const float* src = A + (size_t)(p ? gm : 0) * K + (p ? gk : 0);
            cp16(As + row * GA_STRIDE + ac4 * 4, src, p);
        }
#pragma unroll
        for (int it = 0; it < 4; it++) {
            int row = brow + it * 8;
            bool p = (row < K);
            const float* src = B + (size_t)(p ? row : 0) * N + n0 + bc4 * 4;
            cp16(Bs + row * GB_STRIDE + bc4 * 4, src, p);
        }
        cp_commit();
    }

    int buf = 0;
    for (int i = 0; i < nk; i++) {
        if (i + 1 < nk) {
            const int kc = i + 1;
            float* Ad = As + (buf ^ 1) * A_TILE_W;
            float* Bd = Bs + (buf ^ 1) * B_TILE_W;
#pragma unroll
            for (int it = 0; it < 4; it++) {
                int row = arow + it * 32;
                int gm = m0 + row;
                int gk = kc * 32 + ac4 * 4;
                bool p = (gm < M) && (gk < K);
                const float* src = A + (size_t)(p ? gm : 0) * K + (p ? gk : 0);
                cp16(Ad + row * GA_STRIDE + ac4 * 4, src, p);
            }
#pragma unroll
            for (int it = 0; it < 4; it++) {
                int row = brow + it * 8;
                int gk = kc * 32 + row;
                bool p = (gk < K);
                const float* src = B + (size_t)(p ? gk : 0) * N + n0 + bc4 * 4;
                cp16(Bd + row * GB_STRIDE + bc4 * 4, src, p);
            }
            cp_commit();
            cp_wait<1>();
        } else {
            cp_wait<0>();
        }
        __syncthreads();

        const float* Ab = As + buf * A_TILE_W;
        const float* Bb = Bs + buf * B_TILE_W;
#pragma unroll
        for (int kk = 0; kk < 4; kk++) {
            const int k = kk * 8;
            uint32_t af[2][4];
#pragma unroll
            for (int mi = 0; mi < 2; mi++) {
                const float* p = Ab + (wm + mi * 16 + g) * GA_STRIDE + k + tq;
                af[mi][0] = f2tf32(p[0]);
                af[mi][1] = f2tf32(p[8 * GA_STRIDE]);
                af[mi][2] = f2tf32(p[4]);
                af[mi][3] = f2tf32(p[8 * GA_STRIDE + 4]);
            }
            uint32_t bf[8][2];
#pragma unroll
            for (int ni = 0; ni < 8; ni++) {
                const float* p = Bb + (k + tq) * GB_STRIDE + wn + ni * 8 + g;
                bf[ni][0] = f2tf32(p[0]);
                bf[ni][1] = f2tf32(p[4 * GB_STRIDE]);
            }
#pragma unroll
            for (int mi = 0; mi < 2; mi++)
#pragma unroll
                for (int ni = 0; ni < 8; ni++)
                    mma_tf32(acc[mi][ni], af[mi], bf[ni]);
        }
        __syncthreads();
        buf ^= 1;
    }

#pragma unroll
    for (int mi = 0; mi < 2; mi++) {
        int r0 = m0 + wm + mi * 16 + g;
        int r1 = r0 + 8;
#pragma unroll
        for (int ni = 0; ni < 8; ni++) {
            int col = n0 + wn + ni * 8 + tq * 2;
            float b0 = __ldg(bias + col);
            float b1 = __ldg(bias + col + 1);
            if (r0 < M) *(__half2*)(Chh + (size_t)r0 * N + col) =
                __floats2half2_rn(acc[mi][ni][0] + b0, acc[mi][ni][1] + b1);
            if (r1 < M) *(__half2*)(Chh + (size_t)r1 * N + col) =
                __floats2half2_rn(acc[mi][ni][2] + b0, acc[mi][ni][3] + b1);
        }
    }
}

// ---------------- fused edge weights ------------------------------------------
__global__ void wfuse_kernel(const float* __restrict__ edge_w,
                             const float* __restrict__ edge_b,
                             const float* __restrict__ conv_w,
                             const float* __restrict__ conv_b,
                             float* __restrict__ wf)
{
    int layer = blockIdx.x;
    int k = blockIdx.y;
    int c = threadIdx.x;
    const float* cw = conv_w + (size_t)layer * EDIM * HID;
    float s = 0.f;
    if (k < EDGE_F) {
        for (int j = 0; j < EDIM; j++)
            s = fmaf(__ldg(edge_w + k * EDIM + j), __ldg(cw + (size_t)j * HID + c), s);
    } else {
        for (int j = 0; j < EDIM; j++)
            s = fmaf(__ldg(edge_b + j), __ldg(cw + (size_t)j * HID + c), s);
        s += __ldg(conv_b + (size_t)layer * HID + c);
    }
    wf[((size_t)layer * 7 + k) * HID + c] = s;
}

// ---------------- CSR build (parallel scan) -------------------------------------
__global__ void deg_kernel(const int* __restrict__ dst, int* __restrict__ deg)
{
    int e = blockIdx.x * blockDim.x + threadIdx.x;
    if (e < NEDGES) atomicAdd(&deg[__ldg(dst + e)], 1);
}

__global__ void deg_bsum_kernel(const int* __restrict__ deg, int* __restrict__ bsum)
{
    __shared__ int sh[256];
    int i = blockIdx.x * 256 + threadIdx.x;
    sh[threadIdx.x] = (i < NNODES) ? deg[i] : 0;
    __syncthreads();
    for (int o = 128; o > 0; o >>= 1) {
        if (threadIdx.x < o) sh[threadIdx.x] += sh[threadIdx.x + o];
        __syncthreads();
    }
    if (threadIdx.x == 0) bsum[blockIdx.x] = sh[0];
}

__global__ void bscan_kernel(const int* __restrict__ bsum, int* __restrict__ boffs)
{
    __shared__ int sh[512];
    int t = threadIdx.x;
    int mine = (t < NBLKD) ? bsum[t] : 0;
    sh[t] = mine;
    __syncthreads();
    for (int o = 1; o < 512; o <<= 1) {
        int v = (t >= o) ? sh[t - o] : 0;
        __syncthreads();
        sh[t] += v;
        __syncthreads();
    }
    if (t < NBLKD) boffs[t] = sh[t] - mine;
}

__global__ void rowfill_kernel(const int* __restrict__ deg, const int* __restrict__ boffs,
                               int* __restrict__ rowstart, int* __restrict__ cursor)
{
    __shared__ int sh[256];
    int b = blockIdx.x, t = threadIdx.x;
    int i = b * 256 + t;
    int d = (i < NNODES) ? deg[i] : 0;
    sh[t] = d;
    __syncthreads();
    for (int o = 1; o < 256; o <<= 1) {
        int v = (t >= o) ? sh[t - o] : 0;
        __syncthreads();
        sh[t] += v;
        __syncthreads();
    }
    if (i < NNODES) {
        int rs = boffs[b] + sh[t] - d;
        rowstart[i] = rs;
        cursor[i] = rs;
    }
    if (i == NNODES - 1) rowstart[NNODES] = NEDGES;
}

__global__ void csr_fill_kernel(const int* __restrict__ src,
                                const int* __restrict__ dst,
                                int* __restrict__ cursor,
                                int* __restrict__ csr_eid,
                                int* __restrict__ csr_src)
{
    int e = blockIdx.x * blockDim.x + threadIdx.x;
    if (e >= NEDGES) return;
    int d = __ldg(dst + e);
    int p = atomicAdd(&cursor[d], 1);
    csr_eid[p] = e;
    csr_src[p] = __ldg(src + e);
}

// ---------------- graph ranges --------------------------------------------------
__global__ void gstart_min_kernel(const int* __restrict__ batch, int* __restrict__ gstart)
{
    int n = blockIdx.x * blockDim.x + threadIdx.x;
    if (n < NNODES) atomicMin(&gstart[__ldg(batch + n)], n);
}

__global__ void gstart_fix_kernel(int* __restrict__ gstart, float* __restrict__ cnt)
{
    __shared__ int sg[NGRAPH + 1];
    int t = threadIdx.x;
    for (int i = t; i <= NGRAPH; i += 1024) sg[i] = gstart[i];
    __syncthreads();
    if (t == 0) {
        sg[NGRAPH] = NNODES;
        for (int g2 = NGRAPH - 1; g2 >= 0; g2--)
            if (sg[g2] > sg[g2 + 1]) sg[g2] = sg[g2 + 1];
    }
    __syncthreads();
    for (int i = t; i <= NGRAPH; i += 1024) gstart[i] = sg[i];
    for (int i = t; i < NGRAPH; i += 1024)
        cnt[i] = fmaxf((float)(sg[i + 1] - sg[i]), 1.0f);
}

// ---------------- GINE gather (also zeroes stats + gsum/gsq) -------------------
__device__ __forceinline__ float4 h4load(const uint2* hp, int idx) {
    uint2 u = __ldg(hp + idx);
    float2 f0 = __half22float2(*(__half2*)&u.x);
    float2 f1 = __half22float2(*(__half2*)&u.y);
    return make_float4(f0.x, f0.y, f1.x, f1.y);
}

__global__ __launch_bounds__(256) void gine_gather_fused(
    const __half* __restrict__ h,
    const float* __restrict__ ea,
    const int* __restrict__ rowstart,
    const int* __restrict__ csr_eid,
    const int* __restrict__ csr_src,
    const float* __restrict__ wf,
    const float* __restrict__ eps_ptr,
    __half* __restrict__ aeffh,
    float* __restrict__ stats,
    float* __restrict__ gsum,
    float* __restrict__ gsq)
{
    {
        int gid = blockIdx.x * 256 + threadIdx.x;    // 262144 threads
        gsum[gid] = 0.f; gsum[gid + 262144] = 0.f;
        gsq[gid] = 0.f;  gsq[gid + 262144] = 0.f;
        if (blockIdx.x == 0) {
            stats[threadIdx.x] = 0.f;
            stats[256 + threadIdx.x] = 0.f;
        }
    }

    const int lane = threadIdx.x & 31;
    const int warp_g = (blockIdx.x * blockDim.x + threadIdx.x) >> 5;
    const int nwarps = (gridDim.x * blockDim.x) >> 5;
    const float alpha = 1.0f + __ldg(eps_ptr);

    float4 w0[EDGE_F], w1[EDGE_F];
#pragma unroll
    for (int k = 0; k < EDGE_F; k++) {
        w0[k] = __ldg((const float4*)(wf + k * HID) + lane);
        w1[k] = __ldg((const float4*)(wf + k * HID) + 32 + lane);
    }
    float4 bf0 = __ldg((const float4*)(wf + EDGE_F * HID) + lane);
    float4 bf1 = __ldg((const float4*)(wf + EDGE_F * HID) + 32 + lane);

    for (int n = warp_g; n < NNODES; n += nwarps) {
        const uint2* hn = (const uint2*)(h + (size_t)n * HID);
        float4 a0 = h4load(hn, lane);
        float4 a1 = h4load(hn, 32 + lane);
        a0.x *= alpha; a0.y *= alpha; a0.z *= alpha; a0.w *= alpha;
        a1.x *= alpha; a1.y *= alpha; a1.z *= alpha; a1.w *= alpha;

        int lo = __ldg(rowstart + n), hi = __ldg(rowstart + n + 1);
        for (int j = lo; j < hi; j++) {
            int eid = __ldg(csr_eid + j);
            int s = __ldg(csr_src + j);
            const float* er = ea + (size_t)eid * EDGE_F;
            float e0 = __ldg(er + 0), e1 = __ldg(er + 1), e2 = __ldg(er + 2);
            float e3 = __ldg(er + 3), e4 = __ldg(er + 4), e5 = __ldg(er + 5);

            float4 ee0 = bf0, ee1 = bf1;
            ee0.x = fmaf(e0, w0[0].x, ee0.x); ee0.y = fmaf(e0, w0[0].y, ee0.y);
            ee0.z = fmaf(e0, w0[0].z, ee0.z); ee0.w = fmaf(e0, w0[0].w, ee0.w);
            ee1.x = fmaf(e0, w1[0].x, ee1.x); ee1.y = fmaf(e0, w1[0].y, ee1.y);
            ee1.z = fmaf(e0, w1[0].z, ee1.z); ee1.w = fmaf(e0, w1[0].w, ee1.w);
            ee0.x = fmaf(e1, w0[1].x, ee0.x); ee0.y = fmaf(e1, w0[1].y, ee0.y);
            ee0.z = fmaf(e1, w0[1].z, ee0.z); ee0.w = fmaf(e1, w0[1].w, ee0.w);
            ee1.x = fmaf(e1, w1[1].x, ee1.x); ee1.y = fmaf(e1, w1[1].y, ee1.y);
            ee1.z = fmaf(e1, w1[1].z, ee1.z); ee1.w = fmaf(e1, w1[1].w, ee1.w);
            ee0.x = fmaf(e2, w0[2].x, ee0.x); ee0.y = fmaf(e2, w0[2].y, ee0.y);
            ee0.z = fmaf(e2, w0[2].z, ee0.z); ee0.w = fmaf(e2, w0[2].w, ee0.w);
            ee1.x = fmaf(e2, w1[2].x, ee1.x); ee1.y = fmaf(e2, w1[2].y, ee1.y);
            ee1.z = fmaf(e2, w1[2].z, ee1.z); ee1.w = fmaf(e2, w1[2].w, ee1.w);
            ee0.x = fmaf(e3, w0[3].x, ee0.x); ee0.y = fmaf(e3, w0[3].y, ee0.y);
            ee0.z = fmaf(e3, w0[3].z, ee0.z); ee0.w = fmaf(e3, w0[3].w, ee0.w);
            ee1.x = fmaf(e3, w1[3].x, ee1.x); ee1.y = fmaf(e3, w1[3].y, ee1.y);
            ee1.z = fmaf(e3, w1[3].z, ee1.z); ee1.w = fmaf(e3, w1[3].w, ee1.w);
            ee0.x = fmaf(e4, w0[4].x, ee0.x); ee0.y = fmaf(e4, w0[4].y, ee0.y);
            ee0.z = fmaf(e4, w0[4].z, ee0.z); ee0.w = fmaf(e4, w0[4].w, ee0.w);
            ee1.x = fmaf(e4, w1[4].x, ee1.x); ee1.y = fmaf(e4, w1[4].y, ee1.y);
            ee1.z = fmaf(e4, w1[4].z, ee1.z); ee1.w = fmaf(e4, w1[4].w, ee1.w);
            ee0.x = fmaf(e5, w0[5].x, ee0.x); ee0.y = fmaf(e5, w0[5].y, ee0.y);
            ee0.z = fmaf(e5, w0[5].z, ee0.z); ee0.w = fmaf(e5, w0[5].w, ee0.w);
            ee1.x = fmaf(e5, w1[5].x, ee1.x); ee1.y = fmaf(e5, w1[5].y, ee1.y);
            ee1.z = fmaf(e5, w1[5].z, ee1.z); ee1.w = fmaf(e5, w1[5].w, ee1.w);

            const uint2* hp = (const uint2*)(h + (size_t)s * HID);
            float4 h0 = h4load(hp, lane);
            float4 h1 = h4load(hp, 32 + lane);
            a0.x += fmaxf(h0.x + ee0.x, 0.f); a0.y += fmaxf(h0.y + ee0.y, 0.f);
            a0.z += fmaxf(h0.z + ee0.z, 0.f); a0.w += fmaxf(h0.w + ee0.w, 0.f);
            a1.x += fmaxf(h1.x + ee1.x, 0.f); a1.y += fmaxf(h1.y + ee1.y, 0.f);
            a1.z += fmaxf(h1.z + ee1.z, 0.f); a1.w += fmaxf(h1.w + ee1.w, 0.f);
        }
        __half2* ap = (__half2*)(aeffh + (size_t)n * HID);
        ap[lane * 2]          = __floats2half2_rn(a0.x, a0.y);
        ap[lane * 2 + 1]      = __floats2half2_rn(a0.z, a0.w);
        ap[64 + lane * 2]     = __floats2half2_rn(a1.x, a1.y);
        ap[64 + lane * 2 + 1] = __floats2half2_rn(a1.z, a1.w);
    }
}

// ---------------- attention score (half s1) -------------------------------------
__global__ void attn_score_kernel(const __half* __restrict__ s1,
                                  const float* __restrict__ w2,
                                  const float* __restrict__ b2,
                                  const int* __restrict__ batch,
                                  float* __restrict__ wexp,
                                  float* __restrict__ wsum)
{
    int row = (blockIdx.x * blockDim.x + threadIdx.x) >> 5;
    int lane = threadIdx.x & 31;
    if (row >= NNODES) return;
    const __half2* s = (const __half2*)(s1 + (size_t)row * EDIM);
    float acc = 0.f;
#pragma unroll
    for (int k = lane; k < EDIM / 2; k += 32) {
        float2 f = __half22float2(__ldg(s + k));
        acc = fmaf(f.x, __ldg(w2 + 2 * k), acc);
        acc = fmaf(f.y, __ldg(w2 + 2 * k + 1), acc);
    }
#pragma unroll
    for (int o = 16; o > 0; o >>= 1) acc += __shfl_down_sync(0xffffffffu, acc, o);
    if (lane == 0) {
        float w = expf(acc + __ldg(b2));
        wexp[row] = w;
        atomicAdd(&wsum[__ldg(batch + row)], w);
    }
}

// ---------------- pooling (half h) ----------------------------------------------
__global__ void pool_graph_kernel(const __half* __restrict__ h,
                                  const float* __restrict__ wexp,
                                  const float* __restrict__ wsum,
                                  const int* __restrict__ gstart,
                                  const float* __restrict__ cnt,
                                  float* __restrict__ out)
{
    int g = blockIdx.x;
    int c = threadIdx.x;
    int lo = gstart[g], hi = gstart[g + 1];
    float inv_ws = 1.0f / (wsum[g] + 1e-8f);
    float s = 0.f, mx = 0.f, att = 0.f;
    for (int n = lo; n < hi; n++) {
        float v = __half2float(__ldg(h + (size_t)n * HID + c));
        float coeff = __ldg(wexp + n) * inv_ws;
        s += v;
        mx = fmaxf(mx, v);
        att = fmaf(v, coeff, att);
    }
    float* og = out + (size_t)g * (3 * HID);
    og[c] = s / cnt[g];
    og[HID + c] = mx;
    og[2 * HID + c] = att;
}

// ---------------- host launch --------------------------------------------------------
extern "C" void kernel_launch(void* const* d_in, const int* in_sizes, int n_in,
                              void* d_out, int out_size)
{
    const float* x         = (const float*)d_in[0];
    const float* edge_attr = (const float*)d_in[1];
    const float* node_w    = (const float*)d_in[2];
    const float* node_b    = (const float*)d_in[3];
    const float* edge_w    = (const float*)d_in[4];
    const float* edge_b    = (const float*)d_in[5];
    const float* conv_w    = (const float*)d_in[6];
    const float* conv_b    = (const float*)d_in[7];
    const float* mlp_w1    = (const float*)d_in[8];
    const float* mlp_b1    = (const float*)d_in[9];
    const float* mlp_w2    = (const float*)d_in[10];
    const float* mlp_b2    = (const float*)d_in[11];
    const float* eps       = (const float*)d_in[12];
    const float* bn_gamma  = (const float*)d_in[13];
    const float* bn_beta   = (const float*)d_in[14];
    const float* att_w1    = (const float*)d_in[15];
    const float* att_b1    = (const float*)d_in[16];
    const float* att_w2    = (const float*)d_in[17];
    const float* att_b2    = (const float*)d_in[18];
    const int*   edge_index= (const int*)d_in[19];
    const int*   batch     = (const int*)d_in[20];
    float* out = (float*)d_out;
    (void)bn_beta;   // cancels exactly under PairNorm centering

    const int* src = edge_index;
    const int* dst = edge_index + NEDGES;

    const int HG_SMEM_128 = 2 * HA_TILE_BYTES + 2 * 32 * (128 + 4) * 4;

    cudaFuncSetAttribute(tf32_gemm_h, cudaFuncAttributeMaxDynamicSharedMemorySize, GEMM_SMEM_BYTES);
    cudaFuncSetAttribute(fused_mlp, cudaFuncAttributeMaxDynamicSharedMemorySize, FUSED_SMEM);
    cudaFuncSetAttribute(hgemm_att, cudaFuncAttributeMaxDynamicSharedMemorySize, HG_SMEM_128);

    float *p_stats, *p_gsum, *p_gsq, *p_cnt, *p_wexp, *p_wsum, *p_wf;
    __half *p_hh0, *p_hh1, *p_zh, *p_aeffh, *p_s1h;
    __half2 *p_w1p, *p_w2p, *p_w1a;
    int *p_deg, *p_bsum, *p_boffs, *p_rowstart, *p_cursor, *p_eid, *p_csrc, *p_gstart;
    cudaGetSymbolAddress((void**)&p_hh0, g_hh0);
    cudaGetSymbolAddress((void**)&p_hh1, g_hh1);
    cudaGetSymbolAddress((void**)&p_zh, g_zh);
    cudaGetSymbolAddress((void**)&p_aeffh, g_aeffh);
    cudaGetSymbolAddress((void**)&p_s1h, g_s1h);
    cudaGetSymbolAddress((void**)&p_w1p, g_w1p);
    cudaGetSymbolAddress((void**)&p_w2p, g_w2p);
    cudaGetSymbolAddress((void**)&p_w1a, g_w1a);
    cudaGetSymbolAddress((void**)&p_stats, g_stats);
    cudaGetSymbolAddress((void**)&p_gsum, g_gsum);
    cudaGetSymbolAddress((void**)&p_gsq, g_gsq);
    cudaGetSymbolAddress((void**)&p_cnt, g_cnt);
    cudaGetSymbolAddress((void**)&p_wexp, g_wexp);
    cudaGetSymbolAddress((void**)&p_wsum, g_wsum);
    cudaGetSymbolAddress((void**)&p_wf, g_wf);
    cudaGetSymbolAddress((void**)&p_deg, g_deg);
    cudaGetSymbolAddress((void**)&p_bsum, g_bsum);
    cudaGetSymbolAddress((void**)&p_boffs, g_boffs);
    cudaGetSymbolAddress((void**)&p_rowstart, g_rowstart);
    cudaGetSymbolAddress((void**)&p_cursor, g_cursor);
    cudaGetSymbolAddress((void**)&p_eid, g_csr_eid);
    cudaGetSymbolAddress((void**)&p_csrc, g_csr_src);
    cudaGetSymbolAddress((void**)&p_gstart, g_gstart);

    // ----- CSR build (parallel scan)
    cudaMemsetAsync(p_deg, 0, NNODES * sizeof(int));
    deg_kernel<<<(NEDGES + 255) / 256, 256>>>(dst, p_deg);
    deg_bsum_kernel<<<NBLKD, 256>>>(p_deg, p_bsum);
    bscan_kernel<<<1, 512>>>(p_bsum, p_boffs);
    rowfill_kernel<<<NBLKD, 256>>>(p_deg, p_boffs, p_rowstart, p_cursor);
    csr_fill_kernel<<<(NEDGES + 255) / 256, 256>>>(src, dst, p_cursor, p_eid, p_csrc);

    // ----- graph ranges + counts
    cudaMemsetAsync(p_gstart, 0x7F, (NGRAPH + 1) * sizeof(int));
    gstart_min_kernel<<<(NNODES + 255) / 256, 256>>>(batch, p_gstart);
    gstart_fix_kernel<<<1, 1024>>>(p_gstart, p_cnt);

    // ----- weight prep
    wfuse_kernel<<<dim3(NLAYER, 7), HID>>>(edge_w, edge_b, conv_w, conv_b, p_wf);
    wpack_kernel<<<(NLAYER * 128 * 256) / 256, 256>>>(mlp_w1, mlp_w2, p_w1p, p_w2p);
    wpack_att_kernel<<<(128 * 128) / 256, 256>>>(att_w1, p_w1a);

    // ----- node embedding (tf32, half output)
    {
        dim3 grid(HID / 128, (NNODES + 127) / 128);
        tf32_gemm_h<<<grid, 256, GEMM_SMEM_BYTES>>>(NNODES, HID, NODE_F, x, node_w,
                                                    node_b, p_hh0);
    }

    __half* h_cur = p_hh0;
    __half* h_nxt = p_hh1;
    const int mgrid = (NNODES + 127) / 128;

    for (int i = 0; i < NLAYER; i++) {
        gine_gather_fused<<<1024, 256>>>(
            h_cur, edge_attr, p_rowstart, p_eid, p_csrc,
            p_wf + (size_t)i * 7 * HID, eps + i, p_aeffh, p_stats, p_gsum, p_gsq);

        fused_mlp<<<mgrid, 512, FUSED_SMEM>>>(
            NNODES, p_aeffh,
            p_w1p + (size_t)i * 32768, p_w2p + (size_t)i * 32768,
            mlp_b1 + (size_t)i * HID, mlp_b2 + (size_t)i * HID,
            batch, p_gsum, p_gsq, p_stats, p_zh);

        msq_norm_kernel<<<NGRAPH, HID>>>(p_stats, bn_gamma + (size_t)i * HID,
                                         p_cnt, p_gsum, p_gsq, p_gstart, p_zh, h_nxt);

        __half* t = h_cur; h_cur = h_nxt; h_nxt = t;
    }

    // attention hidden: s1 = tanh(h @ att_w1 + att_b1)
    {
        dim3 agrid(1, (NNODES + 127) / 128);
        hgemm_att<<<agrid, 256, HG_SMEM_128>>>(NNODES, h_cur, p_w1a, att_b1, p_s1h);
    }

    cudaMemsetAsync(p_wsum, 0, NGRAPH * sizeof(float));
    attn_score_kernel<<<(NNODES * 32 + 255) / 256, 256>>>(p_s1h, att_w2, att_b2, batch, p_wexp, p_wsum);

    pool_graph_kernel<<<NGRAPH, HID>>>(h_cur, p_wexp, p_wsum, p_gstart, p_cnt, out);

    (void)in_sizes; (void)n_in; (void)out_size;
}

// round 10
// speedup vs baseline: 6.3587x; 1.0266x over previous
#include <cuda_runtime.h>
#include <cuda_fp16.h>
#include <math.h>
#include <stdint.h>

#define NNODES 100000
#define NEDGES 320000
#define NGRAPH 2048
#define HID    256
#define EDIM   128
#define NODE_F 48
#define EDGE_F 6
#define NLAYER 8
#define NBLKD  ((NNODES + 255) / 256)   // 391

// ---------------- scratch (device globals) ----------------------------------
__device__ __half  g_hh0[(size_t)NNODES * HID];
__device__ __half  g_hh1[(size_t)NNODES * HID];
__device__ __half  g_zh [(size_t)NNODES * HID];
__device__ __half  g_aeffh[(size_t)NNODES * HID];
__device__ __half  g_s1h [(size_t)NNODES * EDIM];
__device__ __half2 g_w1p[(size_t)NLAYER * (HID / 2) * HID];
__device__ __half2 g_w2p[(size_t)NLAYER * (HID / 2) * HID];
__device__ __half2 g_w1a[(size_t)(HID / 2) * EDIM];
__device__ float   g_stats[2 * HID];
__device__ float   g_gsum[(size_t)NGRAPH * HID];
__device__ float   g_gsq [(size_t)NGRAPH * HID];
__device__ float   g_cnt [NGRAPH];
__device__ float   g_wf  [(size_t)NLAYER * 7 * HID];
__device__ int     g_deg [NNODES];
__device__ int     g_bsum[NBLKD];
__device__ int     g_boffs[NBLKD];
__device__ int     g_rowstart[NNODES + 1];
__device__ int     g_cursor[NNODES];
__device__ int     g_csr_eid[NEDGES];
__device__ int     g_csr_src[NEDGES];
__device__ int     g_gstart[NGRAPH + 1];

// ---------------- common helpers ---------------------------------------------
__device__ __forceinline__ uint32_t f2tf32(float x) {
    uint32_t r;
    asm volatile("cvt.rna.tf32.f32 %0, %1;" : "=r"(r) : "f"(x));
    return r;
}
__device__ __forceinline__ void cp16s(uint32_t d, const void* src, bool pred) {
    int sz = pred ? 16 : 0;
    asm volatile("cp.async.cg.shared.global [%0], [%1], 16, %2;" :: "r"(d), "l"(src), "r"(sz));
}
__device__ __forceinline__ void cp_commit() { asm volatile("cp.async.commit_group;"); }
template <int Np>
__device__ __forceinline__ void cp_wait() { asm volatile("cp.async.wait_group %0;" :: "n"(Np)); }
__device__ __forceinline__ void mma_f16(float* c, const uint32_t* a, const uint32_t* b) {
    asm volatile(
        "mma.sync.aligned.m16n8k16.row.col.f32.f16.f16.f32 "
        "{%0,%1,%2,%3}, {%4,%5,%6,%7}, {%8,%9}, {%0,%1,%2,%3};"
        : "+f"(c[0]), "+f"(c[1]), "+f"(c[2]), "+f"(c[3])
        : "r"(a[0]), "r"(a[1]), "r"(a[2]), "r"(a[3]), "r"(b[0]), "r"(b[1]));
}
__device__ __forceinline__ void ldsm4(uint32_t* r, uint32_t addr) {
    asm volatile("ldmatrix.sync.aligned.m8n8.x4.shared.b16 {%0,%1,%2,%3}, [%4];"
                 : "=r"(r[0]), "=r"(r[1]), "=r"(r[2]), "=r"(r[3]) : "r"(addr));
}

extern __shared__ char smemc[];

// ===================== fused MLP + stats ========================================
#define FA_STRIDE 72
#define FA_TILE_BYTES (128 * FA_STRIDE * 2)
#define FB2_STRIDE 260
#define FB_TILE2 (32 * FB2_STRIDE)
#define FTMP_STRIDE 264
#define OFF_B (2 * FA_TILE_BYTES)
#define OFF_TMP (OFF_B + 2 * FB_TILE2 * 4)
#define FUSED_SMEM (OFF_TMP + 128 * FTMP_STRIDE * 2)   // 171008

__global__ __launch_bounds__(512, 1) void fused_mlp(
    int M, const __half* __restrict__ A,
    const __half2* __restrict__ W1p, const __half2* __restrict__ W2p,
    const float* __restrict__ b1, const float* __restrict__ b2,
    const int* __restrict__ batchp,
    float* __restrict__ gsum, float* __restrict__ gsq, float* __restrict__ stats,
    __half* __restrict__ Z)
{
    uint32_t sb = (uint32_t)__cvta_generic_to_shared(smemc);
    const __half2* hB = (const __half2*)(smemc + OFF_B);
    __half* tmp = (__half*)(smemc + OFF_TMP);
    uint32_t sbT = sb + OFF_TMP;

    const int tid = threadIdx.x;
    const int warp = tid >> 5;
    const int lane = tid & 31;
    const int g = lane >> 2;
    const int tq = lane & 3;
    const int m0 = blockIdx.x * 128;
    const int wm = (warp & 3) * 32;
    const int wn = (warp >> 2) * 64;
    const int lrow = ((lane >> 3) & 1) * 8 + (lane & 7);
    const int lcol = (lane >> 4) * 8;

    float acc[2][8][4];
#pragma unroll
    for (int i = 0; i < 2; i++)
#pragma unroll
        for (int j = 0; j < 8; j++)
#pragma unroll
            for (int r = 0; r < 4; r++) acc[i][j][r] = 0.0f;

    auto fillA = [&](int buf, int k0) {
#pragma unroll
        for (int it = 0; it < 2; it++) {
            int chunk = tid + it * 512;
            int r = chunk >> 3, c = (chunk & 7) * 8;
            bool p = (m0 + r) < M;
            cp16s(sb + buf * FA_TILE_BYTES + (r * FA_STRIDE + c) * 2,
                  A + (size_t)(p ? m0 + r : 0) * 256 + k0 + c, p);
        }
    };
    auto fillB = [&](int buf, int k0, const __half2* W) {
#pragma unroll
        for (int it = 0; it < 4; it++) {
            int chunk = tid + it * 512;
            int pr = chunk >> 6, c2 = (chunk & 63) * 4;
            cp16s(sb + OFF_B + (buf * FB_TILE2 + pr * FB2_STRIDE + c2) * 4,
                  W + (size_t)((k0 >> 1) + pr) * 256 + c2, true);
        }
    };

    // phase 1: acc = A @ W1
    fillA(0, 0);
    fillB(0, 0, W1p);
    cp_commit();

    int buf = 0;
#pragma unroll 1
    for (int i = 0; i < 4; i++) {
        if (i < 3) {
            fillA(buf ^ 1, (i + 1) * 64);
            fillB(buf ^ 1, (i + 1) * 64, W1p);
        } else {
            fillB(buf ^ 1, 0, W2p);
        }
        cp_commit();
        cp_wait<1>();
        __syncthreads();

        uint32_t abase = sb + buf * FA_TILE_BYTES;
        const __half2* Bb = hB + buf * FB_TILE2;
#pragma unroll
        for (int kk = 0; kk < 4; kk++) {
            uint32_t af[2][4];
#pragma unroll
            for (int mi = 0; mi < 2; mi++)
                ldsm4(af[mi], abase + ((wm + mi * 16 + lrow) * FA_STRIDE + kk * 16 + lcol) * 2);
            uint32_t bf[8][2];
#pragma unroll
            for (int ni = 0; ni < 8; ni++) {
                const __half2* p = Bb + (kk * 8 + tq) * FB2_STRIDE + wn + ni * 8 + g;
                bf[ni][0] = *(const uint32_t*)(p);
                bf[ni][1] = *(const uint32_t*)(p + 4 * FB2_STRIDE);
            }
#pragma unroll
            for (int mi = 0; mi < 2; mi++)
#pragma unroll
                for (int ni = 0; ni < 8; ni++)
                    mma_f16(acc[mi][ni], af[mi], bf[ni]);
        }
        __syncthreads();
        buf ^= 1;
    }

    if (tid < 128)
        ((int*)smemc)[tid] = (m0 + tid < M) ? __ldg(batchp + m0 + tid) : 0;

    // phase 1 epilogue: tmp = relu(acc + b1)
#pragma unroll
    for (int mi = 0; mi < 2; mi++) {
        int r0 = wm + mi * 16 + g;
        int r1 = r0 + 8;
#pragma unroll
        for (int ni = 0; ni < 8; ni++) {
            int col = wn + ni * 8 + tq * 2;
            float c0 = __ldg(b1 + col);
            float c1 = __ldg(b1 + col + 1);
            float v0 = fmaxf(acc[mi][ni][0] + c0, 0.f);
            float v1 = fmaxf(acc[mi][ni][1] + c1, 0.f);
            float v2 = fmaxf(acc[mi][ni][2] + c0, 0.f);
            float v3 = fmaxf(acc[mi][ni][3] + c1, 0.f);
            *(__half2*)(tmp + r0 * FTMP_STRIDE + col) = __floats2half2_rn(v0, v1);
            *(__half2*)(tmp + r1 * FTMP_STRIDE + col) = __floats2half2_rn(v2, v3);
            acc[mi][ni][0] = 0.f; acc[mi][ni][1] = 0.f;
            acc[mi][ni][2] = 0.f; acc[mi][ni][3] = 0.f;
        }
    }

    // phase 2: acc = tmp @ W2
#pragma unroll 1
    for (int i = 0; i < 4; i++) {
        if (i < 3) {
            fillB(buf ^ 1, (i + 1) * 64, W2p);
            cp_commit();
            cp_wait<1>();
        } else {
            cp_wait<0>();
        }
        __syncthreads();

        const __half2* Bb = hB + buf * FB_TILE2;
#pragma unroll
        for (int kk = 0; kk < 4; kk++) {
            uint32_t af[2][4];
#pragma unroll
            for (int mi = 0; mi < 2; mi++)
                ldsm4(af[mi], sbT + ((wm + mi * 16 + lrow) * FTMP_STRIDE + i * 64 + kk * 16 + lcol) * 2);
            uint32_t bf[8][2];
#pragma unroll
            for (int ni = 0; ni < 8; ni++) {
                const __half2* p = Bb + (kk * 8 + tq) * FB2_STRIDE + wn + ni * 8 + g;
                bf[ni][0] = *(const uint32_t*)(p);
                bf[ni][1] = *(const uint32_t*)(p + 4 * FB2_STRIDE);
            }
#pragma unroll
            for (int mi = 0; mi < 2; mi++)
#pragma unroll
                for (int ni = 0; ni < 8; ni++)
                    mma_f16(acc[mi][ni], af[mi], bf[ni]);
        }
        __syncthreads();
        buf ^= 1;
    }

    // phase 2 epilogue: Z(global) + z(tmp smem)
#pragma unroll
    for (int mi = 0; mi < 2; mi++) {
        int rr0 = wm + mi * 16 + g;
        int rr1 = rr0 + 8;
        int r0 = m0 + rr0;
        int r1 = m0 + rr1;
#pragma unroll
        for (int ni = 0; ni < 8; ni++) {
            int col = wn + ni * 8 + tq * 2;
            float c0 = __ldg(b2 + col);
            float c1 = __ldg(b2 + col + 1);
            __half2 z0 = __floats2half2_rn(acc[mi][ni][0] + c0, acc[mi][ni][1] + c1);
            __half2 z1 = __floats2half2_rn(acc[mi][ni][2] + c0, acc[mi][ni][3] + c1);
            *(__half2*)(tmp + rr0 * FTMP_STRIDE + col) = z0;
            *(__half2*)(tmp + rr1 * FTMP_STRIDE + col) = z1;
            if (r0 < M) *(__half2*)(Z + (size_t)r0 * 256 + col) = z0;
            if (r1 < M) *(__half2*)(Z + (size_t)r1 * 256 + col) = z1;
        }
    }
    __syncthreads();

    // phase 3: per-graph + chip stats from smem z
    {
        const int c = tid & 255;
        const int rbeg = (tid >> 8) * 64;
        const int* sbatch = (const int*)smemc;
        float ts = 0.f, tqs = 0.f;
        int curg = -1;
        float s = 0.f, q = 0.f;
        for (int r = rbeg; r < rbeg + 64; r++) {
            if (m0 + r >= M) break;
            int gg = sbatch[r];
            if (gg != curg) {
                if (curg >= 0) {
                    atomicAdd(gsum + (size_t)curg * 256 + c, s);
                    atomicAdd(gsq + (size_t)curg * 256 + c, q);
                }
                curg = gg; s = 0.f; q = 0.f;
            }
            float v = __half2float(tmp[r * FTMP_STRIDE + c]);
            s += v; q = fmaf(v, v, q);
            ts += v; tqs = fmaf(v, v, tqs);
        }
        if (curg >= 0) {
            atomicAdd(gsum + (size_t)curg * 256 + c, s);
            atomicAdd(gsq + (size_t)curg * 256 + c, q);
        }
        atomicAdd(stats + c, ts);
        atomicAdd(stats + 256 + c, tqs);
    }
}

// ===================== merged msq + normalize (block per graph) ================
__global__ void msq_norm_kernel(const float* __restrict__ stats,
                                const float* __restrict__ gamma,
                                const float* __restrict__ cnt,
                                const float* __restrict__ gsum,
                                const float* __restrict__ gsq,
                                const int* __restrict__ gstart,
                                const __half* __restrict__ zh,
                                __half* __restrict__ hout)
{
    __shared__ float red[HID];
    int gb = blockIdx.x;
    int c = threadIdx.x;
    const float invN = 1.0f / (float)NNODES;
    float mu = __ldg(stats + c) * invN;
    float var = __ldg(stats + HID + c) * invN - mu * mu;
    float ac = __ldg(gamma + c) * rsqrtf(var + 1e-5f);
    float cg = cnt[gb];
    size_t gi = (size_t)gb * HID + c;
    float S = gsum[gi], Q = gsq[gi];
    float m = S / cg;
    red[c] = ac * ac * (Q - cg * m * m);
    __syncthreads();
    for (int o = HID / 2; o > 0; o >>= 1) {
        if (c < o) red[c] += red[c + o];
        __syncthreads();
    }
    float sc = rsqrtf(1e-5f + red[0] / cg);
    int lo = gstart[gb], hi = gstart[gb + 1];
    float acs = ac * sc;
    for (int n = lo; n < hi; n++) {
        size_t i = (size_t)n * HID + c;
        float v = acs * (__half2float(zh[i]) - m);
        hout[i] = __float2half(fmaxf(v, 0.f));
    }
}

// ===================== fp16 GEMM (attention, tanh) =============================
#define HA_STRIDE 72
#define HA_TILE_BYTES (128 * HA_STRIDE * 2)

__global__ __launch_bounds__(256, 2) void hgemm_att(
    int M, const __half* __restrict__ A, const __half2* __restrict__ Bp,
    const float* __restrict__ bias, __half* __restrict__ Ch)
{
    constexpr int WN = 128;
    constexpr int HB2_STRIDE = WN + 4;
    constexpr int HB_TILE2 = 32 * HB2_STRIDE;
    const __half2* hB = (const __half2*)(smemc + 2 * HA_TILE_BYTES);
    uint32_t sb = (uint32_t)__cvta_generic_to_shared(smemc);
    uint32_t sbB = sb + 2 * HA_TILE_BYTES;

    const int tid = threadIdx.x;
    const int warp = tid >> 5;
    const int lane = tid & 31;
    const int g = lane >> 2;
    const int tq = lane & 3;
    const int m0 = blockIdx.y * 128;
    const int wm = (warp >> 1) * 32;
    const int wn = (warp & 1) * 64;
    const int lrow = ((lane >> 3) & 1) * 8 + (lane & 7);
    const int lcol = (lane >> 4) * 8;

    float acc[2][8][4];
#pragma unroll
    for (int i = 0; i < 2; i++)
#pragma unroll
        for (int j = 0; j < 8; j++)
#pragma unroll
            for (int r = 0; r < 4; r++) acc[i][j][r] = 0.0f;

    auto fillA = [&](int buf, int k0) {
#pragma unroll
        for (int it = 0; it < 4; it++) {
            int chunk = tid + it * 256;
            int r = chunk >> 3, c = (chunk & 7) * 8;
            bool p = (m0 + r) < M;
            cp16s(sb + buf * HA_TILE_BYTES + (r * HA_STRIDE + c) * 2,
                  A + (size_t)(p ? m0 + r : 0) * 256 + k0 + c, p);
        }
    };
    auto fillB = [&](int buf, int k0) {
#pragma unroll
        for (int it = 0; it < 4; it++) {
            int chunk = tid + it * 256;
            int pr = chunk >> 5, c2 = (chunk & 31) * 4;
            cp16s(sbB + (buf * HB_TILE2 + pr * HB2_STRIDE + c2) * 4,
                  Bp + (size_t)((k0 >> 1) + pr) * WN + c2, true);
        }
    };

    fillA(0, 0);
    fillB(0, 0);
    cp_commit();

    int buf = 0;
#pragma unroll 1
    for (int i = 0; i < 4; i++) {
        if (i + 1 < 4) {
            fillA(buf ^ 1, (i + 1) * 64);
            fillB(buf ^ 1, (i + 1) * 64);
            cp_commit();
            cp_wait<1>();
        } else {
            cp_wait<0>();
        }
        __syncthreads();

        uint32_t abase = sb + buf * HA_TILE_BYTES;
        const __half2* Bb = hB + buf * HB_TILE2;
#pragma unroll
        for (int kk = 0; kk < 4; kk++) {
            uint32_t af[2][4];
#pragma unroll
            for (int mi = 0; mi < 2; mi++)
                ldsm4(af[mi], abase + ((wm + mi * 16 + lrow) * HA_STRIDE + kk * 16 + lcol) * 2);
            uint32_t bf[8][2];
#pragma unroll
            for (int ni = 0; ni < 8; ni++) {
                const __half2* p = Bb + (kk * 8 + tq) * HB2_STRIDE + wn + ni * 8 + g;
                bf[ni][0] = *(const uint32_t*)(p);
                bf[ni][1] = *(const uint32_t*)(p + 4 * HB2_STRIDE);
            }
#pragma unroll
            for (int mi = 0; mi < 2; mi++)
#pragma unroll
                for (int ni = 0; ni < 8; ni++)
                    mma_f16(acc[mi][ni], af[mi], bf[ni]);
        }
        __syncthreads();
        buf ^= 1;
    }

#pragma unroll
    for (int mi = 0; mi < 2; mi++) {
        int r0 = m0 + wm + mi * 16 + g;
        int r1 = r0 + 8;
#pragma unroll
        for (int ni = 0; ni < 8; ni++) {
            int col = wn + ni * 8 + tq * 2;
            float b0 = __ldg(bias + col);
            float b1 = __ldg(bias + col + 1);
            float v0 = tanhf(acc[mi][ni][0] + b0);
            float v1 = tanhf(acc[mi][ni][1] + b1);
            float v2 = tanhf(acc[mi][ni][2] + b0);
            float v3 = tanhf(acc[mi][ni][3] + b1);
            if (r0 < M) *(__half2*)(Ch + (size_t)r0 * WN + col) = __floats2half2_rn(v0, v1);
            if (r1 < M) *(__half2*)(Ch + (size_t)r1 * WN + col) = __floats2half2_rn(v2, v3);
        }
    }
}

// ---------------- weight packs ---------------------------------------------------
__global__ void wpack_kernel(const float* __restrict__ w1, const float* __restrict__ w2,
                             __half2* __restrict__ w1p, __half2* __restrict__ w2p)
{
    int idx = blockIdx.x * 256 + threadIdx.x;
    int l = idx >> 15;
    int rem = idx & 32767;
    int p = rem >> 8;
    int n = rem & 255;
    size_t base = (size_t)l * 65536 + (size_t)(2 * p) * 256 + n;
    w1p[idx] = __floats2half2_rn(__ldg(w1 + base), __ldg(w1 + base + 256));
    w2p[idx] = __floats2half2_rn(__ldg(w2 + base), __ldg(w2 + base + 256));
}
__global__ void wpack_att_kernel(const float* __restrict__ w, __half2* __restrict__ wp)
{
    int idx = blockIdx.x * 256 + threadIdx.x;
    int p = idx >> 7;
    int n = idx & 127;
    size_t base = (size_t)(2 * p) * 128 + n;
    wp[idx] = __floats2half2_rn(__ldg(w + base), __ldg(w + base + 128));
}

// ===================== mma.sync TF32 GEMM (node embed) ========================
#define GA_STRIDE 36
#define GB_STRIDE 132
#define A_TILE_W (128 * GA_STRIDE)
#define B_TILE_W (32 * GB_STRIDE)
#define GEMM_SMEM_BYTES ((2 * A_TILE_W + 2 * B_TILE_W) * 4)

__device__ __forceinline__ void cp16(float* dst, const float* src, bool pred) {
    cp16s((uint32_t)__cvta_generic_to_shared(dst), src, pred);
}
__device__ __forceinline__ void mma_tf32(float* c, const uint32_t* a, const uint32_t* b) {
    asm volatile(
        "mma.sync.aligned.m16n8k8.row.col.f32.tf32.tf32.f32 "
        "{%0,%1,%2,%3}, {%4,%5,%6,%7}, {%8,%9}, {%0,%1,%2,%3};"
        : "+f"(c[0]), "+f"(c[1]), "+f"(c[2]), "+f"(c[3])
        : "r"(a[0]), "r"(a[1]), "r"(a[2]), "r"(a[3]), "r"(b[0]), "r"(b[1]));
}

__global__ __launch_bounds__(256, 2) void tf32_gemm_h(
    int M, int N, int K,
    const float* __restrict__ A, const float* __restrict__ B,
    const float* __restrict__ bias, __half* __restrict__ Chh)
{
    float* sm = (float*)smemc;
    float* As = sm;
    float* Bs = sm + 2 * A_TILE_W;

    const int tid = threadIdx.x;
    const int warp = tid >> 5;
    const int lane = tid & 31;
    const int g = lane >> 2;
    const int tq = lane & 3;
    const int m0 = blockIdx.y * 128;
    const int n0 = blockIdx.x * 128;
    const int wm = (warp >> 1) * 32;
    const int wn = (warp & 1) * 64;

    float acc[2][8][4];
#pragma unroll
    for (int i = 0; i < 2; i++)
#pragma unroll
        for (int j = 0; j < 8; j++)
#pragma unroll
            for (int r = 0; r < 4; r++) acc[i][j][r] = 0.0f;

    const int arow = tid >> 3;
    const int ac4 = tid & 7;
    const int brow = tid >> 5;
    const int bc4 = tid & 31;
    const int nk = (K + 31) / 32;

    {
#pragma unroll
        for (int it = 0; it < 4; it++) {
            int row = arow + it * 32;
            int gm = m0 + row;
            int gk = ac4 * 4;
            bool p = (gm < M) && (gk < K);
            const float* src = A + (size_t)(p ? gm : 0) * K + (p ? gk : 0);
            cp16(As + row * GA_STRIDE + ac4 * 4, src, p);
        }
#pragma unroll
        for (int it = 0; it < 4; it++) {
            int row = brow + it * 8;
            bool p = (row < K);
            const float* src = B + (size_t)(p ? row : 0) * N + n0 + bc4 * 4;
            cp16(Bs + row * GB_STRIDE + bc4 * 4, src, p);
        }
        cp_commit();
    }

    int buf = 0;
    for (int i = 0; i < nk; i++) {
        if (i + 1 < nk) {
            const int kc = i + 1;
            float* Ad = As + (buf ^ 1) * A_TILE_W;
            float* Bd = Bs + (buf ^ 1) * B_TILE_W;
#pragma unroll
            for (int it = 0; it < 4; it++) {
                int row = arow + it * 32;
                int gm = m0 + row;
                int gk = kc * 32 + ac4 * 4;
                bool p = (gm < M) && (gk < K);
                const float* src = A + (size_t)(p ? gm : 0) * K + (p ? gk : 0);
                cp16(Ad + row * GA_STRIDE + ac4 * 4, src, p);
            }
#pragma unroll
            for (int it = 0; it < 4; it++) {
                int row = brow + it * 8;
                int gk = kc * 32 + row;
                bool p = (gk < K);
                const float* src = B + (size_t)(p ? gk : 0) * N + n0 + bc4 * 4;
                cp16(Bd + row * GB_STRIDE + bc4 * 4, src, p);
            }
            cp_commit();
            cp_wait<1>();
        } else {
            cp_wait<0>();
        }
        __syncthreads();

        const float* Ab = As + buf * A_TILE_W;
        const float* Bb = Bs + buf * B_TILE_W;
#pragma unroll
        for (int kk = 0; kk < 4; kk++) {
            const int k = kk * 8;
            uint32_t af[2][4];
#pragma unroll
            for (int mi = 0; mi < 2; mi++) {
                const float* p = Ab + (wm + mi * 16 + g) * GA_STRIDE + k + tq;
                af[mi][0] = f2tf32(p[0]);
                af[mi][1] = f2tf32(p[8 * GA_STRIDE]);
                af[mi][2] = f2tf32(p[4]);
                af[mi][3] = f2tf32(p[8 * GA_STRIDE + 4]);
            }
            uint32_t bf[8][2];
#pragma unroll
            for (int ni = 0; ni < 8; ni++) {
                const float* p = Bb + (k + tq) * GB_STRIDE + wn + ni * 8 + g;
                bf[ni][0] = f2tf32(p[0]);
                bf[ni][1] = f2tf32(p[4 * GB_STRIDE]);
            }
#pragma unroll
            for (int mi = 0; mi < 2; mi++)
#pragma unroll
                for (int ni = 0; ni < 8; ni++)
                    mma_tf32(acc[mi][ni], af[mi], bf[ni]);
        }
        __syncthreads();
        buf ^= 1;
    }

#pragma unroll
    for (int mi = 0; mi < 2; mi++) {
        int r0 = m0 + wm + mi * 16 + g;
        int r1 = r0 + 8;
#pragma unroll
        for (int ni = 0; ni < 8; ni++) {
            int col = n0 + wn + ni * 8 + tq * 2;
            float b0 = __ldg(bias + col);
            float b1 = __ldg(bias + col + 1);
            if (r0 < M) *(__half2*)(Chh + (size_t)r0 * N + col) =
                __floats2half2_rn(acc[mi][ni][0] + b0, acc[mi][ni][1] + b1);
            if (r1 < M) *(__half2*)(Chh + (size_t)r1 * N + col) =
                __floats2half2_rn(acc[mi][ni][2] + b0, acc[mi][ni][3] + b1);
        }
    }
}

// ---------------- fused edge weights ------------------------------------------
__global__ void wfuse_kernel(const float* __restrict__ edge_w,
                             const float* __restrict__ edge_b,
                             const float* __restrict__ conv_w,
                             const float* __restrict__ conv_b,
                             float* __restrict__ wf)
{
    int layer = blockIdx.x;
    int k = blockIdx.y;
    int c = threadIdx.x;
    const float* cw = conv_w + (size_t)layer * EDIM * HID;
    float s = 0.f;
    if (k < EDGE_F) {
        for (int j = 0; j < EDIM; j++)
            s = fmaf(__ldg(edge_w + k * EDIM + j), __ldg(cw + (size_t)j * HID + c), s);
    } else {
        for (int j = 0; j < EDIM; j++)
            s = fmaf(__ldg(edge_b + j), __ldg(cw + (size_t)j * HID + c), s);
        s += __ldg(conv_b + (size_t)layer * HID + c);
    }
    wf[((size_t)layer * 7 + k) * HID + c] = s;
}

// ---------------- CSR build (parallel scan) -------------------------------------
__global__ void deg_kernel(const int* __restrict__ dst, int* __restrict__ deg)
{
    int e = blockIdx.x * blockDim.x + threadIdx.x;
    if (e < NEDGES) atomicAdd(&deg[__ldg(dst + e)], 1);
}

__global__ void deg_bsum_kernel(const int* __restrict__ deg, int* __restrict__ bsum)
{
    __shared__ int sh[256];
    int i = blockIdx.x * 256 + threadIdx.x;
    sh[threadIdx.x] = (i < NNODES) ? deg[i] : 0;
    __syncthreads();
    for (int o = 128; o > 0; o >>= 1) {
        if (threadIdx.x < o) sh[threadIdx.x] += sh[threadIdx.x + o];
        __syncthreads();
    }
    if (threadIdx.x == 0) bsum[blockIdx.x] = sh[0];
}

__global__ void bscan_kernel(const int* __restrict__ bsum, int* __restrict__ boffs)
{
    __shared__ int sh[512];
    int t = threadIdx.x;
    int mine = (t < NBLKD) ? bsum[t] : 0;
    sh[t] = mine;
    __syncthreads();
    for (int o = 1; o < 512; o <<= 1) {
        int v = (t >= o) ? sh[t - o] : 0;
        __syncthreads();
        sh[t] += v;
        __syncthreads();
    }
    if (t < NBLKD) boffs[t] = sh[t] - mine;
}

__global__ void rowfill_kernel(const int* __restrict__ deg, const int* __restrict__ boffs,
                               int* __restrict__ rowstart, int* __restrict__ cursor)
{
    __shared__ int sh[256];
    int b = blockIdx.x, t = threadIdx.x;
    int i = b * 256 + t;
    int d = (i < NNODES) ? deg[i] : 0;
    sh[t] = d;
    __syncthreads();
    for (int o = 1; o < 256; o <<= 1) {
        int v = (t >= o) ? sh[t - o] : 0;
        __syncthreads();
        sh[t] += v;
        __syncthreads();
    }
    if (i < NNODES) {
        int rs = boffs[b] + sh[t] - d;
        rowstart[i] = rs;
        cursor[i] = rs;
    }
    if (i == NNODES - 1) rowstart[NNODES] = NEDGES;
}

__global__ void csr_fill_kernel(const int* __restrict__ src,
                                const int* __restrict__ dst,
                                int* __restrict__ cursor,
                                int* __restrict__ csr_eid,
                                int* __restrict__ csr_src)
{
    int e = blockIdx.x * blockDim.x + threadIdx.x;
    if (e >= NEDGES) return;
    int d = __ldg(dst + e);
    int p = atomicAdd(&cursor[d], 1);
    csr_eid[p] = e;
    csr_src[p] = __ldg(src + e);
}

// ---------------- graph ranges --------------------------------------------------
__global__ void gstart_min_kernel(const int* __restrict__ batch, int* __restrict__ gstart)
{
    int n = blockIdx.x * blockDim.x + threadIdx.x;
    if (n < NNODES) atomicMin(&gstart[__ldg(batch + n)], n);
}

__global__ void gstart_fix_kernel(int* __restrict__ gstart, float* __restrict__ cnt)
{
    __shared__ int sg[NGRAPH + 1];
    int t = threadIdx.x;
    for (int i = t; i <= NGRAPH; i += 1024) sg[i] = gstart[i];
    __syncthreads();
    if (t == 0) {
        sg[NGRAPH] = NNODES;
        for (int g2 = NGRAPH - 1; g2 >= 0; g2--)
            if (sg[g2] > sg[g2 + 1]) sg[g2] = sg[g2 + 1];
    }
    __syncthreads();
    for (int i = t; i <= NGRAPH; i += 1024) gstart[i] = sg[i];
    for (int i = t; i < NGRAPH; i += 1024)
        cnt[i] = fmaxf((float)(sg[i + 1] - sg[i]), 1.0f);
}

// ---------------- GINE gather v2: 64-thread node groups ------------------------
// Each 64-thread group handles one node; thread t covers channels 4t..4t+3.
__device__ __forceinline__ float4 h4load(const uint2* hp, int idx) {
    uint2 u = __ldg(hp + idx);
    float2 f0 = __half22float2(*(__half2*)&u.x);
    float2 f1 = __half22float2(*(__half2*)&u.y);
    return make_float4(f0.x, f0.y, f1.x, f1.y);
}

__global__ __launch_bounds__(256) void gine_gather_fused(
    const __half* __restrict__ h,
    const float* __restrict__ ea,
    const int* __restrict__ rowstart,
    const int* __restrict__ csr_eid,
    const int* __restrict__ csr_src,
    const float* __restrict__ wf,
    const float* __restrict__ eps_ptr,
    __half* __restrict__ aeffh,
    float* __restrict__ stats,
    float* __restrict__ gsum,
    float* __restrict__ gsq)
{
    {
        int gid = blockIdx.x * 256 + threadIdx.x;
        if (gid < 262144) {
            gsum[gid] = 0.f; gsum[gid + 262144] = 0.f;
            gsq[gid] = 0.f;  gsq[gid + 262144] = 0.f;
        }
        if (blockIdx.x == 0) {
            stats[threadIdx.x] = 0.f;
            stats[256 + threadIdx.x] = 0.f;
        }
    }

    const int t = threadIdx.x & 63;                         // channel quad
    const int group = (blockIdx.x * blockDim.x + threadIdx.x) >> 6;
    const int ngroups = (gridDim.x * blockDim.x) >> 6;
    const float alpha = 1.0f + __ldg(eps_ptr);

    float4 w[EDGE_F];
#pragma unroll
    for (int k = 0; k < EDGE_F; k++)
        w[k] = __ldg((const float4*)(wf + k * HID) + t);
    float4 bf = __ldg((const float4*)(wf + EDGE_F * HID) + t);

    for (int n = group; n < NNODES; n += ngroups) {
        float4 a = h4load((const uint2*)(h + (size_t)n * HID), t);
        a.x *= alpha; a.y *= alpha; a.z *= alpha; a.w *= alpha;

        int lo = __ldg(rowstart + n), hi = __ldg(rowstart + n + 1);
        for (int j = lo; j < hi; j++) {
            int eid = __ldg(csr_eid + j);
            int s = __ldg(csr_src + j);
            const float* er = ea + (size_t)eid * EDGE_F;
            float e0 = __ldg(er + 0), e1 = __ldg(er + 1), e2 = __ldg(er + 2);
            float e3 = __ldg(er + 3), e4 = __ldg(er + 4), e5 = __ldg(er + 5);

            float4 ee = bf;
            ee.x = fmaf(e0, w[0].x, ee.x); ee.y = fmaf(e0, w[0].y, ee.y);
            ee.z = fmaf(e0, w[0].z, ee.z); ee.w = fmaf(e0, w[0].w, ee.w);
            ee.x = fmaf(e1, w[1].x, ee.x); ee.y = fmaf(e1, w[1].y, ee.y);
            ee.z = fmaf(e1, w[1].z, ee.z); ee.w = fmaf(e1, w[1].w, ee.w);
            ee.x = fmaf(e2, w[2].x, ee.x); ee.y = fmaf(e2, w[2].y, ee.y);
            ee.z = fmaf(e2, w[2].z, ee.z); ee.w = fmaf(e2, w[2].w, ee.w);
            ee.x = fmaf(e3, w[3].x, ee.x); ee.y = fmaf(e3, w[3].y, ee.y);
            ee.z = fmaf(e3, w[3].z, ee.z); ee.w = fmaf(e3, w[3].w, ee.w);
            ee.x = fmaf(e4, w[4].x, ee.x); ee.y = fmaf(e4, w[4].y, ee.y);
            ee.z = fmaf(e4, w[4].z, ee.z); ee.w = fmaf(e4, w[4].w, ee.w);
            ee.x = fmaf(e5, w[5].x, ee.x); ee.y = fmaf(e5, w[5].y, ee.y);
            ee.z = fmaf(e5, w[5].z, ee.z); ee.w = fmaf(e5, w[5].w, ee.w);

            float4 hv = h4load((const uint2*)(h + (size_t)s * HID), t);
            a.x += fmaxf(hv.x + ee.x, 0.f);
            a.y += fmaxf(hv.y + ee.y, 0.f);
            a.z += fmaxf(hv.z + ee.z, 0.f);
            a.w += fmaxf(hv.w + ee.w, 0.f);
        }
        __half2* ap = (__half2*)(aeffh + (size_t)n * HID);
        ap[2 * t]     = __floats2half2_rn(a.x, a.y);
        ap[2 * t + 1] = __floats2half2_rn(a.z, a.w);
    }
}

// ---------------- merged attention + pooling (block per graph) -----------------
__global__ void pool_att_kernel(const __half* __restrict__ h,
                                const __half* __restrict__ s1,
                                const float* __restrict__ w2,
                                const float* __restrict__ b2,
                                const int* __restrict__ gstart,
                                const float* __restrict__ cnt,
                                float* __restrict__ out)
{
    __shared__ float swexp[128];
    __shared__ float sw2[128];
    __shared__ float swsum;
    int g = blockIdx.x;
    int t = threadIdx.x;
    int warp = t >> 5, lane = t & 31;
    if (t < 128) sw2[t] = __ldg(w2 + t);
    if (t == 0) swsum = 0.f;
    float b2v = __ldg(b2);
    int lo = gstart[g], hi = gstart[g + 1];
    float s = 0.f, mx = 0.f, att = 0.f;
    __syncthreads();

    for (int c0 = lo; c0 < hi; c0 += 128) {
        int nchunk = min(128, hi - c0);
        // phase A: scores (warp per node)
        for (int j = warp; j < nchunk; j += 8) {
            const __half2* sp = (const __half2*)(s1 + (size_t)(c0 + j) * EDIM);
            float acc = 0.f;
#pragma unroll
            for (int k = lane; k < 64; k += 32) {
                float2 f = __half22float2(__ldg(sp + k));
                acc = fmaf(f.x, sw2[2 * k], acc);
                acc = fmaf(f.y, sw2[2 * k + 1], acc);
            }
#pragma unroll
            for (int o = 16; o > 0; o >>= 1) acc += __shfl_down_sync(0xffffffffu, acc, o);
            if (lane == 0) swexp[j] = expf(acc + b2v);
        }
        __syncthreads();
        if (t < 32) {
            float wv = 0.f;
            for (int j = t; j < nchunk; j += 32) wv += swexp[j];
#pragma unroll
            for (int o = 16; o > 0; o >>= 1) wv += __shfl_down_sync(0xffffffffu, wv, o);
            if (t == 0) swsum += wv;
        }
        // phase B: channel per thread
        for (int j = 0; j < nchunk; j++) {
            float v = __half2float(__ldg(h + (size_t)(c0 + j) * HID + t));
            s += v;
            mx = fmaxf(mx, v);
            att = fmaf(v, swexp[j], att);
        }
        __syncthreads();
    }
    float* og = out + (size_t)g * (3 * HID);
    og[t] = s / cnt[g];
    og[HID + t] = mx;
    og[2 * HID + t] = att / (swsum + 1e-8f);
}

// ---------------- host launch --------------------------------------------------------
extern "C" void kernel_launch(void* const* d_in, const int* in_sizes, int n_in,
                              void* d_out, int out_size)
{
    const float* x         = (const float*)d_in[0];
    const float* edge_attr = (const float*)d_in[1];
    const float* node_w    = (const float*)d_in[2];
    const float* node_b    = (const float*)d_in[3];
    const float* edge_w    = (const float*)d_in[4];
    const float* edge_b    = (const float*)d_in[5];
    const float* conv_w    = (const float*)d_in[6];
    const float* conv_b    = (const float*)d_in[7];
    const float* mlp_w1    = (const float*)d_in[8];
    const float* mlp_b1    = (const float*)d_in[9];
    const float* mlp_w2    = (const float*)d_in[10];
    const float* mlp_b2    = (const float*)d_in[11];
    const float* eps       = (const float*)d_in[12];
    const float* bn_gamma  = (const float*)d_in[13];
    const float* bn_beta   = (const float*)d_in[14];
    const float* att_w1    = (const float*)d_in[15];
    const float* att_b1    = (const float*)d_in[16];
    const float* att_w2    = (const float*)d_in[17];
    const float* att_b2    = (const float*)d_in[18];
    const int*   edge_index= (const int*)d_in[19];
    const int*   batch     = (const int*)d_in[20];
    float* out = (float*)d_out;
    (void)bn_beta;   // cancels exactly under PairNorm centering

    const int* src = edge_index;
    const int* dst = edge_index + NEDGES;

    const int HG_SMEM_128 = 2 * HA_TILE_BYTES + 2 * 32 * (128 + 4) * 4;

    cudaFuncSetAttribute(tf32_gemm_h, cudaFuncAttributeMaxDynamicSharedMemorySize, GEMM_SMEM_BYTES);
    cudaFuncSetAttribute(fused_mlp, cudaFuncAttributeMaxDynamicSharedMemorySize, FUSED_SMEM);
    cudaFuncSetAttribute(hgemm_att, cudaFuncAttributeMaxDynamicSharedMemorySize, HG_SMEM_128);

    float *p_stats, *p_gsum, *p_gsq, *p_cnt, *p_wf;
    __half *p_hh0, *p_hh1, *p_zh, *p_aeffh, *p_s1h;
    __half2 *p_w1p, *p_w2p, *p_w1a;
    int *p_deg, *p_bsum, *p_boffs, *p_rowstart, *p_cursor, *p_eid, *p_csrc, *p_gstart;
    cudaGetSymbolAddress((void**)&p_hh0, g_hh0);
    cudaGetSymbolAddress((void**)&p_hh1, g_hh1);
    cudaGetSymbolAddress((void**)&p_zh, g_zh);
    cudaGetSymbolAddress((void**)&p_aeffh, g_aeffh);
    cudaGetSymbolAddress((void**)&p_s1h, g_s1h);
    cudaGetSymbolAddress((void**)&p_w1p, g_w1p);
    cudaGetSymbolAddress((void**)&p_w2p, g_w2p);
    cudaGetSymbolAddress((void**)&p_w1a, g_w1a);
    cudaGetSymbolAddress((void**)&p_stats, g_stats);
    cudaGetSymbolAddress((void**)&p_gsum, g_gsum);
    cudaGetSymbolAddress((void**)&p_gsq, g_gsq);
    cudaGetSymbolAddress((void**)&p_cnt, g_cnt);
    cudaGetSymbolAddress((void**)&p_wf, g_wf);
    cudaGetSymbolAddress((void**)&p_deg, g_deg);
    cudaGetSymbolAddress((void**)&p_bsum, g_bsum);
    cudaGetSymbolAddress((void**)&p_boffs, g_boffs);
    cudaGetSymbolAddress((void**)&p_rowstart, g_rowstart);
    cudaGetSymbolAddress((void**)&p_cursor, g_cursor);
    cudaGetSymbolAddress((void**)&p_eid, g_csr_eid);
    cudaGetSymbolAddress((void**)&p_csrc, g_csr_src);
    cudaGetSymbolAddress((void**)&p_gstart, g_gstart);

    // ----- CSR build (parallel scan)
    cudaMemsetAsync(p_deg, 0, NNODES * sizeof(int));
    deg_kernel<<<(NEDGES + 255) / 256, 256>>>(dst, p_deg);
    deg_bsum_kernel<<<NBLKD, 256>>>(p_deg, p_bsum);
    bscan_kernel<<<1, 512>>>(p_bsum, p_boffs);
    rowfill_kernel<<<NBLKD, 256>>>(p_deg, p_boffs, p_rowstart, p_cursor);
    csr_fill_kernel<<<(NEDGES + 255) / 256, 256>>>(src, dst, p_cursor, p_eid, p_csrc);

    // ----- graph ranges + counts
    cudaMemsetAsync(p_gstart, 0x7F, (NGRAPH + 1) * sizeof(int));
    gstart_min_kernel<<<(NNODES + 255) / 256, 256>>>(batch, p_gstart);
    gstart_fix_kernel<<<1, 1024>>>(p_gstart, p_cnt);

    // ----- weight prep
    wfuse_kernel<<<dim3(NLAYER, 7), HID>>>(edge_w, edge_b, conv_w, conv_b, p_wf);
    wpack_kernel<<<(NLAYER * 128 * 256) / 256, 256>>>(mlp_w1, mlp_w2, p_w1p, p_w2p);
    wpack_att_kernel<<<(128 * 128) / 256, 256>>>(att_w1, p_w1a);

    // ----- node embedding (tf32, half output)
    {
        dim3 grid(HID / 128, (NNODES + 127) / 128);
        tf32_gemm_h<<<grid, 256, GEMM_SMEM_BYTES>>>(NNODES, HID, NODE_F, x, node_w,
                                                    node_b, p_hh0);
    }

    __half* h_cur = p_hh0;
    __half* h_nxt = p_hh1;
    const int mgrid = (NNODES + 127) / 128;

    for (int i = 0; i < NLAYER; i++) {
        gine_gather_fused<<<2048, 256>>>(
            h_cur, edge_attr, p_rowstart, p_eid, p_csrc,
            p_wf + (size_t)i * 7 * HID, eps + i, p_aeffh, p_stats, p_gsum, p_gsq);

        fused_mlp<<<mgrid, 512, FUSED_SMEM>>>(
            NNODES, p_aeffh,
            p_w1p + (size_t)i * 32768, p_w2p + (size_t)i * 32768,
            mlp_b1 + (size_t)i * HID, mlp_b2 + (size_t)i * HID,
            batch, p_gsum, p_gsq, p_stats, p_zh);

        msq_norm_kernel<<<NGRAPH, HID>>>(p_stats, bn_gamma + (size_t)i * HID,
                                         p_cnt, p_gsum, p_gsq, p_gstart, p_zh, h_nxt);

        __half* t = h_cur; h_cur = h_nxt; h_nxt = t;
    }

    // attention hidden: s1 = tanh(h @ att_w1 + att_b1)
    {
        dim3 agrid(1, (NNODES + 127) / 128);
        hgemm_att<<<agrid, 256, HG_SMEM_128>>>(NNODES, h_cur, p_w1a, att_b1, p_s1h);
    }

    // merged attention-score + pooling
    pool_att_kernel<<<NGRAPH, HID>>>(h_cur, p_s1h, att_w2, att_b2, p_gstart, p_cnt, out);

    (void)in_sizes; (void)n_in; (void)out_size;
}

// round 11
// speedup vs baseline: 6.6856x; 1.0514x over previous
#include <cuda_runtime.h>
#include <cuda_fp16.h>
#include <math.h>
#include <stdint.h>

#define NNODES 100000
#define NEDGES 320000
#define NGRAPH 2048
#define HID    256
#define EDIM   128
#define NODE_F 48
#define EDGE_F 6
#define NLAYER 8
#define NBLKD  ((NNODES + 255) / 256)   // 391

// ---------------- scratch (device globals) ----------------------------------
__device__ __half  g_hh0[(size_t)NNODES * HID];
__device__ __half  g_hh1[(size_t)NNODES * HID];
__device__ __half  g_zh [(size_t)NNODES * HID];
__device__ __half  g_aeffh[(size_t)NNODES * HID];
__device__ __half  g_s1h [(size_t)NNODES * EDIM];
__device__ __half2 g_w1p[(size_t)NLAYER * (HID / 2) * HID];
__device__ __half2 g_w2p[(size_t)NLAYER * (HID / 2) * HID];
__device__ __half2 g_w1a[(size_t)(HID / 2) * EDIM];
__device__ float   g_eap[(size_t)NEDGES * 8];     // CSR-permuted edge attrs (padded)
__device__ float   g_stats[2 * HID];
__device__ float   g_gsum[(size_t)NGRAPH * HID];
__device__ float   g_gsq [(size_t)NGRAPH * HID];
__device__ float   g_cnt [NGRAPH];
__device__ float   g_wf  [(size_t)NLAYER * 7 * HID];
__device__ int     g_deg [NNODES];
__device__ int     g_bsum[NBLKD];
__device__ int     g_boffs[NBLKD];
__device__ int     g_rowstart[NNODES + 1];
__device__ int     g_cursor[NNODES];
__device__ int     g_csr_eid[NEDGES];
__device__ int     g_csr_src[NEDGES];
__device__ int     g_gstart[NGRAPH + 1];

// ---------------- common helpers ---------------------------------------------
__device__ __forceinline__ uint32_t f2tf32(float x) {
    uint32_t r;
    asm volatile("cvt.rna.tf32.f32 %0, %1;" : "=r"(r) : "f"(x));
    return r;
}
__device__ __forceinline__ void cp16s(uint32_t d, const void* src, bool pred) {
    int sz = pred ? 16 : 0;
    asm volatile("cp.async.cg.shared.global [%0], [%1], 16, %2;" :: "r"(d), "l"(src), "r"(sz));
}
__device__ __forceinline__ void cp_commit() { asm volatile("cp.async.commit_group;"); }
template <int Np>
__device__ __forceinline__ void cp_wait() { asm volatile("cp.async.wait_group %0;" :: "n"(Np)); }
__device__ __forceinline__ void mma_f16(float* c, const uint32_t* a, const uint32_t* b) {
    asm volatile(
        "mma.sync.aligned.m16n8k16.row.col.f32.f16.f16.f32 "
        "{%0,%1,%2,%3}, {%4,%5,%6,%7}, {%8,%9}, {%0,%1,%2,%3};"
        : "+f"(c[0]), "+f"(c[1]), "+f"(c[2]), "+f"(c[3])
        : "r"(a[0]), "r"(a[1]), "r"(a[2]), "r"(a[3]), "r"(b[0]), "r"(b[1]));
}
__device__ __forceinline__ void ldsm4(uint32_t* r, uint32_t addr) {
    asm volatile("ldmatrix.sync.aligned.m8n8.x4.shared.b16 {%0,%1,%2,%3}, [%4];"
                 : "=r"(r[0]), "=r"(r[1]), "=r"(r[2]), "=r"(r[3]) : "r"(addr));
}

extern __shared__ char smemc[];

// ===================== fused MLP + stats ========================================
#define FA_STRIDE 72
#define FA_TILE_BYTES (128 * FA_STRIDE * 2)
#define FB2_STRIDE 260
#define FB_TILE2 (32 * FB2_STRIDE)
#define FTMP_STRIDE 264
#define OFF_B (2 * FA_TILE_BYTES)
#define OFF_TMP (OFF_B + 2 * FB_TILE2 * 4)
#define FUSED_SMEM (OFF_TMP + 128 * FTMP_STRIDE * 2)   // 171008

__global__ __launch_bounds__(512, 1) void fused_mlp(
    int M, const __half* __restrict__ A,
    const __half2* __restrict__ W1p, const __half2* __restrict__ W2p,
    const float* __restrict__ b1, const float* __restrict__ b2,
    const int* __restrict__ batchp,
    float* __restrict__ gsum, float* __restrict__ gsq, float* __restrict__ stats,
    __half* __restrict__ Z)
{
    uint32_t sb = (uint32_t)__cvta_generic_to_shared(smemc);
    const __half2* hB = (const __half2*)(smemc + OFF_B);
    __half* tmp = (__half*)(smemc + OFF_TMP);
    uint32_t sbT = sb + OFF_TMP;

    const int tid = threadIdx.x;
    const int warp = tid >> 5;
    const int lane = tid & 31;
    const int g = lane >> 2;
    const int tq = lane & 3;
    const int m0 = blockIdx.x * 128;
    const int wm = (warp & 3) * 32;
    const int wn = (warp >> 2) * 64;
    const int lrow = ((lane >> 3) & 1) * 8 + (lane & 7);
    const int lcol = (lane >> 4) * 8;

    float acc[2][8][4];
#pragma unroll
    for (int i = 0; i < 2; i++)
#pragma unroll
        for (int j = 0; j < 8; j++)
#pragma unroll
            for (int r = 0; r < 4; r++) acc[i][j][r] = 0.0f;

    auto fillA = [&](int buf, int k0) {
#pragma unroll
        for (int it = 0; it < 2; it++) {
            int chunk = tid + it * 512;
            int r = chunk >> 3, c = (chunk & 7) * 8;
            bool p = (m0 + r) < M;
            cp16s(sb + buf * FA_TILE_BYTES + (r * FA_STRIDE + c) * 2,
                  A + (size_t)(p ? m0 + r : 0) * 256 + k0 + c, p);
        }
    };
    auto fillB = [&](int buf, int k0, const __half2* W) {
#pragma unroll
        for (int it = 0; it < 4; it++) {
            int chunk = tid + it * 512;
            int pr = chunk >> 6, c2 = (chunk & 63) * 4;
            cp16s(sb + OFF_B + (buf * FB_TILE2 + pr * FB2_STRIDE + c2) * 4,
                  W + (size_t)((k0 >> 1) + pr) * 256 + c2, true);
        }
    };

    // phase 1: acc = A @ W1
    fillA(0, 0);
    fillB(0, 0, W1p);
    cp_commit();

    int buf = 0;
#pragma unroll 1
    for (int i = 0; i < 4; i++) {
        if (i < 3) {
            fillA(buf ^ 1, (i + 1) * 64);
            fillB(buf ^ 1, (i + 1) * 64, W1p);
        } else {
            fillB(buf ^ 1, 0, W2p);
        }
        cp_commit();
        cp_wait<1>();
        __syncthreads();

        uint32_t abase = sb + buf * FA_TILE_BYTES;
        const __half2* Bb = hB + buf * FB_TILE2;
#pragma unroll
        for (int kk = 0; kk < 4; kk++) {
            uint32_t af[2][4];
#pragma unroll
            for (int mi = 0; mi < 2; mi++)
                ldsm4(af[mi], abase + ((wm + mi * 16 + lrow) * FA_STRIDE + kk * 16 + lcol) * 2);
            uint32_t bf[8][2];
#pragma unroll
            for (int ni = 0; ni < 8; ni++) {
                const __half2* p = Bb + (kk * 8 + tq) * FB2_STRIDE + wn + ni * 8 + g;
                bf[ni][0] = *(const uint32_t*)(p);
                bf[ni][1] = *(const uint32_t*)(p + 4 * FB2_STRIDE);
            }
#pragma unroll
            for (int mi = 0; mi < 2; mi++)
#pragma unroll
                for (int ni = 0; ni < 8; ni++)
                    mma_f16(acc[mi][ni], af[mi], bf[ni]);
        }
        __syncthreads();
        buf ^= 1;
    }

    if (tid < 128)
        ((int*)smemc)[tid] = (m0 + tid < M) ? __ldg(batchp + m0 + tid) : 0;

    // phase 1 epilogue: tmp = relu(acc + b1)
#pragma unroll
    for (int mi = 0; mi < 2; mi++) {
        int r0 = wm + mi * 16 + g;
        int r1 = r0 + 8;
#pragma unroll
        for (int ni = 0; ni < 8; ni++) {
            int col = wn + ni * 8 + tq * 2;
            float c0 = __ldg(b1 + col);
            float c1 = __ldg(b1 + col + 1);
            float v0 = fmaxf(acc[mi][ni][0] + c0, 0.f);
            float v1 = fmaxf(acc[mi][ni][1] + c1, 0.f);
            float v2 = fmaxf(acc[mi][ni][2] + c0, 0.f);
            float v3 = fmaxf(acc[mi][ni][3] + c1, 0.f);
            *(__half2*)(tmp + r0 * FTMP_STRIDE + col) = __floats2half2_rn(v0, v1);
            *(__half2*)(tmp + r1 * FTMP_STRIDE + col) = __floats2half2_rn(v2, v3);
            acc[mi][ni][0] = 0.f; acc[mi][ni][1] = 0.f;
            acc[mi][ni][2] = 0.f; acc[mi][ni][3] = 0.f;
        }
    }

    // phase 2: acc = tmp @ W2
#pragma unroll 1
    for (int i = 0; i < 4; i++) {
        if (i < 3) {
            fillB(buf ^ 1, (i + 1) * 64, W2p);
            cp_commit();
            cp_wait<1>();
        } else {
            cp_wait<0>();
        }
        __syncthreads();

        const __half2* Bb = hB + buf * FB_TILE2;
#pragma unroll
        for (int kk = 0; kk < 4; kk++) {
            uint32_t af[2][4];
#pragma unroll
            for (int mi = 0; mi < 2; mi++)
                ldsm4(af[mi], sbT + ((wm + mi * 16 + lrow) * FTMP_STRIDE + i * 64 + kk * 16 + lcol) * 2);
            uint32_t bf[8][2];
#pragma unroll
            for (int ni = 0; ni < 8; ni++) {
                const __half2* p = Bb + (kk * 8 + tq) * FB2_STRIDE + wn + ni * 8 + g;
                bf[ni][0] = *(const uint32_t*)(p);
                bf[ni][1] = *(const uint32_t*)(p + 4 * FB2_STRIDE);
            }
#pragma unroll
            for (int mi = 0; mi < 2; mi++)
#pragma unroll
                for (int ni = 0; ni < 8; ni++)
                    mma_f16(acc[mi][ni], af[mi], bf[ni]);
        }
        __syncthreads();
        buf ^= 1;
    }

    // phase 2 epilogue: Z(global) + z(tmp smem)
#pragma unroll
    for (int mi = 0; mi < 2; mi++) {
        int rr0 = wm + mi * 16 + g;
        int rr1 = rr0 + 8;
        int r0 = m0 + rr0;
        int r1 = m0 + rr1;
#pragma unroll
        for (int ni = 0; ni < 8; ni++) {
            int col = wn + ni * 8 + tq * 2;
            float c0 = __ldg(b2 + col);
            float c1 = __ldg(b2 + col + 1);
            __half2 z0 = __floats2half2_rn(acc[mi][ni][0] + c0, acc[mi][ni][1] + c1);
            __half2 z1 = __floats2half2_rn(acc[mi][ni][2] + c0, acc[mi][ni][3] + c1);
            *(__half2*)(tmp + rr0 * FTMP_STRIDE + col) = z0;
            *(__half2*)(tmp + rr1 * FTMP_STRIDE + col) = z1;
            if (r0 < M) *(__half2*)(Z + (size_t)r0 * 256 + col) = z0;
            if (r1 < M) *(__half2*)(Z + (size_t)r1 * 256 + col) = z1;
        }
    }
    __syncthreads();

    // phase 3: per-graph + chip stats from smem z
    {
        const int c = tid & 255;
        const int rbeg = (tid >> 8) * 64;
        const int* sbatch = (const int*)smemc;
        float ts = 0.f, tqs = 0.f;
        int curg = -1;
        float s = 0.f, q = 0.f;
        for (int r = rbeg; r < rbeg + 64; r++) {
            if (m0 + r >= M) break;
            int gg = sbatch[r];
            if (gg != curg) {
                if (curg >= 0) {
                    atomicAdd(gsum + (size_t)curg * 256 + c, s);
                    atomicAdd(gsq + (size_t)curg * 256 + c, q);
                }
                curg = gg; s = 0.f; q = 0.f;
            }
            float v = __half2float(tmp[r * FTMP_STRIDE + c]);
            s += v; q = fmaf(v, v, q);
            ts += v; tqs = fmaf(v, v, tqs);
        }
        if (curg >= 0) {
            atomicAdd(gsum + (size_t)curg * 256 + c, s);
            atomicAdd(gsq + (size_t)curg * 256 + c, q);
        }
        atomicAdd(stats + c, ts);
        atomicAdd(stats + 256 + c, tqs);
    }
}

// ===================== merged msq + normalize (block per graph) ================
__global__ void msq_norm_kernel(const float* __restrict__ stats,
                                const float* __restrict__ gamma,
                                const float* __restrict__ cnt,
                                const float* __restrict__ gsum,
                                const float* __restrict__ gsq,
                                const int* __restrict__ gstart,
                                const __half* __restrict__ zh,
                                __half* __restrict__ hout)
{
    __shared__ float red[HID];
    int gb = blockIdx.x;
    int c = threadIdx.x;
    const float invN = 1.0f / (float)NNODES;
    float mu = __ldg(stats + c) * invN;
    float var = __ldg(stats + HID + c) * invN - mu * mu;
    float ac = __ldg(gamma + c) * rsqrtf(var + 1e-5f);
    float cg = cnt[gb];
    size_t gi = (size_t)gb * HID + c;
    float S = gsum[gi], Q = gsq[gi];
    float m = S / cg;
    red[c] = ac * ac * (Q - cg * m * m);
    __syncthreads();
    for (int o = HID / 2; o > 0; o >>= 1) {
        if (c < o) red[c] += red[c + o];
        __syncthreads();
    }
    float sc = rsqrtf(1e-5f + red[0] / cg);
    int lo = gstart[gb], hi = gstart[gb + 1];
    float acs = ac * sc;
    for (int n = lo; n < hi; n++) {
        size_t i = (size_t)n * HID + c;
        float v = acs * (__half2float(zh[i]) - m);
        hout[i] = __float2half(fmaxf(v, 0.f));
    }
}

// ===================== fp16 GEMM (attention, tanh) =============================
#define HA_STRIDE 72
#define HA_TILE_BYTES (128 * HA_STRIDE * 2)

__global__ __launch_bounds__(256, 2) void hgemm_att(
    int M, const __half* __restrict__ A, const __half2* __restrict__ Bp,
    const float* __restrict__ bias, __half* __restrict__ Ch)
{
    constexpr int WN = 128;
    constexpr int HB2_STRIDE = WN + 4;
    constexpr int HB_TILE2 = 32 * HB2_STRIDE;
    const __half2* hB = (const __half2*)(smemc + 2 * HA_TILE_BYTES);
    uint32_t sb = (uint32_t)__cvta_generic_to_shared(smemc);
    uint32_t sbB = sb + 2 * HA_TILE_BYTES;

    const int tid = threadIdx.x;
    const int warp = tid >> 5;
    const int lane = tid & 31;
    const int g = lane >> 2;
    const int tq = lane & 3;
    const int m0 = blockIdx.y * 128;
    const int wm = (warp >> 1) * 32;
    const int wn = (warp & 1) * 64;
    const int lrow = ((lane >> 3) & 1) * 8 + (lane & 7);
    const int lcol = (lane >> 4) * 8;

    float acc[2][8][4];
#pragma unroll
    for (int i = 0; i < 2; i++)
#pragma unroll
        for (int j = 0; j < 8; j++)
#pragma unroll
            for (int r = 0; r < 4; r++) acc[i][j][r] = 0.0f;

    auto fillA = [&](int buf, int k0) {
#pragma unroll
        for (int it = 0; it < 4; it++) {
            int chunk = tid + it * 256;
            int r = chunk >> 3, c = (chunk & 7) * 8;
            bool p = (m0 + r) < M;
            cp16s(sb + buf * HA_TILE_BYTES + (r * HA_STRIDE + c) * 2,
                  A + (size_t)(p ? m0 + r : 0) * 256 + k0 + c, p);
        }
    };
    auto fillB = [&](int buf, int k0) {
#pragma unroll
        for (int it = 0; it < 4; it++) {
            int chunk = tid + it * 256;
            int pr = chunk >> 5, c2 = (chunk & 31) * 4;
            cp16s(sbB + (buf * HB_TILE2 + pr * HB2_STRIDE + c2) * 4,
                  Bp + (size_t)((k0 >> 1) + pr) * WN + c2, true);
        }
    };

    fillA(0, 0);
    fillB(0, 0);
    cp_commit();

    int buf = 0;
#pragma unroll 1
    for (int i = 0; i < 4; i++) {
        if (i + 1 < 4) {
            fillA(buf ^ 1, (i + 1) * 64);
            fillB(buf ^ 1, (i + 1) * 64);
            cp_commit();
            cp_wait<1>();
        } else {
            cp_wait<0>();
        }
        __syncthreads();

        uint32_t abase = sb + buf * HA_TILE_BYTES;
        const __half2* Bb = hB + buf * HB_TILE2;
#pragma unroll
        for (int kk = 0; kk < 4; kk++) {
            uint32_t af[2][4];
#pragma unroll
            for (int mi = 0; mi < 2; mi++)
                ldsm4(af[mi], abase + ((wm + mi * 16 + lrow) * HA_STRIDE + kk * 16 + lcol) * 2);
            uint32_t bf[8][2];
#pragma unroll
            for (int ni = 0; ni < 8; ni++) {
                const __half2* p = Bb + (kk * 8 + tq) * HB2_STRIDE + wn + ni * 8 + g;
                bf[ni][0] = *(const uint32_t*)(p);
                bf[ni][1] = *(const uint32_t*)(p + 4 * HB2_STRIDE);
            }
#pragma unroll
            for (int mi = 0; mi < 2; mi++)
#pragma unroll
                for (int ni = 0; ni < 8; ni++)
                    mma_f16(acc[mi][ni], af[mi], bf[ni]);
        }
        __syncthreads();
        buf ^= 1;
    }

#pragma unroll
    for (int mi = 0; mi < 2; mi++) {
        int r0 = m0 + wm + mi * 16 + g;
        int r1 = r0 + 8;
#pragma unroll
        for (int ni = 0; ni < 8; ni++) {
            int col = wn + ni * 8 + tq * 2;
            float b0 = __ldg(bias + col);
            float b1 = __ldg(bias + col + 1);
            float v0 = tanhf(acc[mi][ni][0] + b0);
            float v1 = tanhf(acc[mi][ni][1] + b1);
            float v2 = tanhf(acc[mi][ni][2] + b0);
            float v3 = tanhf(acc[mi][ni][3] + b1);
            if (r0 < M) *(__half2*)(Ch + (size_t)r0 * WN + col) = __floats2half2_rn(v0, v1);
            if (r1 < M) *(__half2*)(Ch + (size_t)r1 * WN + col) = __floats2half2_rn(v2, v3);
        }
    }
}

// ---------------- weight packs ---------------------------------------------------
__global__ void wpack_kernel(const float* __restrict__ w1, const float* __restrict__ w2,
                             __half2* __restrict__ w1p, __half2* __restrict__ w2p)
{
    int idx = blockIdx.x * 256 + threadIdx.x;
    int l = idx >> 15;
    int rem = idx & 32767;
    int p = rem >> 8;
    int n = rem & 255;
    size_t base = (size_t)l * 65536 + (size_t)(2 * p) * 256 + n;
    w1p[idx] = __floats2half2_rn(__ldg(w1 + base), __ldg(w1 + base + 256));
    w2p[idx] = __floats2half2_rn(__ldg(w2 + base), __ldg(w2 + base + 256));
}
__global__ void wpack_att_kernel(const float* __restrict__ w, __half2* __restrict__ wp)
{
    int idx = blockIdx.x * 256 + threadIdx.x;
    int p = idx >> 7;
    int n = idx & 127;
    size_t base = (size_t)(2 * p) * 128 + n;
    wp[idx] = __floats2half2_rn(__ldg(w + base), __ldg(w + base + 128));
}

// ===================== mma.sync TF32 GEMM (node embed) ========================
#define GA_STRIDE 36
#define GB_STRIDE 132
#define A_TILE_W (128 * GA_STRIDE)
#define B_TILE_W (32 * GB_STRIDE)
#define GEMM_SMEM_BYTES ((2 * A_TILE_W + 2 * B_TILE_W) * 4)

__device__ __forceinline__ void cp16(float* dst, const float* src, bool pred) {
    cp16s((uint32_t)__cvta_generic_to_shared(dst), src, pred);
}
__device__ __forceinline__ void mma_tf32(float* c, const uint32_t* a, const uint32_t* b) {
    asm volatile(
        "mma.sync.aligned.m16n8k8.row.col.f32.tf32.tf32.f32 "
        "{%0,%1,%2,%3}, {%4,%5,%6,%7}, {%8,%9}, {%0,%1,%2,%3};"
        : "+f"(c[0]), "+f"(c[1]), "+f"(c[2]), "+f"(c[3])
        : "r"(a[0]), "r"(a[1]), "r"(a[2]), "r"(a[3]), "r"(b[0]), "r"(b[1]));
}

__global__ __launch_bounds__(256, 2) void tf32_gemm_h(
    int M, int N, int K,
    const float* __restrict__ A, const float* __restrict__ B,
    const float* __restrict__ bias, __half* __restrict__ Chh)
{
    float* sm = (float*)smemc;
    float* As = sm;
    float* Bs = sm + 2 * A_TILE_W;

    const int tid = threadIdx.x;
    const int warp = tid >> 5;
    const int lane = tid & 31;
    const int g = lane >> 2;
    const int tq = lane & 3;
    const int m0 = blockIdx.y * 128;
    const int n0 = blockIdx.x * 128;
    const int wm = (warp >> 1) * 32;
    const int wn = (warp & 1) * 64;

    float acc[2][8][4];
#pragma unroll
    for (int i = 0; i < 2; i++)
#pragma unroll
        for (int j = 0; j < 8; j++)
#pragma unroll
            for (int r = 0; r < 4; r++) acc[i][j][r] = 0.0f;

    const int arow = tid >> 3;
    const int ac4 = tid & 7;
    const int brow = tid >> 5;
    const int bc4 = tid & 31;
    const int nk = (K + 31) / 32;

    {
#pragma unroll
        for (int it = 0; it < 4; it++) {
            int row = arow + it * 32;
            int gm = m0 + row;
            int gk = ac4 * 4;
            bool p = (gm < M) && (gk < K);
            const float* src = A + (size_t)(p ? gm : 0) * K + (p ? gk : 0);
            cp16(As + row * GA_STRIDE + ac4 * 4, src, p);
        }
#pragma unroll
        for (int it = 0; it < 4; it++) {
            int row = brow + it * 8;
            bool p = (row < K);
            const float* src = B + (size_t)(p ? row : 0) * N + n0 + bc4 * 4;
            cp16(Bs + row * GB_STRIDE + bc4 * 4, src, p);
        }
        cp_commit();
    }

    int buf = 0;
    for (int i = 0; i < nk; i++) {
        if (i + 1 < nk) {
            const int kc = i + 1;
            float* Ad = As + (buf ^ 1) * A_TILE_W;
            float* Bd = Bs + (buf ^ 1) * B_TILE_W;
#pragma unroll
            for (int it = 0; it < 4; it++) {
                int row = arow + it * 32;
                int gm = m0 + row;
                int gk = kc * 32 + ac4 * 4;
                bool p = (gm < M) && (gk < K);
                const float* src = A + (size_t)(p ? gm : 0) * K + (p ? gk : 0);
                cp16(Ad + row * GA_STRIDE + ac4 * 4, src, p);
            }
#pragma unroll
            for (int it = 0; it < 4; it++) {
                int row = brow + it * 8;
                int gk = kc * 32 + row;
                bool p = (gk < K);
                const float* src = B + (size_t)(p ? gk : 0) * N + n0 + bc4 * 4;
                cp16(Bd + row * GB_STRIDE + bc4 * 4, src, p);
            }
            cp_commit();
            cp_wait<1>();
        } else {
            cp_wait<0>();
        }
        __syncthreads();

        const float* Ab = As + buf * A_TILE_W;
        const float* Bb = Bs + buf * B_TILE_W;
#pragma unroll
        for (int kk = 0; kk < 4; kk++) {
            const int k = kk * 8;
            uint32_t af[2][4];
#pragma unroll
            for (int mi = 0; mi < 2; mi++) {
                const float* p = Ab + (wm + mi * 16 + g) * GA_STRIDE + k + tq;
                af[mi][0] = f2tf32(p[0]);
                af[mi][1] = f2tf32(p[8 * GA_STRIDE]);
                af[mi][2] = f2tf32(p[4]);
                af[mi][3] = f2tf32(p[8 * GA_STRIDE + 4]);
            }
            uint32_t bf[8][2];
#pragma unroll
            for (int ni = 0; ni < 8; ni++) {
                const float* p = Bb + (k + tq) * GB_STRIDE + wn + ni * 8 + g;
                bf[ni][0] = f2tf32(p[0]);
                bf[ni][1] = f2tf32(p[4 * GB_STRIDE]);
            }
#pragma unroll
            for (int mi = 0; mi < 2; mi++)
#pragma unroll
                for (int ni = 0; ni < 8; ni++)
                    mma_tf32(acc[mi][ni], af[mi], bf[ni]);
        }
        __syncthreads();
        buf ^= 1;
    }

#pragma unroll
    for (int mi = 0; mi < 2; mi++) {
        int r0 = m0 + wm + mi * 16 + g;
        int r1 = r0 + 8;
#pragma unroll
        for (int ni = 0; ni < 8; ni++) {
            int col = n0 + wn + ni * 8 + tq * 2;
            float b0 = __ldg(bias + col);
            float b1 = __ldg(bias + col + 1);
            if (r0 < M) *(__half2*)(Chh + (size_t)r0 * N + col) =
                __floats2half2_rn(acc[mi][ni][0] + b0, acc[mi][ni][1] + b1);
            if (r1 < M) *(__half2*)(Chh + (size_t)r1 * N + col) =
                __floats2half2_rn(acc[mi][ni][2] + b0, acc[mi][ni][3] + b1);
        }
    }
}

// ---------------- fused edge weights ------------------------------------------
__global__ void wfuse_kernel(const float* __restrict__ edge_w,
                             const float* __restrict__ edge_b,
                             const float* __restrict__ conv_w,
                             const float* __restrict__ conv_b,
                             float* __restrict__ wf)
{
    int layer = blockIdx.x;
    int k = blockIdx.y;
    int c = threadIdx.x;
    const float* cw = conv_w + (size_t)layer * EDIM * HID;
    float s = 0.f;
    if (k < EDGE_F) {
        for (int j = 0; j < EDIM; j++)
            s = fmaf(__ldg(edge_w + k * EDIM + j), __ldg(cw + (size_t)j * HID + c), s);
    } else {
        for (int j = 0; j < EDIM; j++)
            s = fmaf(__ldg(edge_b + j), __ldg(cw + (size_t)j * HID + c), s);
        s += __ldg(conv_b + (size_t)layer * HID + c);
    }
    wf[((size_t)layer * 7 + k) * HID + c] = s;
}

// ---------------- CSR build (parallel scan) -------------------------------------
__global__ void deg_kernel(const int* __restrict__ dst, int* __restrict__ deg)
{
    int e = blockIdx.x * blockDim.x + threadIdx.x;
    if (e < NEDGES) atomicAdd(&deg[__ldg(dst + e)], 1);
}

__global__ void deg_bsum_kernel(const int* __restrict__ deg, int* __restrict__ bsum)
{
    __shared__ int sh[256];
    int i = blockIdx.x * 256 + threadIdx.x;
    sh[threadIdx.x] = (i < NNODES) ? deg[i] : 0;
    __syncthreads();
    for (int o = 128; o > 0; o >>= 1) {
        if (threadIdx.x < o) sh[threadIdx.x] += sh[threadIdx.x + o];
        __syncthreads();
    }
    if (threadIdx.x == 0) bsum[blockIdx.x] = sh[0];
}

__global__ void bscan_kernel(const int* __restrict__ bsum, int* __restrict__ boffs)
{
    __shared__ int sh[512];
    int t = threadIdx.x;
    int mine = (t < NBLKD) ? bsum[t] : 0;
    sh[t] = mine;
    __syncthreads();
    for (int o = 1; o < 512; o <<= 1) {
        int v = (t >= o) ? sh[t - o] : 0;
        __syncthreads();
        sh[t] += v;
        __syncthreads();
    }
    if (t < NBLKD) boffs[t] = sh[t] - mine;
}

__global__ void rowfill_kernel(const int* __restrict__ deg, const int* __restrict__ boffs,
                               int* __restrict__ rowstart, int* __restrict__ cursor)
{
    __shared__ int sh[256];
    int b = blockIdx.x, t = threadIdx.x;
    int i = b * 256 + t;
    int d = (i < NNODES) ? deg[i] : 0;
    sh[t] = d;
    __syncthreads();
    for (int o = 1; o < 256; o <<= 1) {
        int v = (t >= o) ? sh[t - o] : 0;
        __syncthreads();
        sh[t] += v;
        __syncthreads();
    }
    if (i < NNODES) {
        int rs = boffs[b] + sh[t] - d;
        rowstart[i] = rs;
        cursor[i] = rs;
    }
    if (i == NNODES - 1) rowstart[NNODES] = NEDGES;
}

__global__ void csr_fill_kernel(const int* __restrict__ src,
                                const int* __restrict__ dst,
                                int* __restrict__ cursor,
                                int* __restrict__ csr_eid,
                                int* __restrict__ csr_src)
{
    int e = blockIdx.x * blockDim.x + threadIdx.x;
    if (e >= NEDGES) return;
    int d = __ldg(dst + e);
    int p = atomicAdd(&cursor[d], 1);
    csr_eid[p] = e;
    csr_src[p] = __ldg(src + e);
}

// ---------------- permute edge attrs into CSR order (padded to 8) --------------
__global__ void eaperm_kernel(const float* __restrict__ ea,
                              const int* __restrict__ csr_eid,
                              float* __restrict__ eap)
{
    int j = blockIdx.x * blockDim.x + threadIdx.x;
    if (j >= NEDGES) return;
    int eid = __ldg(csr_eid + j);
    const float* e = ea + (size_t)eid * EDGE_F;
    float4 a = make_float4(__ldg(e), __ldg(e + 1), __ldg(e + 2), __ldg(e + 3));
    float2 b = make_float2(__ldg(e + 4), __ldg(e + 5));
    *(float4*)(eap + (size_t)j * 8) = a;
    *(float2*)(eap + (size_t)j * 8 + 4) = b;
}

// ---------------- graph ranges --------------------------------------------------
__global__ void gstart_min_kernel(const int* __restrict__ batch, int* __restrict__ gstart)
{
    int n = blockIdx.x * blockDim.x + threadIdx.x;
    if (n < NNODES) atomicMin(&gstart[__ldg(batch + n)], n);
}

__global__ void gstart_fix_kernel(int* __restrict__ gstart, float* __restrict__ cnt)
{
    __shared__ int sg[NGRAPH + 1];
    int t = threadIdx.x;
    for (int i = t; i <= NGRAPH; i += 1024) sg[i] = gstart[i];
    __syncthreads();
    if (t == 0) {
        sg[NGRAPH] = NNODES;
        for (int g2 = NGRAPH - 1; g2 >= 0; g2--)
            if (sg[g2] > sg[g2 + 1]) sg[g2] = sg[g2 + 1];
    }
    __syncthreads();
    for (int i = t; i <= NGRAPH; i += 1024) gstart[i] = sg[i];
    for (int i = t; i < NGRAPH; i += 1024)
        cnt[i] = fmaxf((float)(sg[i + 1] - sg[i]), 1.0f);
}

// ---------------- GINE gather v3: permuted ea + pipelined src ------------------
__device__ __forceinline__ float4 h4load(const uint2* hp, int idx) {
    uint2 u = __ldg(hp + idx);
    float2 f0 = __half22float2(*(__half2*)&u.x);
    float2 f1 = __half22float2(*(__half2*)&u.y);
    return make_float4(f0.x, f0.y, f1.x, f1.y);
}

__global__ __launch_bounds__(256) void gine_gather_fused(
    const __half* __restrict__ h,
    const float* __restrict__ eap,
    const int* __restrict__ rowstart,
    const int* __restrict__ csr_src,
    const float* __restrict__ wf,
    const float* __restrict__ eps_ptr,
    __half* __restrict__ aeffh,
    float* __restrict__ stats,
    float* __restrict__ gsum,
    float* __restrict__ gsq)
{
    {
        int gid = blockIdx.x * 256 + threadIdx.x;
        if (gid < 262144) {
            gsum[gid] = 0.f; gsum[gid + 262144] = 0.f;
            gsq[gid] = 0.f;  gsq[gid + 262144] = 0.f;
        }
        if (blockIdx.x == 0) {
            stats[threadIdx.x] = 0.f;
            stats[256 + threadIdx.x] = 0.f;
        }
    }

    const int t = threadIdx.x & 63;
    const int group = (blockIdx.x * blockDim.x + threadIdx.x) >> 6;
    const int ngroups = (gridDim.x * blockDim.x) >> 6;
    const float alpha = 1.0f + __ldg(eps_ptr);

    float4 w[EDGE_F];
#pragma unroll
    for (int k = 0; k < EDGE_F; k++)
        w[k] = __ldg((const float4*)(wf + k * HID) + t);
    float4 bf = __ldg((const float4*)(wf + EDGE_F * HID) + t);

    for (int n = group; n < NNODES; n += ngroups) {
        float4 a = h4load((const uint2*)(h + (size_t)n * HID), t);
        a.x *= alpha; a.y *= alpha; a.z *= alpha; a.w *= alpha;

        int lo = __ldg(rowstart + n), hi = __ldg(rowstart + n + 1);
        int s_next = (lo < hi) ? __ldg(csr_src + lo) : 0;
        for (int j = lo; j < hi; j++) {
            int s_cur = s_next;
            if (j + 1 < hi) s_next = __ldg(csr_src + j + 1);
            float4 e03 = __ldg((const float4*)(eap + (size_t)j * 8));
            float2 e45 = __ldg((const float2*)(eap + (size_t)j * 8 + 4));
            float4 hv = h4load((const uint2*)(h + (size_t)s_cur * HID), t);

            float4 ee = bf;
            ee.x = fmaf(e03.x, w[0].x, ee.x); ee.y = fmaf(e03.x, w[0].y, ee.y);
            ee.z = fmaf(e03.x, w[0].z, ee.z); ee.w = fmaf(e03.x, w[0].w, ee.w);
            ee.x = fmaf(e03.y, w[1].x, ee.x); ee.y = fmaf(e03.y, w[1].y, ee.y);
            ee.z = fmaf(e03.y, w[1].z, ee.z); ee.w = fmaf(e03.y, w[1].w, ee.w);
            ee.x = fmaf(e03.z, w[2].x, ee.x); ee.y = fmaf(e03.z, w[2].y, ee.y);
            ee.z = fmaf(e03.z, w[2].z, ee.z); ee.w = fmaf(e03.z, w[2].w, ee.w);
            ee.x = fmaf(e03.w, w[3].x, ee.x); ee.y = fmaf(e03.w, w[3].y, ee.y);
            ee.z = fmaf(e03.w, w[3].z, ee.z); ee.w = fmaf(e03.w, w[3].w, ee.w);
            ee.x = fmaf(e45.x, w[4].x, ee.x); ee.y = fmaf(e45.x, w[4].y, ee.y);
            ee.z = fmaf(e45.x, w[4].z, ee.z); ee.w = fmaf(e45.x, w[4].w, ee.w);
            ee.x = fmaf(e45.y, w[5].x, ee.x); ee.y = fmaf(e45.y, w[5].y, ee.y);
            ee.z = fmaf(e45.y, w[5].z, ee.z); ee.w = fmaf(e45.y, w[5].w, ee.w);

            a.x += fmaxf(hv.x + ee.x, 0.f);
            a.y += fmaxf(hv.y + ee.y, 0.f);
            a.z += fmaxf(hv.z + ee.z, 0.f);
            a.w += fmaxf(hv.w + ee.w, 0.f);
        }
        __half2* ap = (__half2*)(aeffh + (size_t)n * HID);
        ap[2 * t]     = __floats2half2_rn(a.x, a.y);
        ap[2 * t + 1] = __floats2half2_rn(a.z, a.w);
    }
}

// ---------------- merged attention + pooling (block per graph) -----------------
__global__ void pool_att_kernel(const __half* __restrict__ h,
                                const __half* __restrict__ s1,
                                const float* __restrict__ w2,
                                const float* __restrict__ b2,
                                const int* __restrict__ gstart,
                                const float* __restrict__ cnt,
                                float* __restrict__ out)
{
    __shared__ float swexp[128];
    __shared__ float sw2[128];
    __shared__ float swsum;
    int g = blockIdx.x;
    int t = threadIdx.x;
    int warp = t >> 5, lane = t & 31;
    if (t < 128) sw2[t] = __ldg(w2 + t);
    if (t == 0) swsum = 0.f;
    float b2v = __ldg(b2);
    int lo = gstart[g], hi = gstart[g + 1];
    float s = 0.f, mx = 0.f, att = 0.f;
    __syncthreads();

    for (int c0 = lo; c0 < hi; c0 += 128) {
        int nchunk = min(128, hi - c0);
        for (int j = warp; j < nchunk; j += 8) {
            const __half2* sp = (const __half2*)(s1 + (size_t)(c0 + j) * EDIM);
            float acc = 0.f;
#pragma unroll
            for (int k = lane; k < 64; k += 32) {
                float2 f = __half22float2(__ldg(sp + k));
                acc = fmaf(f.x, sw2[2 * k], acc);
                acc = fmaf(f.y, sw2[2 * k + 1], acc);
            }
#pragma unroll
            for (int o = 16; o > 0; o >>= 1) acc += __shfl_down_sync(0xffffffffu, acc, o);
            if (lane == 0) swexp[j] = expf(acc + b2v);
        }
        __syncthreads();
        if (t < 32) {
            float wv = 0.f;
            for (int j = t; j < nchunk; j += 32) wv += swexp[j];
#pragma unroll
            for (int o = 16; o > 0; o >>= 1) wv += __shfl_down_sync(0xffffffffu, wv, o);
            if (t == 0) swsum += wv;
        }
        for (int j = 0; j < nchunk; j++) {
            float v = __half2float(__ldg(h + (size_t)(c0 + j) * HID + t));
            s += v;
            mx = fmaxf(mx, v);
            att = fmaf(v, swexp[j], att);
        }
        __syncthreads();
    }
    float* og = out + (size_t)g * (3 * HID);
    og[t] = s / cnt[g];
    og[HID + t] = mx;
    og[2 * HID + t] = att / (swsum + 1e-8f);
}

// ---------------- host launch --------------------------------------------------------
extern "C" void kernel_launch(void* const* d_in, const int* in_sizes, int n_in,
                              void* d_out, int out_size)
{
    const float* x         = (const float*)d_in[0];
    const float* edge_attr = (const float*)d_in[1];
    const float* node_w    = (const float*)d_in[2];
    const float* node_b    = (const float*)d_in[3];
    const float* edge_w    = (const float*)d_in[4];
    const float* edge_b    = (const float*)d_in[5];
    const float* conv_w    = (const float*)d_in[6];
    const float* conv_b    = (const float*)d_in[7];
    const float* mlp_w1    = (const float*)d_in[8];
    const float* mlp_b1    = (const float*)d_in[9];
    const float* mlp_w2    = (const float*)d_in[10];
    const float* mlp_b2    = (const float*)d_in[11];
    const float* eps       = (const float*)d_in[12];
    const float* bn_gamma  = (const float*)d_in[13];
    const float* bn_beta   = (const float*)d_in[14];
    const float* att_w1    = (const float*)d_in[15];
    const float* att_b1    = (const float*)d_in[16];
    const float* att_w2    = (const float*)d_in[17];
    const float* att_b2    = (const float*)d_in[18];
    const int*   edge_index= (const int*)d_in[19];
    const int*   batch     = (const int*)d_in[20];
    float* out = (float*)d_out;
    (void)bn_beta;   // cancels exactly under PairNorm centering

    const int* src = edge_index;
    const int* dst = edge_index + NEDGES;

    const int HG_SMEM_128 = 2 * HA_TILE_BYTES + 2 * 32 * (128 + 4) * 4;

    cudaFuncSetAttribute(tf32_gemm_h, cudaFuncAttributeMaxDynamicSharedMemorySize, GEMM_SMEM_BYTES);
    cudaFuncSetAttribute(fused_mlp, cudaFuncAttributeMaxDynamicSharedMemorySize, FUSED_SMEM);
    cudaFuncSetAttribute(hgemm_att, cudaFuncAttributeMaxDynamicSharedMemorySize, HG_SMEM_128);

    float *p_stats, *p_gsum, *p_gsq, *p_cnt, *p_wf, *p_eap;
    __half *p_hh0, *p_hh1, *p_zh, *p_aeffh, *p_s1h;
    __half2 *p_w1p, *p_w2p, *p_w1a;
    int *p_deg, *p_bsum, *p_boffs, *p_rowstart, *p_cursor, *p_eid, *p_csrc, *p_gstart;
    cudaGetSymbolAddress((void**)&p_hh0, g_hh0);
    cudaGetSymbolAddress((void**)&p_hh1, g_hh1);
    cudaGetSymbolAddress((void**)&p_zh, g_zh);
    cudaGetSymbolAddress((void**)&p_aeffh, g_aeffh);
    cudaGetSymbolAddress((void**)&p_s1h, g_s1h);
    cudaGetSymbolAddress((void**)&p_w1p, g_w1p);
    cudaGetSymbolAddress((void**)&p_w2p, g_w2p);
    cudaGetSymbolAddress((void**)&p_w1a, g_w1a);
    cudaGetSymbolAddress((void**)&p_eap, g_eap);
    cudaGetSymbolAddress((void**)&p_stats, g_stats);
    cudaGetSymbolAddress((void**)&p_gsum, g_gsum);
    cudaGetSymbolAddress((void**)&p_gsq, g_gsq);
    cudaGetSymbolAddress((void**)&p_cnt, g_cnt);
    cudaGetSymbolAddress((void**)&p_wf, g_wf);
    cudaGetSymbolAddress((void**)&p_deg, g_deg);
    cudaGetSymbolAddress((void**)&p_bsum, g_bsum);
    cudaGetSymbolAddress((void**)&p_boffs, g_boffs);
    cudaGetSymbolAddress((void**)&p_rowstart, g_rowstart);
    cudaGetSymbolAddress((void**)&p_cursor, g_cursor);
    cudaGetSymbolAddress((void**)&p_eid, g_csr_eid);
    cudaGetSymbolAddress((void**)&p_csrc, g_csr_src);
    cudaGetSymbolAddress((void**)&p_gstart, g_gstart);

    // ----- CSR build (parallel scan)
    cudaMemsetAsync(p_deg, 0, NNODES * sizeof(int));
    deg_kernel<<<(NEDGES + 255) / 256, 256>>>(dst, p_deg);
    deg_bsum_kernel<<<NBLKD, 256>>>(p_deg, p_bsum);
    bscan_kernel<<<1, 512>>>(p_bsum, p_boffs);
    rowfill_kernel<<<NBLKD, 256>>>(p_deg, p_boffs, p_rowstart, p_cursor);
    csr_fill_kernel<<<(NEDGES + 255) / 256, 256>>>(src, dst, p_cursor, p_eid, p_csrc);
    eaperm_kernel<<<(NEDGES + 255) / 256, 256>>>(edge_attr, p_eid, p_eap);

    // ----- graph ranges + counts
    cudaMemsetAsync(p_gstart, 0x7F, (NGRAPH + 1) * sizeof(int));
    gstart_min_kernel<<<(NNODES + 255) / 256, 256>>>(batch, p_gstart);
    gstart_fix_kernel<<<1, 1024>>>(p_gstart, p_cnt);

    // ----- weight prep
    wfuse_kernel<<<dim3(NLAYER, 7), HID>>>(edge_w, edge_b, conv_w, conv_b, p_wf);
    wpack_kernel<<<(NLAYER * 128 * 256) / 256, 256>>>(mlp_w1, mlp_w2, p_w1p, p_w2p);
    wpack_att_kernel<<<(128 * 128) / 256, 256>>>(att_w1, p_w1a);

    // ----- node embedding (tf32, half output)
    {
        dim3 grid(HID / 128, (NNODES + 127) / 128);
        tf32_gemm_h<<<grid, 256, GEMM_SMEM_BYTES>>>(NNODES, HID, NODE_F, x, node_w,
                                                    node_b, p_hh0);
    }

    __half* h_cur = p_hh0;
    __half* h_nxt = p_hh1;
    const int mgrid = (NNODES + 127) / 128;

    for (int i = 0; i < NLAYER; i++) {
        gine_gather_fused<<<2048, 256>>>(
            h_cur, p_eap, p_rowstart, p_csrc,
            p_wf + (size_t)i * 7 * HID, eps + i, p_aeffh, p_stats, p_gsum, p_gsq);

        fused_mlp<<<mgrid, 512, FUSED_SMEM>>>(
            NNODES, p_aeffh,
            p_w1p + (size_t)i * 32768, p_w2p + (size_t)i * 32768,
            mlp_b1 + (size_t)i * HID, mlp_b2 + (size_t)i * HID,
            batch, p_gsum, p_gsq, p_stats, p_zh);

        msq_norm_kernel<<<NGRAPH, HID>>>(p_stats, bn_gamma + (size_t)i * HID,
                                         p_cnt, p_gsum, p_gsq, p_gstart, p_zh, h_nxt);

        __half* t = h_cur; h_cur = h_nxt; h_nxt = t;
    }

    // attention hidden: s1 = tanh(h @ att_w1 + att_b1)
    {
        dim3 agrid(1, (NNODES + 127) / 128);
        hgemm_att<<<agrid, 256, HG_SMEM_128>>>(NNODES, h_cur, p_w1a, att_b1, p_s1h);
    }

    // merged attention-score + pooling
    pool_att_kernel<<<NGRAPH, HID>>>(h_cur, p_s1h, att_w2, att_b2, p_gstart, p_cnt, out);

    (void)in_sizes; (void)n_in; (void)out_size;
}